// round 1
// baseline (speedup 1.0000x reference)
#include <cuda_runtime.h>
#include <cstdint>
#include <float.h>

// ---------------- problem constants ----------------
#define BDIM 4
#define SDIM 4096
#define HDIM 1024
#define PDIM 4096
#define DDIM 512
#define NTOK (BDIM * SDIM)          // 16384
#define INTER_DIM 1024
#define NDIL 3

// ---------------- scratch (device globals; no allocs allowed) ----------------
__device__ float g_inter[NTOK * INTER_DIM];        // 64 MB
__device__ float g_logits[(size_t)NTOK * PDIM];    // 256 MB
__device__ float g_concat[(size_t)NTOK * 3 * HDIM];// 192 MB
__device__ float g_local[NTOK * HDIM];             // 64 MB
__device__ float g_combined[NTOK * 2 * DDIM];      // 64 MB  [LN(proj) | weighted_map]
__device__ float g_transf[NTOK * DDIM];            // 32 MB
__device__ float g_global[NTOK * HDIM];            // 64 MB
__device__ float g_proj[NTOK * DDIM];              // 32 MB
__device__ float g_convwt[NDIL * 3 * HDIM * HDIM]; // 36 MB, [dil][k][ho][hi]
__device__ float g_usage[PDIM];

// ---------------- helpers ----------------
__device__ __forceinline__ float block_reduce_sum(float v, float* sh) {
    int tid = threadIdx.x;
    #pragma unroll
    for (int o = 16; o; o >>= 1) v += __shfl_xor_sync(0xffffffffu, v, o);
    if ((tid & 31) == 0) sh[tid >> 5] = v;
    __syncthreads();
    int nw = blockDim.x >> 5;
    float r = (tid < nw) ? sh[tid] : 0.f;
    if (tid < 32) {
        #pragma unroll
        for (int o = 16; o; o >>= 1) r += __shfl_xor_sync(0xffffffffu, r, o);
        if (tid == 0) sh[32] = r;
    }
    __syncthreads();
    float total = sh[32];
    __syncthreads();
    return total;
}

// ---------------- generic tiled GEMM: C = act(A[M,K] @ W[Ncols,K]^T + bias) ----------------
// BM=128, BN=64, BK=16, 256 threads, 8x4 per thread. All dims divide evenly.
__global__ void __launch_bounds__(256) gemm_bias_act(
    const float* __restrict__ A, const float* __restrict__ W,
    const float* __restrict__ bias, float* __restrict__ C,
    int M, int Ncols, int K, int ldc, int coff, int act)
{
    __shared__ float As[16][132];
    __shared__ float Bs[16][68];
    const int tid = threadIdx.x;
    const int tx = tid & 15;        // -> n
    const int ty = tid >> 4;        // -> m
    const int row0 = blockIdx.y * 128;
    const int col0 = blockIdx.x * 64;

    float acc[8][4];
    #pragma unroll
    for (int i = 0; i < 8; i++)
        #pragma unroll
        for (int j = 0; j < 4; j++) acc[i][j] = 0.f;

    for (int k0 = 0; k0 < K; k0 += 16) {
        #pragma unroll
        for (int i = 0; i < 2; i++) {
            int f = tid + i * 256;
            int r = f >> 2;
            int c = (f & 3) << 2;
            float4 v = *reinterpret_cast<const float4*>(A + (size_t)(row0 + r) * K + (k0 + c));
            As[c + 0][r] = v.x; As[c + 1][r] = v.y; As[c + 2][r] = v.z; As[c + 3][r] = v.w;
        }
        {
            int r = tid >> 2;
            int c = (tid & 3) << 2;
            float4 v = *reinterpret_cast<const float4*>(W + (size_t)(col0 + r) * K + (k0 + c));
            Bs[c + 0][r] = v.x; Bs[c + 1][r] = v.y; Bs[c + 2][r] = v.z; Bs[c + 3][r] = v.w;
        }
        __syncthreads();
        #pragma unroll
        for (int k = 0; k < 16; k++) {
            float4 a0 = *reinterpret_cast<const float4*>(&As[k][ty * 8]);
            float4 a1 = *reinterpret_cast<const float4*>(&As[k][ty * 8 + 4]);
            float4 b4 = *reinterpret_cast<const float4*>(&Bs[k][tx * 4]);
            float av[8] = {a0.x, a0.y, a0.z, a0.w, a1.x, a1.y, a1.z, a1.w};
            float bv[4] = {b4.x, b4.y, b4.z, b4.w};
            #pragma unroll
            for (int i = 0; i < 8; i++)
                #pragma unroll
                for (int j = 0; j < 4; j++)
                    acc[i][j] = fmaf(av[i], bv[j], acc[i][j]);
        }
        __syncthreads();
    }
    #pragma unroll
    for (int j = 0; j < 4; j++) {
        int col = col0 + tx * 4 + j;
        float bv = bias ? bias[col] : 0.f;
        #pragma unroll
        for (int i = 0; i < 8; i++) {
            float v = acc[i][j] + bv;
            if (act == 1) v = fmaxf(v, 0.f);
            else if (act == 2) v = 0.5f * v * (1.f + erff(v * 0.70710678118654752f));
            C[(size_t)(row0 + ty * 8 + i) * ldc + coff + col] = v;
        }
    }
}

// ---------------- conv-as-GEMM: virtual im2col A (token shifts), K = 3*H ----------------
__global__ void __launch_bounds__(256) conv_gemm(
    const float* __restrict__ x, const float* __restrict__ Wt, /* [3][H][H] for this dilation */
    const float* __restrict__ bias, float* __restrict__ C,
    int dil, int coff)
{
    __shared__ float As[16][132];
    __shared__ float Bs[16][68];
    const int tid = threadIdx.x;
    const int tx = tid & 15;
    const int ty = tid >> 4;
    const int row0 = blockIdx.y * 128;
    const int col0 = blockIdx.x * 64;

    float acc[8][4];
    #pragma unroll
    for (int i = 0; i < 8; i++)
        #pragma unroll
        for (int j = 0; j < 4; j++) acc[i][j] = 0.f;

    for (int k0 = 0; k0 < 3 * HDIM; k0 += 16) {
        int ksl = k0 >> 10;              // which tap (0,1,2): 16-tile never straddles
        int h0 = k0 & (HDIM - 1);
        int shift = (ksl - 1) * dil;
        #pragma unroll
        for (int i = 0; i < 2; i++) {
            int f = tid + i * 256;
            int r = f >> 2;
            int c = (f & 3) << 2;
            int n = row0 + r;
            int s2 = (n & (SDIM - 1)) + shift;
            float4 v = make_float4(0.f, 0.f, 0.f, 0.f);
            if ((unsigned)s2 < (unsigned)SDIM)
                v = *reinterpret_cast<const float4*>(x + (size_t)(n + shift) * HDIM + h0 + c);
            As[c + 0][r] = v.x; As[c + 1][r] = v.y; As[c + 2][r] = v.z; As[c + 3][r] = v.w;
        }
        {
            int r = tid >> 2;
            int c = (tid & 3) << 2;
            float4 v = *reinterpret_cast<const float4*>(
                Wt + ((size_t)ksl * HDIM + col0 + r) * HDIM + h0 + c);
            Bs[c + 0][r] = v.x; Bs[c + 1][r] = v.y; Bs[c + 2][r] = v.z; Bs[c + 3][r] = v.w;
        }
        __syncthreads();
        #pragma unroll
        for (int k = 0; k < 16; k++) {
            float4 a0 = *reinterpret_cast<const float4*>(&As[k][ty * 8]);
            float4 a1 = *reinterpret_cast<const float4*>(&As[k][ty * 8 + 4]);
            float4 b4 = *reinterpret_cast<const float4*>(&Bs[k][tx * 4]);
            float av[8] = {a0.x, a0.y, a0.z, a0.w, a1.x, a1.y, a1.z, a1.w};
            float bv[4] = {b4.x, b4.y, b4.z, b4.w};
            #pragma unroll
            for (int i = 0; i < 8; i++)
                #pragma unroll
                for (int j = 0; j < 4; j++)
                    acc[i][j] = fmaf(av[i], bv[j], acc[i][j]);
        }
        __syncthreads();
    }
    #pragma unroll
    for (int j = 0; j < 4; j++) {
        int col = col0 + tx * 4 + j;
        float bv = bias[col];
        #pragma unroll
        for (int i = 0; i < 8; i++) {
            float v = acc[i][j] + bv;
            v = 0.5f * v * (1.f + erff(v * 0.70710678118654752f));   // exact GELU
            C[(size_t)(row0 + ty * 8 + i) * (3 * HDIM) + coff + col] = v;
        }
    }
}

// ---------------- conv weight repack: [dil][ho][hi][k] -> [dil][k][ho][hi] ----------------
__global__ void repack_convw(const float* __restrict__ cw, float* __restrict__ out) {
    int idx = blockIdx.x * blockDim.x + threadIdx.x;
    const int total = NDIL * 3 * HDIM * HDIM;
    if (idx >= total) return;
    int hi = idx & (HDIM - 1);
    int t = idx >> 10;
    int ho = t & (HDIM - 1);
    int t2 = t >> 10;
    int k = t2 % 3;
    int d = t2 / 3;
    out[idx] = cw[(((size_t)d * HDIM + ho) * HDIM + hi) * 3 + k];
}

__global__ void zero_usage(float* usage) {
    int i = blockIdx.x * blockDim.x + threadIdx.x;
    if (i < PDIM) usage[i] = 0.f;
}

// ---------------- fused top-2 + softmax + expert mix + usage ----------------
__device__ __forceinline__ void ins2(float& v1, int& i1, float& v2, int& i2, float v, int i) {
    if (i == i1 || i == i2) return;
    if (v > v1 || (v == v1 && i < i1)) { v2 = v1; i2 = i1; v1 = v; i1 = i; }
    else if (v > v2 || (v == v2 && i < i2)) { v2 = v; i2 = i; }
}

__global__ void __launch_bounds__(256) topk_map_kernel(
    const float* __restrict__ logits, const float* __restrict__ tpool,
    const float* __restrict__ temp_p, float* __restrict__ combined,
    float* __restrict__ usage)
{
    int gw = (blockIdx.x * blockDim.x + threadIdx.x) >> 5;
    int lane = threadIdx.x & 31;
    if (gw >= NTOK) return;
    float temp = fminf(fmaxf(*temp_p, 0.1f), 5.0f);
    const float* lrow = logits + (size_t)gw * PDIM;
    float v1 = -FLT_MAX, v2 = -FLT_MAX;
    int i1 = 0x3fffffff, i2 = 0x3fffffff;
    for (int j = lane; j < PDIM; j += 32) {
        float v = fminf(fmaxf(lrow[j] / temp, -10.f), 10.f);
        ins2(v1, i1, v2, i2, v, j);
    }
    #pragma unroll
    for (int off = 16; off; off >>= 1) {
        float ov1 = __shfl_xor_sync(0xffffffffu, v1, off);
        int   oi1 = __shfl_xor_sync(0xffffffffu, i1, off);
        float ov2 = __shfl_xor_sync(0xffffffffu, v2, off);
        int   oi2 = __shfl_xor_sync(0xffffffffu, i2, off);
        ins2(v1, i1, v2, i2, ov1, oi1);
        ins2(v1, i1, v2, i2, ov2, oi2);
    }
    float e = expf(v2 - v1);
    float w1 = 1.f / (1.f + e);
    float w2 = e / (1.f + e);
    if (lane == 0) {
        atomicAdd(&usage[i1], w1);
        atomicAdd(&usage[i2], w2);
    }
    const float* p1 = tpool + (size_t)i1 * DDIM;
    const float* p2 = tpool + (size_t)i2 * DDIM;
    float* dst = combined + (size_t)gw * (2 * DDIM) + DDIM;
    for (int d = lane; d < DDIM; d += 32)
        dst[d] = w1 * p1[d] + w2 * p2[d];
}

// ---------------- layernorm over D=512, writes combined[:, :512] ----------------
__global__ void ln_kernel(const float* __restrict__ proj, const float* __restrict__ g,
                          const float* __restrict__ b, float* __restrict__ combined)
{
    __shared__ float sh[33];
    int n = blockIdx.x;
    const float* row = proj + (size_t)n * DDIM;
    float v[4];
    float s = 0.f;
    #pragma unroll
    for (int j = 0; j < 4; j++) { v[j] = row[threadIdx.x + j * 128]; s += v[j]; }
    float mean = block_reduce_sum(s, sh) * (1.f / DDIM);
    float q = 0.f;
    #pragma unroll
    for (int j = 0; j < 4; j++) { float d = v[j] - mean; q += d * d; }
    float var = block_reduce_sum(q, sh) * (1.f / DDIM);
    float rstd = rsqrtf(var + 1e-5f);
    float* dst = combined + (size_t)n * (2 * DDIM);
    #pragma unroll
    for (int j = 0; j < 4; j++) {
        int idx = threadIdx.x + j * 128;
        dst[idx] = (v[j] - mean) * rstd * g[idx] + b[idx];
    }
}

// ---------------- gate + final mix ----------------
__global__ void gate_combine(const float* __restrict__ x, const float* __restrict__ wg,
                             const float* __restrict__ bg, const float* __restrict__ local,
                             const float* __restrict__ glob, float* __restrict__ out)
{
    __shared__ float sh[33];
    int n = blockIdx.x;
    const float* xr = x + (size_t)n * HDIM;
    float s = 0.f;
    for (int j = threadIdx.x; j < HDIM; j += 128) s += xr[j] * wg[j];
    float dot = block_reduce_sum(s, sh);
    float g = 1.f / (1.f + expf(-(dot + bg[0])));
    const float* lr = local + (size_t)n * HDIM;
    const float* gr = glob + (size_t)n * HDIM;
    float* orow = out + (size_t)n * HDIM;
    for (int j = threadIdx.x; j < HDIM; j += 128)
        orow[j] = g * lr[j] + (1.f - g) * gr[j];
}

// ---------------- diversity loss ----------------
__global__ void divloss_kernel(const float* __restrict__ usage, float* __restrict__ out) {
    __shared__ float sh[33];
    float s = 0.f;
    for (int j = threadIdx.x; j < PDIM; j += 1024) s += usage[j];
    float total = block_reduce_sum(s, sh);
    float inv = 1.f / (total + 1e-8f);
    float q = 0.f;
    const float ip = 1.f / (float)PDIM;
    for (int j = threadIdx.x; j < PDIM; j += 1024) {
        float f = usage[j] * inv - ip;
        q += f * f;
    }
    float qt = block_reduce_sum(q, sh);
    if (threadIdx.x == 0) out[0] = (qt / (float)PDIM) * 0.01f;  // scale=min(1, BSH/(P*K))=1
}

// ---------------- host launcher ----------------
extern "C" void kernel_launch(void* const* d_in, const int* in_sizes, int n_in,
                              void* d_out, int out_size)
{
    const float* x      = (const float*)d_in[0];
    const float* tpool  = (const float*)d_in[1];
    const float* w1     = (const float*)d_in[2];
    const float* b1     = (const float*)d_in[3];
    const float* w2     = (const float*)d_in[4];
    const float* b2     = (const float*)d_in[5];
    const float* temp   = (const float*)d_in[6];
    const float* wproj  = (const float*)d_in[7];
    const float* bproj  = (const float*)d_in[8];
    const float* ln_g   = (const float*)d_in[9];
    const float* ln_b   = (const float*)d_in[10];
    const float* wmap   = (const float*)d_in[11];
    const float* bmap   = (const float*)d_in[12];
    const float* conv_w = (const float*)d_in[13];
    const float* conv_b = (const float*)d_in[14];
    const float* wout   = (const float*)d_in[15];
    const float* bout   = (const float*)d_in[16];
    const float* wrp    = (const float*)d_in[17];
    const float* brp    = (const float*)d_in[18];
    const float* wg     = (const float*)d_in[19];
    const float* bg     = (const float*)d_in[20];
    float* out = (float*)d_out;

    float *inter, *logits, *concat, *local, *combined, *transf, *glob, *proj, *convwt, *usage;
    cudaGetSymbolAddress((void**)&inter,    g_inter);
    cudaGetSymbolAddress((void**)&logits,   g_logits);
    cudaGetSymbolAddress((void**)&concat,   g_concat);
    cudaGetSymbolAddress((void**)&local,    g_local);
    cudaGetSymbolAddress((void**)&combined, g_combined);
    cudaGetSymbolAddress((void**)&transf,   g_transf);
    cudaGetSymbolAddress((void**)&glob,     g_global);
    cudaGetSymbolAddress((void**)&proj,     g_proj);
    cudaGetSymbolAddress((void**)&convwt,   g_convwt);
    cudaGetSymbolAddress((void**)&usage,    g_usage);

    const int total_cw = NDIL * 3 * HDIM * HDIM;
    repack_convw<<<(total_cw + 255) / 256, 256>>>(conv_w, convwt);
    zero_usage<<<(PDIM + 255) / 256, 256>>>(usage);

    // router MLP
    gemm_bias_act<<<dim3(INTER_DIM / 64, NTOK / 128), 256>>>(
        x, w1, b1, inter, NTOK, INTER_DIM, HDIM, INTER_DIM, 0, 1);
    gemm_bias_act<<<dim3(PDIM / 64, NTOK / 128), 256>>>(
        inter, w2, b2, logits, NTOK, PDIM, INTER_DIM, PDIM, 0, 0);

    // fused top-2 + expert mix -> combined[:, 512:]
    topk_map_kernel<<<(NTOK * 32 + 255) / 256, 256>>>(logits, tpool, temp, combined, usage);

    // projected_x -> LN -> combined[:, :512]
    gemm_bias_act<<<dim3(DDIM / 64, NTOK / 128), 256>>>(
        x, wproj, bproj, proj, NTOK, DDIM, HDIM, DDIM, 0, 0);
    ln_kernel<<<NTOK, 128>>>(proj, ln_g, ln_b, combined);

    // dilated convs (virtual im2col GEMM + fused GELU) -> concat
    const int dils[NDIL] = {1, 2, 4};
    for (int i = 0; i < NDIL; i++)
        conv_gemm<<<dim3(HDIM / 64, NTOK / 128), 256>>>(
            x, convwt + (size_t)i * 3 * HDIM * HDIM, conv_b + i * HDIM, concat, dils[i], i * HDIM);

    // local out
    gemm_bias_act<<<dim3(HDIM / 64, NTOK / 128), 256>>>(
        concat, wout, bout, local, NTOK, HDIM, 3 * HDIM, HDIM, 0, 0);

    // transformation and global out
    gemm_bias_act<<<dim3(DDIM / 64, NTOK / 128), 256>>>(
        combined, wmap, bmap, transf, NTOK, DDIM, 2 * DDIM, DDIM, 0, 0);
    gemm_bias_act<<<dim3(HDIM / 64, NTOK / 128), 256>>>(
        transf, wrp, brp, glob, NTOK, HDIM, DDIM, HDIM, 0, 0);

    // gate + mix -> out
    gate_combine<<<NTOK, 128>>>(x, wg, bg, local, glob, out);

    // diversity loss -> last output element
    if (out_size > NTOK * HDIM)
        divloss_kernel<<<1, 1024>>>(usage, out + (size_t)NTOK * HDIM);
}

// round 2
// speedup vs baseline: 1.0007x; 1.0007x over previous
#include <cuda_runtime.h>
#include <cstdint>
#include <float.h>

// ---------------- problem constants ----------------
#define BDIM 4
#define SDIM 4096
#define HDIM 1024
#define PDIM 4096
#define DDIM 512
#define NTOK (BDIM * SDIM)          // 16384
#define INTER_DIM 1024
#define NDIL 3

// ---------------- scratch (device globals; no allocs allowed) ----------------
__device__ float g_inter[NTOK * INTER_DIM];        // 64 MB
__device__ float g_logits[(size_t)NTOK * PDIM];    // 256 MB
__device__ float g_concat[(size_t)NTOK * 3 * HDIM];// 192 MB
__device__ float g_local[NTOK * HDIM];             // 64 MB
__device__ float g_combined[NTOK * 2 * DDIM];      // 64 MB  [LN(proj) | weighted_map]
__device__ float g_transf[NTOK * DDIM];            // 32 MB
__device__ float g_global[NTOK * HDIM];            // 64 MB
__device__ float g_proj[NTOK * DDIM];              // 32 MB
__device__ float g_convwt[NDIL * 3 * HDIM * HDIM]; // 36 MB, [dil][k][ho][hi]
__device__ float g_usage[PDIM];

// ---------------- helpers ----------------
__device__ __forceinline__ float block_reduce_sum(float v, float* sh) {
    int tid = threadIdx.x;
    #pragma unroll
    for (int o = 16; o; o >>= 1) v += __shfl_xor_sync(0xffffffffu, v, o);
    if ((tid & 31) == 0) sh[tid >> 5] = v;
    __syncthreads();
    int nw = blockDim.x >> 5;
    float r = (tid < nw) ? sh[tid] : 0.f;
    if (tid < 32) {
        #pragma unroll
        for (int o = 16; o; o >>= 1) r += __shfl_xor_sync(0xffffffffu, r, o);
        if (tid == 0) sh[32] = r;
    }
    __syncthreads();
    float total = sh[32];
    __syncthreads();
    return total;
}

// ---------------- generic tiled GEMM: C = act(A[M,K] @ W[Ncols,K]^T + bias) ----------------
// BM=128, BN=64, BK=16, 256 threads, 8x4 per thread. All dims divide evenly.
__global__ void __launch_bounds__(256) gemm_bias_act(
    const float* __restrict__ A, const float* __restrict__ W,
    const float* __restrict__ bias, float* __restrict__ C,
    int M, int Ncols, int K, int ldc, int coff, int act)
{
    __shared__ float As[16][132];
    __shared__ float Bs[16][68];
    const int tid = threadIdx.x;
    const int tx = tid & 15;        // -> n
    const int ty = tid >> 4;        // -> m
    const int row0 = blockIdx.y * 128;
    const int col0 = blockIdx.x * 64;

    float acc[8][4];
    #pragma unroll
    for (int i = 0; i < 8; i++)
        #pragma unroll
        for (int j = 0; j < 4; j++) acc[i][j] = 0.f;

    for (int k0 = 0; k0 < K; k0 += 16) {
        #pragma unroll
        for (int i = 0; i < 2; i++) {
            int f = tid + i * 256;
            int r = f >> 2;
            int c = (f & 3) << 2;
            float4 v = *reinterpret_cast<const float4*>(A + (size_t)(row0 + r) * K + (k0 + c));
            As[c + 0][r] = v.x; As[c + 1][r] = v.y; As[c + 2][r] = v.z; As[c + 3][r] = v.w;
        }
        {
            int r = tid >> 2;
            int c = (tid & 3) << 2;
            float4 v = *reinterpret_cast<const float4*>(W + (size_t)(col0 + r) * K + (k0 + c));
            Bs[c + 0][r] = v.x; Bs[c + 1][r] = v.y; Bs[c + 2][r] = v.z; Bs[c + 3][r] = v.w;
        }
        __syncthreads();
        #pragma unroll
        for (int k = 0; k < 16; k++) {
            float4 a0 = *reinterpret_cast<const float4*>(&As[k][ty * 8]);
            float4 a1 = *reinterpret_cast<const float4*>(&As[k][ty * 8 + 4]);
            float4 b4 = *reinterpret_cast<const float4*>(&Bs[k][tx * 4]);
            float av[8] = {a0.x, a0.y, a0.z, a0.w, a1.x, a1.y, a1.z, a1.w};
            float bv[4] = {b4.x, b4.y, b4.z, b4.w};
            #pragma unroll
            for (int i = 0; i < 8; i++)
                #pragma unroll
                for (int j = 0; j < 4; j++)
                    acc[i][j] = fmaf(av[i], bv[j], acc[i][j]);
        }
        __syncthreads();
    }
    #pragma unroll
    for (int j = 0; j < 4; j++) {
        int col = col0 + tx * 4 + j;
        float bv = bias ? bias[col] : 0.f;
        #pragma unroll
        for (int i = 0; i < 8; i++) {
            float v = acc[i][j] + bv;
            if (act == 1) v = fmaxf(v, 0.f);
            else if (act == 2) v = 0.5f * v * (1.f + erff(v * 0.70710678118654752f));
            C[(size_t)(row0 + ty * 8 + i) * ldc + coff + col] = v;
        }
    }
}

// ---------------- conv-as-GEMM: virtual im2col A (token shifts), K = 3*H ----------------
__global__ void __launch_bounds__(256) conv_gemm(
    const float* __restrict__ x, const float* __restrict__ Wt, /* [3][H][H] for this dilation */
    const float* __restrict__ bias, float* __restrict__ C,
    int dil, int coff)
{
    __shared__ float As[16][132];
    __shared__ float Bs[16][68];
    const int tid = threadIdx.x;
    const int tx = tid & 15;
    const int ty = tid >> 4;
    const int row0 = blockIdx.y * 128;
    const int col0 = blockIdx.x * 64;

    float acc[8][4];
    #pragma unroll
    for (int i = 0; i < 8; i++)
        #pragma unroll
        for (int j = 0; j < 4; j++) acc[i][j] = 0.f;

    for (int k0 = 0; k0 < 3 * HDIM; k0 += 16) {
        int ksl = k0 >> 10;              // which tap (0,1,2): 16-tile never straddles
        int h0 = k0 & (HDIM - 1);
        int shift = (ksl - 1) * dil;
        #pragma unroll
        for (int i = 0; i < 2; i++) {
            int f = tid + i * 256;
            int r = f >> 2;
            int c = (f & 3) << 2;
            int n = row0 + r;
            int s2 = (n & (SDIM - 1)) + shift;
            float4 v = make_float4(0.f, 0.f, 0.f, 0.f);
            if ((unsigned)s2 < (unsigned)SDIM)
                v = *reinterpret_cast<const float4*>(x + (size_t)(n + shift) * HDIM + h0 + c);
            As[c + 0][r] = v.x; As[c + 1][r] = v.y; As[c + 2][r] = v.z; As[c + 3][r] = v.w;
        }
        {
            int r = tid >> 2;
            int c = (tid & 3) << 2;
            float4 v = *reinterpret_cast<const float4*>(
                Wt + ((size_t)ksl * HDIM + col0 + r) * HDIM + h0 + c);
            Bs[c + 0][r] = v.x; Bs[c + 1][r] = v.y; Bs[c + 2][r] = v.z; Bs[c + 3][r] = v.w;
        }
        __syncthreads();
        #pragma unroll
        for (int k = 0; k < 16; k++) {
            float4 a0 = *reinterpret_cast<const float4*>(&As[k][ty * 8]);
            float4 a1 = *reinterpret_cast<const float4*>(&As[k][ty * 8 + 4]);
            float4 b4 = *reinterpret_cast<const float4*>(&Bs[k][tx * 4]);
            float av[8] = {a0.x, a0.y, a0.z, a0.w, a1.x, a1.y, a1.z, a1.w};
            float bv[4] = {b4.x, b4.y, b4.z, b4.w};
            #pragma unroll
            for (int i = 0; i < 8; i++)
                #pragma unroll
                for (int j = 0; j < 4; j++)
                    acc[i][j] = fmaf(av[i], bv[j], acc[i][j]);
        }
        __syncthreads();
    }
    #pragma unroll
    for (int j = 0; j < 4; j++) {
        int col = col0 + tx * 4 + j;
        float bv = bias[col];
        #pragma unroll
        for (int i = 0; i < 8; i++) {
            float v = acc[i][j] + bv;
            v = 0.5f * v * (1.f + erff(v * 0.70710678118654752f));   // exact GELU
            C[(size_t)(row0 + ty * 8 + i) * (3 * HDIM) + coff + col] = v;
        }
    }
}

// ---------------- conv weight repack: [dil][ho][hi][k] -> [dil][k][ho][hi] ----------------
__global__ void repack_convw(const float* __restrict__ cw, float* __restrict__ out) {
    int idx = blockIdx.x * blockDim.x + threadIdx.x;
    const int total = NDIL * 3 * HDIM * HDIM;
    if (idx >= total) return;
    int hi = idx & (HDIM - 1);
    int t = idx >> 10;
    int ho = t & (HDIM - 1);
    int t2 = t >> 10;
    int k = t2 % 3;
    int d = t2 / 3;
    out[idx] = cw[(((size_t)d * HDIM + ho) * HDIM + hi) * 3 + k];
}

__global__ void zero_usage(float* usage) {
    int i = blockIdx.x * blockDim.x + threadIdx.x;
    if (i < PDIM) usage[i] = 0.f;
}

// ---------------- fused top-2 + softmax + expert mix + usage ----------------
__device__ __forceinline__ void ins2(float& v1, int& i1, float& v2, int& i2, float v, int i) {
    if (i == i1 || i == i2) return;
    if (v > v1 || (v == v1 && i < i1)) { v2 = v1; i2 = i1; v1 = v; i1 = i; }
    else if (v > v2 || (v == v2 && i < i2)) { v2 = v; i2 = i; }
}

__global__ void __launch_bounds__(256) topk_map_kernel(
    const float* __restrict__ logits, const float* __restrict__ tpool,
    const float* __restrict__ temp_p, float* __restrict__ combined,
    float* __restrict__ usage)
{
    int gw = (blockIdx.x * blockDim.x + threadIdx.x) >> 5;
    int lane = threadIdx.x & 31;
    if (gw >= NTOK) return;
    float temp = fminf(fmaxf(*temp_p, 0.1f), 5.0f);
    const float* lrow = logits + (size_t)gw * PDIM;
    float v1 = -FLT_MAX, v2 = -FLT_MAX;
    int i1 = 0x3fffffff, i2 = 0x3fffffff;
    for (int j = lane; j < PDIM; j += 32) {
        float v = fminf(fmaxf(lrow[j] / temp, -10.f), 10.f);
        ins2(v1, i1, v2, i2, v, j);
    }
    #pragma unroll
    for (int off = 16; off; off >>= 1) {
        float ov1 = __shfl_xor_sync(0xffffffffu, v1, off);
        int   oi1 = __shfl_xor_sync(0xffffffffu, i1, off);
        float ov2 = __shfl_xor_sync(0xffffffffu, v2, off);
        int   oi2 = __shfl_xor_sync(0xffffffffu, i2, off);
        ins2(v1, i1, v2, i2, ov1, oi1);
        ins2(v1, i1, v2, i2, ov2, oi2);
    }
    float e = expf(v2 - v1);
    float w1 = 1.f / (1.f + e);
    float w2 = e / (1.f + e);
    if (lane == 0) {
        atomicAdd(&usage[i1], w1);
        atomicAdd(&usage[i2], w2);
    }
    const float* p1 = tpool + (size_t)i1 * DDIM;
    const float* p2 = tpool + (size_t)i2 * DDIM;
    float* dst = combined + (size_t)gw * (2 * DDIM) + DDIM;
    for (int d = lane; d < DDIM; d += 32)
        dst[d] = w1 * p1[d] + w2 * p2[d];
}

// ---------------- layernorm over D=512, writes combined[:, :512] ----------------
__global__ void ln_kernel(const float* __restrict__ proj, const float* __restrict__ g,
                          const float* __restrict__ b, float* __restrict__ combined)
{
    __shared__ float sh[33];
    int n = blockIdx.x;
    const float* row = proj + (size_t)n * DDIM;
    float v[4];
    float s = 0.f;
    #pragma unroll
    for (int j = 0; j < 4; j++) { v[j] = row[threadIdx.x + j * 128]; s += v[j]; }
    float mean = block_reduce_sum(s, sh) * (1.f / DDIM);
    float q = 0.f;
    #pragma unroll
    for (int j = 0; j < 4; j++) { float d = v[j] - mean; q += d * d; }
    float var = block_reduce_sum(q, sh) * (1.f / DDIM);
    float rstd = rsqrtf(var + 1e-5f);
    float* dst = combined + (size_t)n * (2 * DDIM);
    #pragma unroll
    for (int j = 0; j < 4; j++) {
        int idx = threadIdx.x + j * 128;
        dst[idx] = (v[j] - mean) * rstd * g[idx] + b[idx];
    }
}

// ---------------- gate + final mix ----------------
__global__ void gate_combine(const float* __restrict__ x, const float* __restrict__ wg,
                             const float* __restrict__ bg, const float* __restrict__ local,
                             const float* __restrict__ glob, float* __restrict__ out)
{
    __shared__ float sh[33];
    int n = blockIdx.x;
    const float* xr = x + (size_t)n * HDIM;
    float s = 0.f;
    for (int j = threadIdx.x; j < HDIM; j += 128) s += xr[j] * wg[j];
    float dot = block_reduce_sum(s, sh);
    float g = 1.f / (1.f + expf(-(dot + bg[0])));
    const float* lr = local + (size_t)n * HDIM;
    const float* gr = glob + (size_t)n * HDIM;
    float* orow = out + (size_t)n * HDIM;
    for (int j = threadIdx.x; j < HDIM; j += 128)
        orow[j] = g * lr[j] + (1.f - g) * gr[j];
}

// ---------------- diversity loss ----------------
__global__ void divloss_kernel(const float* __restrict__ usage, float* __restrict__ out) {
    __shared__ float sh[33];
    float s = 0.f;
    for (int j = threadIdx.x; j < PDIM; j += 1024) s += usage[j];
    float total = block_reduce_sum(s, sh);
    float inv = 1.f / (total + 1e-8f);
    float q = 0.f;
    const float ip = 1.f / (float)PDIM;
    for (int j = threadIdx.x; j < PDIM; j += 1024) {
        float f = usage[j] * inv - ip;
        q += f * f;
    }
    float qt = block_reduce_sum(q, sh);
    if (threadIdx.x == 0) out[0] = (qt / (float)PDIM) * 0.01f;  // scale=min(1, BSH/(P*K))=1
}

// ---------------- host launcher ----------------
extern "C" void kernel_launch(void* const* d_in, const int* in_sizes, int n_in,
                              void* d_out, int out_size)
{
    const float* x      = (const float*)d_in[0];
    const float* tpool  = (const float*)d_in[1];
    const float* w1     = (const float*)d_in[2];
    const float* b1     = (const float*)d_in[3];
    const float* w2     = (const float*)d_in[4];
    const float* b2     = (const float*)d_in[5];
    const float* temp   = (const float*)d_in[6];
    const float* wproj  = (const float*)d_in[7];
    const float* bproj  = (const float*)d_in[8];
    const float* ln_g   = (const float*)d_in[9];
    const float* ln_b   = (const float*)d_in[10];
    const float* wmap   = (const float*)d_in[11];
    const float* bmap   = (const float*)d_in[12];
    const float* conv_w = (const float*)d_in[13];
    const float* conv_b = (const float*)d_in[14];
    const float* wout   = (const float*)d_in[15];
    const float* bout   = (const float*)d_in[16];
    const float* wrp    = (const float*)d_in[17];
    const float* brp    = (const float*)d_in[18];
    const float* wg     = (const float*)d_in[19];
    const float* bg     = (const float*)d_in[20];
    float* out = (float*)d_out;

    float *inter, *logits, *concat, *local, *combined, *transf, *glob, *proj, *convwt, *usage;
    cudaGetSymbolAddress((void**)&inter,    g_inter);
    cudaGetSymbolAddress((void**)&logits,   g_logits);
    cudaGetSymbolAddress((void**)&concat,   g_concat);
    cudaGetSymbolAddress((void**)&local,    g_local);
    cudaGetSymbolAddress((void**)&combined, g_combined);
    cudaGetSymbolAddress((void**)&transf,   g_transf);
    cudaGetSymbolAddress((void**)&glob,     g_global);
    cudaGetSymbolAddress((void**)&proj,     g_proj);
    cudaGetSymbolAddress((void**)&convwt,   g_convwt);
    cudaGetSymbolAddress((void**)&usage,    g_usage);

    const int total_cw = NDIL * 3 * HDIM * HDIM;
    repack_convw<<<(total_cw + 255) / 256, 256>>>(conv_w, convwt);
    zero_usage<<<(PDIM + 255) / 256, 256>>>(usage);

    // router MLP
    gemm_bias_act<<<dim3(INTER_DIM / 64, NTOK / 128), 256>>>(
        x, w1, b1, inter, NTOK, INTER_DIM, HDIM, INTER_DIM, 0, 1);
    gemm_bias_act<<<dim3(PDIM / 64, NTOK / 128), 256>>>(
        inter, w2, b2, logits, NTOK, PDIM, INTER_DIM, PDIM, 0, 0);

    // fused top-2 + expert mix -> combined[:, 512:]
    topk_map_kernel<<<(NTOK * 32 + 255) / 256, 256>>>(logits, tpool, temp, combined, usage);

    // projected_x -> LN -> combined[:, :512]
    gemm_bias_act<<<dim3(DDIM / 64, NTOK / 128), 256>>>(
        x, wproj, bproj, proj, NTOK, DDIM, HDIM, DDIM, 0, 0);
    ln_kernel<<<NTOK, 128>>>(proj, ln_g, ln_b, combined);

    // dilated convs (virtual im2col GEMM + fused GELU) -> concat
    const int dils[NDIL] = {1, 2, 4};
    for (int i = 0; i < NDIL; i++)
        conv_gemm<<<dim3(HDIM / 64, NTOK / 128), 256>>>(
            x, convwt + (size_t)i * 3 * HDIM * HDIM, conv_b + i * HDIM, concat, dils[i], i * HDIM);

    // local out
    gemm_bias_act<<<dim3(HDIM / 64, NTOK / 128), 256>>>(
        concat, wout, bout, local, NTOK, HDIM, 3 * HDIM, HDIM, 0, 0);

    // transformation and global out
    gemm_bias_act<<<dim3(DDIM / 64, NTOK / 128), 256>>>(
        combined, wmap, bmap, transf, NTOK, DDIM, 2 * DDIM, DDIM, 0, 0);
    gemm_bias_act<<<dim3(HDIM / 64, NTOK / 128), 256>>>(
        transf, wrp, brp, glob, NTOK, HDIM, DDIM, HDIM, 0, 0);

    // gate + mix -> out
    gate_combine<<<NTOK, 128>>>(x, wg, bg, local, glob, out);

    // diversity loss -> last output element
    if (out_size > NTOK * HDIM)
        divloss_kernel<<<1, 1024>>>(usage, out + (size_t)NTOK * HDIM);
}

// round 3
// speedup vs baseline: 2.0361x; 2.0346x over previous
#include <cuda_runtime.h>
#include <cstdint>
#include <float.h>

// ---------------- problem constants ----------------
#define BDIM 4
#define SDIM 4096
#define HDIM 1024
#define PDIM 4096
#define DDIM 512
#define NTOK (BDIM * SDIM)          // 16384
#define INTER_DIM 1024
#define NDIL 3

// ---------------- scratch (device globals; no allocs allowed) ----------------
__device__ float g_inter[NTOK * INTER_DIM];        // 64 MB
__device__ float g_logits[(size_t)NTOK * PDIM];    // 256 MB
__device__ float g_concat[(size_t)NTOK * 3 * HDIM];// 192 MB
__device__ float g_local[NTOK * HDIM];             // 64 MB
__device__ float g_combined[NTOK * 2 * DDIM];      // 64 MB  [LN(proj) | weighted_map]
__device__ float g_transf[NTOK * DDIM];            // 32 MB
__device__ float g_global[NTOK * HDIM];            // 64 MB
__device__ float g_proj[NTOK * DDIM];              // 32 MB
__device__ float g_convwt[NDIL * 3 * HDIM * HDIM]; // 36 MB, [dil][k][ho][hi]
__device__ float g_usage[PDIM];

// ---------------- helpers ----------------
__device__ __forceinline__ float block_reduce_sum(float v, float* sh) {
    int tid = threadIdx.x;
    #pragma unroll
    for (int o = 16; o; o >>= 1) v += __shfl_xor_sync(0xffffffffu, v, o);
    if ((tid & 31) == 0) sh[tid >> 5] = v;
    __syncthreads();
    int nw = blockDim.x >> 5;
    float r = (tid < nw) ? sh[tid] : 0.f;
    if (tid < 32) {
        #pragma unroll
        for (int o = 16; o; o >>= 1) r += __shfl_xor_sync(0xffffffffu, r, o);
        if (tid == 0) sh[32] = r;
    }
    __syncthreads();
    float total = sh[32];
    __syncthreads();
    return total;
}

__device__ __forceinline__ unsigned cvt_tf32(float x) {
    unsigned r;
    asm("cvt.rna.tf32.f32 %0, %1;" : "=r"(r) : "f"(x));
    return r;
}

__device__ __forceinline__ void mma_tf32(float* c, const unsigned* a, const unsigned* b) {
    asm volatile(
        "mma.sync.aligned.m16n8k8.row.col.f32.tf32.tf32.f32 "
        "{%0,%1,%2,%3}, {%4,%5,%6,%7}, {%8,%9}, {%0,%1,%2,%3};\n"
        : "+f"(c[0]), "+f"(c[1]), "+f"(c[2]), "+f"(c[3])
        : "r"(a[0]), "r"(a[1]), "r"(a[2]), "r"(a[3]), "r"(b[0]), "r"(b[1]));
}

__device__ __forceinline__ void cp16(void* dst_smem, const float* src, bool pred) {
    unsigned d = (unsigned)__cvta_generic_to_shared(dst_smem);
    int sz = pred ? 16 : 0;
    asm volatile("cp.async.cg.shared.global [%0], [%1], 16, %2;\n"
                 :: "r"(d), "l"(src), "r"(sz));
}

// =====================================================================
// TF32 tensor-core GEMM: C = act(A[M,K] @ W[Ncols,K]^T + bias)
// BM=BN=128, BK=32, 256 threads (8 warps, 2x4), warp tile 64x32,
// mma m16n8k8 tf32, cp.async double-buffered smem.
// CONV: A is virtual im2col of x [NTOK,HDIM] with per-1024-slice token
// shift (dilated conv); W is convwt slice [3][H][H]; GELU epilogue.
// =====================================================================
#define TFPAD 36   // row stride in floats (32 + 4 pad)

template<bool CONV>
__global__ void __launch_bounds__(256) gemm_tf32(
    const float* __restrict__ A, const float* __restrict__ W,
    const float* __restrict__ bias, float* __restrict__ C,
    int M, int Ncols, int K, int ldc, int coff, int act, int dil)
{
    extern __shared__ float smem[];
    float* As = smem;                     // [2][128][TFPAD]
    float* Bs = smem + 2 * 128 * TFPAD;   // [2][128][TFPAD]

    const int tid = threadIdx.x;
    const int lane = tid & 31;
    const int wid = tid >> 5;
    const int wm = wid >> 2;      // 0..1  warp row
    const int wn = wid & 3;       // 0..3  warp col
    const int g = lane >> 2;      // group 0..7
    const int t = lane & 3;       // thread-in-group
    const int row0 = blockIdx.y * 128;
    const int col0 = blockIdx.x * 128;
    const int KT = K >> 5;

    float acc[4][4][4];
    #pragma unroll
    for (int i = 0; i < 4; i++)
        #pragma unroll
        for (int j = 0; j < 4; j++)
            #pragma unroll
            for (int q = 0; q < 4; q++) acc[i][j][q] = 0.f;

    // tile loader: 128 rows x 8 float4 each for A and B; 4 float4/thread each
    auto load_tile = [&](int kt, int buf) {
        int k0 = kt << 5;
        int ksl = 0, h0 = k0, shift = 0;
        if (CONV) {
            ksl = k0 >> 10;
            h0 = k0 & (HDIM - 1);
            shift = (ksl - 1) * dil;
        }
        float* Ad = As + buf * 128 * TFPAD;
        float* Bd = Bs + buf * 128 * TFPAD;
        #pragma unroll
        for (int i = 0; i < 4; i++) {
            int idx = tid + i * 256;
            int r = idx >> 3;
            int c4 = (idx & 7) << 2;
            // A
            const float* srcA;
            bool pred = true;
            if (CONV) {
                int n = row0 + r;
                int s2 = (n & (SDIM - 1)) + shift;
                pred = ((unsigned)s2 < (unsigned)SDIM);
                srcA = pred ? (A + (size_t)(n + shift) * HDIM + h0 + c4) : A;
            } else {
                srcA = A + (size_t)(row0 + r) * K + k0 + c4;
            }
            cp16(Ad + r * TFPAD + c4, srcA, pred);
            // B
            const float* srcB;
            if (CONV)
                srcB = W + ((size_t)ksl * HDIM + col0 + r) * HDIM + h0 + c4;
            else
                srcB = W + (size_t)(col0 + r) * K + k0 + c4;
            cp16(Bd + r * TFPAD + c4, srcB, true);
        }
    };

    load_tile(0, 0);
    asm volatile("cp.async.commit_group;\n" ::);

    for (int kt = 0; kt < KT; kt++) {
        int buf = kt & 1;
        if (kt + 1 < KT) load_tile(kt + 1, buf ^ 1);
        asm volatile("cp.async.commit_group;\n" ::);
        asm volatile("cp.async.wait_group 1;\n" ::);
        __syncthreads();

        const float* AsB = As + buf * 128 * TFPAD;
        const float* BsB = Bs + buf * 128 * TFPAD;
        #pragma unroll
        for (int kk = 0; kk < 4; kk++) {
            unsigned af[4][4], bf[4][2];
            #pragma unroll
            for (int mt = 0; mt < 4; mt++) {
                const float* p = AsB + (wm * 64 + mt * 16 + g) * TFPAD + kk * 8 + t;
                af[mt][0] = cvt_tf32(p[0]);
                af[mt][1] = cvt_tf32(p[8 * TFPAD]);
                af[mt][2] = cvt_tf32(p[4]);
                af[mt][3] = cvt_tf32(p[8 * TFPAD + 4]);
            }
            #pragma unroll
            for (int nt = 0; nt < 4; nt++) {
                const float* p = BsB + (wn * 32 + nt * 8 + g) * TFPAD + kk * 8 + t;
                bf[nt][0] = cvt_tf32(p[0]);
                bf[nt][1] = cvt_tf32(p[4]);
            }
            #pragma unroll
            for (int mt = 0; mt < 4; mt++)
                #pragma unroll
                for (int nt = 0; nt < 4; nt++)
                    mma_tf32(acc[mt][nt], af[mt], bf[nt]);
        }
        __syncthreads();
    }

    // epilogue: bias + act, float2 stores
    #pragma unroll
    for (int mt = 0; mt < 4; mt++) {
        int r0 = row0 + wm * 64 + mt * 16 + g;
        int r1 = r0 + 8;
        #pragma unroll
        for (int nt = 0; nt < 4; nt++) {
            int c = col0 + wn * 32 + nt * 8 + 2 * t;
            float b0v = bias ? bias[c] : 0.f;
            float b1v = bias ? bias[c + 1] : 0.f;
            float v[4] = {acc[mt][nt][0] + b0v, acc[mt][nt][1] + b1v,
                          acc[mt][nt][2] + b0v, acc[mt][nt][3] + b1v};
            if (CONV || act == 2) {
                #pragma unroll
                for (int q = 0; q < 4; q++)
                    v[q] = 0.5f * v[q] * (1.f + erff(v[q] * 0.70710678118654752f));
            } else if (act == 1) {
                #pragma unroll
                for (int q = 0; q < 4; q++) v[q] = fmaxf(v[q], 0.f);
            }
            *reinterpret_cast<float2*>(C + (size_t)r0 * ldc + coff + c) = make_float2(v[0], v[1]);
            *reinterpret_cast<float2*>(C + (size_t)r1 * ldc + coff + c) = make_float2(v[2], v[3]);
        }
    }
}

// ---------------- fp32 SIMT GEMM (router path only — exact selection) ----------------
__global__ void __launch_bounds__(256) gemm_bias_act(
    const float* __restrict__ A, const float* __restrict__ W,
    const float* __restrict__ bias, float* __restrict__ C,
    int M, int Ncols, int K, int ldc, int coff, int act)
{
    __shared__ float As[16][132];
    __shared__ float Bs[16][68];
    const int tid = threadIdx.x;
    const int tx = tid & 15;
    const int ty = tid >> 4;
    const int row0 = blockIdx.y * 128;
    const int col0 = blockIdx.x * 64;

    float acc[8][4];
    #pragma unroll
    for (int i = 0; i < 8; i++)
        #pragma unroll
        for (int j = 0; j < 4; j++) acc[i][j] = 0.f;

    for (int k0 = 0; k0 < K; k0 += 16) {
        #pragma unroll
        for (int i = 0; i < 2; i++) {
            int f = tid + i * 256;
            int r = f >> 2;
            int c = (f & 3) << 2;
            float4 v = *reinterpret_cast<const float4*>(A + (size_t)(row0 + r) * K + (k0 + c));
            As[c + 0][r] = v.x; As[c + 1][r] = v.y; As[c + 2][r] = v.z; As[c + 3][r] = v.w;
        }
        {
            int r = tid >> 2;
            int c = (tid & 3) << 2;
            float4 v = *reinterpret_cast<const float4*>(W + (size_t)(col0 + r) * K + (k0 + c));
            Bs[c + 0][r] = v.x; Bs[c + 1][r] = v.y; Bs[c + 2][r] = v.z; Bs[c + 3][r] = v.w;
        }
        __syncthreads();
        #pragma unroll
        for (int k = 0; k < 16; k++) {
            float4 a0 = *reinterpret_cast<const float4*>(&As[k][ty * 8]);
            float4 a1 = *reinterpret_cast<const float4*>(&As[k][ty * 8 + 4]);
            float4 b4 = *reinterpret_cast<const float4*>(&Bs[k][tx * 4]);
            float av[8] = {a0.x, a0.y, a0.z, a0.w, a1.x, a1.y, a1.z, a1.w};
            float bv[4] = {b4.x, b4.y, b4.z, b4.w};
            #pragma unroll
            for (int i = 0; i < 8; i++)
                #pragma unroll
                for (int j = 0; j < 4; j++)
                    acc[i][j] = fmaf(av[i], bv[j], acc[i][j]);
        }
        __syncthreads();
    }
    #pragma unroll
    for (int j = 0; j < 4; j++) {
        int col = col0 + tx * 4 + j;
        float bv = bias ? bias[col] : 0.f;
        #pragma unroll
        for (int i = 0; i < 8; i++) {
            float v = acc[i][j] + bv;
            if (act == 1) v = fmaxf(v, 0.f);
            C[(size_t)(row0 + ty * 8 + i) * ldc + coff + col] = v;
        }
    }
}

// ---------------- conv weight repack: [dil][ho][hi][k] -> [dil][k][ho][hi] ----------------
__global__ void repack_convw(const float* __restrict__ cw, float* __restrict__ out) {
    int idx = blockIdx.x * blockDim.x + threadIdx.x;
    const int total = NDIL * 3 * HDIM * HDIM;
    if (idx >= total) return;
    int hi = idx & (HDIM - 1);
    int t = idx >> 10;
    int ho = t & (HDIM - 1);
    int t2 = t >> 10;
    int k = t2 % 3;
    int d = t2 / 3;
    out[idx] = cw[(((size_t)d * HDIM + ho) * HDIM + hi) * 3 + k];
}

__global__ void zero_usage(float* usage) {
    int i = blockIdx.x * blockDim.x + threadIdx.x;
    if (i < PDIM) usage[i] = 0.f;
}

// ---------------- fused top-2 + softmax + expert mix + usage ----------------
__device__ __forceinline__ void ins2(float& v1, int& i1, float& v2, int& i2, float v, int i) {
    if (i == i1 || i == i2) return;
    if (v > v1 || (v == v1 && i < i1)) { v2 = v1; i2 = i1; v1 = v; i1 = i; }
    else if (v > v2 || (v == v2 && i < i2)) { v2 = v; i2 = i; }
}

__global__ void __launch_bounds__(256) topk_map_kernel(
    const float* __restrict__ logits, const float* __restrict__ tpool,
    const float* __restrict__ temp_p, float* __restrict__ combined,
    float* __restrict__ usage)
{
    int gw = (blockIdx.x * blockDim.x + threadIdx.x) >> 5;
    int lane = threadIdx.x & 31;
    if (gw >= NTOK) return;
    float temp = fminf(fmaxf(*temp_p, 0.1f), 5.0f);
    const float* lrow = logits + (size_t)gw * PDIM;
    float v1 = -FLT_MAX, v2 = -FLT_MAX;
    int i1 = 0x3fffffff, i2 = 0x3fffffff;
    for (int j = lane; j < PDIM; j += 32) {
        float v = fminf(fmaxf(lrow[j] / temp, -10.f), 10.f);
        ins2(v1, i1, v2, i2, v, j);
    }
    #pragma unroll
    for (int off = 16; off; off >>= 1) {
        float ov1 = __shfl_xor_sync(0xffffffffu, v1, off);
        int   oi1 = __shfl_xor_sync(0xffffffffu, i1, off);
        float ov2 = __shfl_xor_sync(0xffffffffu, v2, off);
        int   oi2 = __shfl_xor_sync(0xffffffffu, i2, off);
        ins2(v1, i1, v2, i2, ov1, oi1);
        ins2(v1, i1, v2, i2, ov2, oi2);
    }
    float e = expf(v2 - v1);
    float w1 = 1.f / (1.f + e);
    float w2 = e / (1.f + e);
    if (lane == 0) {
        atomicAdd(&usage[i1], w1);
        atomicAdd(&usage[i2], w2);
    }
    const float* p1 = tpool + (size_t)i1 * DDIM;
    const float* p2 = tpool + (size_t)i2 * DDIM;
    float* dst = combined + (size_t)gw * (2 * DDIM) + DDIM;
    for (int d = lane; d < DDIM; d += 32)
        dst[d] = w1 * p1[d] + w2 * p2[d];
}

// ---------------- layernorm over D=512, writes combined[:, :512] ----------------
__global__ void ln_kernel(const float* __restrict__ proj, const float* __restrict__ g,
                          const float* __restrict__ b, float* __restrict__ combined)
{
    __shared__ float sh[33];
    int n = blockIdx.x;
    const float* row = proj + (size_t)n * DDIM;
    float v[4];
    float s = 0.f;
    #pragma unroll
    for (int j = 0; j < 4; j++) { v[j] = row[threadIdx.x + j * 128]; s += v[j]; }
    float mean = block_reduce_sum(s, sh) * (1.f / DDIM);
    float q = 0.f;
    #pragma unroll
    for (int j = 0; j < 4; j++) { float d = v[j] - mean; q += d * d; }
    float var = block_reduce_sum(q, sh) * (1.f / DDIM);
    float rstd = rsqrtf(var + 1e-5f);
    float* dst = combined + (size_t)n * (2 * DDIM);
    #pragma unroll
    for (int j = 0; j < 4; j++) {
        int idx = threadIdx.x + j * 128;
        dst[idx] = (v[j] - mean) * rstd * g[idx] + b[idx];
    }
}

// ---------------- gate + final mix ----------------
__global__ void gate_combine(const float* __restrict__ x, const float* __restrict__ wg,
                             const float* __restrict__ bg, const float* __restrict__ local,
                             const float* __restrict__ glob, float* __restrict__ out)
{
    __shared__ float sh[33];
    int n = blockIdx.x;
    const float* xr = x + (size_t)n * HDIM;
    float s = 0.f;
    for (int j = threadIdx.x; j < HDIM; j += 128) s += xr[j] * wg[j];
    float dot = block_reduce_sum(s, sh);
    float g = 1.f / (1.f + expf(-(dot + bg[0])));
    const float* lr = local + (size_t)n * HDIM;
    const float* gr = glob + (size_t)n * HDIM;
    float* orow = out + (size_t)n * HDIM;
    for (int j = threadIdx.x; j < HDIM; j += 128)
        orow[j] = g * lr[j] + (1.f - g) * gr[j];
}

// ---------------- diversity loss ----------------
__global__ void divloss_kernel(const float* __restrict__ usage, float* __restrict__ out) {
    __shared__ float sh[33];
    float s = 0.f;
    for (int j = threadIdx.x; j < PDIM; j += 1024) s += usage[j];
    float total = block_reduce_sum(s, sh);
    float inv = 1.f / (total + 1e-8f);
    float q = 0.f;
    const float ip = 1.f / (float)PDIM;
    for (int j = threadIdx.x; j < PDIM; j += 1024) {
        float f = usage[j] * inv - ip;
        q += f * f;
    }
    float qt = block_reduce_sum(q, sh);
    if (threadIdx.x == 0) out[0] = (qt / (float)PDIM) * 0.01f;
}

// ---------------- host launcher ----------------
extern "C" void kernel_launch(void* const* d_in, const int* in_sizes, int n_in,
                              void* d_out, int out_size)
{
    const float* x      = (const float*)d_in[0];
    const float* tpool  = (const float*)d_in[1];
    const float* w1     = (const float*)d_in[2];
    const float* b1     = (const float*)d_in[3];
    const float* w2     = (const float*)d_in[4];
    const float* b2     = (const float*)d_in[5];
    const float* temp   = (const float*)d_in[6];
    const float* wproj  = (const float*)d_in[7];
    const float* bproj  = (const float*)d_in[8];
    const float* ln_g   = (const float*)d_in[9];
    const float* ln_b   = (const float*)d_in[10];
    const float* wmap   = (const float*)d_in[11];
    const float* bmap   = (const float*)d_in[12];
    const float* conv_w = (const float*)d_in[13];
    const float* conv_b = (const float*)d_in[14];
    const float* wout   = (const float*)d_in[15];
    const float* bout   = (const float*)d_in[16];
    const float* wrp    = (const float*)d_in[17];
    const float* brp    = (const float*)d_in[18];
    const float* wg     = (const float*)d_in[19];
    const float* bg     = (const float*)d_in[20];
    float* out = (float*)d_out;

    float *inter, *logits, *concat, *local, *combined, *transf, *glob, *proj, *convwt, *usage;
    cudaGetSymbolAddress((void**)&inter,    g_inter);
    cudaGetSymbolAddress((void**)&logits,   g_logits);
    cudaGetSymbolAddress((void**)&concat,   g_concat);
    cudaGetSymbolAddress((void**)&local,    g_local);
    cudaGetSymbolAddress((void**)&combined, g_combined);
    cudaGetSymbolAddress((void**)&transf,   g_transf);
    cudaGetSymbolAddress((void**)&glob,     g_global);
    cudaGetSymbolAddress((void**)&proj,     g_proj);
    cudaGetSymbolAddress((void**)&convwt,   g_convwt);
    cudaGetSymbolAddress((void**)&usage,    g_usage);

    const int TF_SMEM = 4 * 128 * TFPAD * sizeof(float);  // 73728 B
    static bool attr_set = false;
    if (!attr_set) {
        cudaFuncSetAttribute(gemm_tf32<false>, cudaFuncAttributeMaxDynamicSharedMemorySize, TF_SMEM);
        cudaFuncSetAttribute(gemm_tf32<true>,  cudaFuncAttributeMaxDynamicSharedMemorySize, TF_SMEM);
        attr_set = true;
    }

    const int total_cw = NDIL * 3 * HDIM * HDIM;
    repack_convw<<<(total_cw + 255) / 256, 256>>>(conv_w, convwt);
    zero_usage<<<(PDIM + 255) / 256, 256>>>(usage);

    // ---- router MLP: exact fp32 (top-k selection sensitivity) ----
    gemm_bias_act<<<dim3(INTER_DIM / 64, NTOK / 128), 256>>>(
        x, w1, b1, inter, NTOK, INTER_DIM, HDIM, INTER_DIM, 0, 1);
    gemm_bias_act<<<dim3(PDIM / 64, NTOK / 128), 256>>>(
        inter, w2, b2, logits, NTOK, PDIM, INTER_DIM, PDIM, 0, 0);

    // fused top-2 + expert mix -> combined[:, 512:]
    topk_map_kernel<<<(NTOK * 32 + 255) / 256, 256>>>(logits, tpool, temp, combined, usage);

    // ---- projected_x (tf32) -> LN -> combined[:, :512] ----
    gemm_tf32<false><<<dim3(DDIM / 128, NTOK / 128), 256, TF_SMEM>>>(
        x, wproj, bproj, proj, NTOK, DDIM, HDIM, DDIM, 0, 0, 0);
    ln_kernel<<<NTOK, 128>>>(proj, ln_g, ln_b, combined);

    // ---- dilated convs (tf32 virtual im2col + fused GELU) -> concat ----
    const int dils[NDIL] = {1, 2, 4};
    for (int i = 0; i < NDIL; i++)
        gemm_tf32<true><<<dim3(HDIM / 128, NTOK / 128), 256, TF_SMEM>>>(
            x, convwt + (size_t)i * 3 * HDIM * HDIM, conv_b + i * HDIM, concat,
            NTOK, HDIM, 3 * HDIM, 3 * HDIM, i * HDIM, 2, dils[i]);

    // ---- local out (tf32) ----
    gemm_tf32<false><<<dim3(HDIM / 128, NTOK / 128), 256, TF_SMEM>>>(
        concat, wout, bout, local, NTOK, HDIM, 3 * HDIM, HDIM, 0, 0, 0);

    // ---- transformation + global out (tf32) ----
    gemm_tf32<false><<<dim3(DDIM / 128, NTOK / 128), 256, TF_SMEM>>>(
        combined, wmap, bmap, transf, NTOK, DDIM, 2 * DDIM, DDIM, 0, 0, 0);
    gemm_tf32<false><<<dim3(HDIM / 128, NTOK / 128), 256, TF_SMEM>>>(
        transf, wrp, brp, glob, NTOK, HDIM, DDIM, HDIM, 0, 0, 0);

    // gate + mix -> out
    gate_combine<<<NTOK, 128>>>(x, wg, bg, local, glob, out);

    // diversity loss -> last output element
    if (out_size > NTOK * HDIM)
        divloss_kernel<<<1, 1024>>>(usage, out + (size_t)NTOK * HDIM);
}

// round 4
// speedup vs baseline: 2.7356x; 1.3435x over previous
#include <cuda_runtime.h>
#include <cstdint>
#include <float.h>

// ---------------- problem constants ----------------
#define BDIM 4
#define SDIM 4096
#define HDIM 1024
#define PDIM 4096
#define DDIM 512
#define NTOK (BDIM * SDIM)          // 16384
#define INTER_DIM 1024
#define NDIL 3

// ---------------- scratch (device globals; no allocs allowed) ----------------
__device__ float g_inter[NTOK * INTER_DIM];        // 64 MB
__device__ float g_logits[(size_t)NTOK * PDIM];    // 256 MB (tf32-accurate)
__device__ float g_concat[(size_t)NTOK * 3 * HDIM];// 192 MB
__device__ float g_local[NTOK * HDIM];             // 64 MB
__device__ float g_combined[NTOK * 2 * DDIM];      // 64 MB  [LN(proj) | weighted_map]
__device__ float g_transf[NTOK * DDIM];            // 32 MB
__device__ float g_global[NTOK * HDIM];            // 64 MB
__device__ float g_proj[NTOK * DDIM];              // 32 MB
__device__ float g_convwt[NDIL * 3 * HDIM * HDIM]; // 36 MB, [dil][k][ho][hi]
__device__ float g_usage[PDIM];

// ---------------- helpers ----------------
__device__ __forceinline__ float block_reduce_sum(float v, float* sh) {
    int tid = threadIdx.x;
    #pragma unroll
    for (int o = 16; o; o >>= 1) v += __shfl_xor_sync(0xffffffffu, v, o);
    if ((tid & 31) == 0) sh[tid >> 5] = v;
    __syncthreads();
    int nw = blockDim.x >> 5;
    float r = (tid < nw) ? sh[tid] : 0.f;
    if (tid < 32) {
        #pragma unroll
        for (int o = 16; o; o >>= 1) r += __shfl_xor_sync(0xffffffffu, r, o);
        if (tid == 0) sh[32] = r;
    }
    __syncthreads();
    float total = sh[32];
    __syncthreads();
    return total;
}

__device__ __forceinline__ unsigned cvt_tf32(float x) {
    unsigned r;
    asm("cvt.rna.tf32.f32 %0, %1;" : "=r"(r) : "f"(x));
    return r;
}

__device__ __forceinline__ void mma_tf32(float* c, const unsigned* a, const unsigned* b) {
    asm volatile(
        "mma.sync.aligned.m16n8k8.row.col.f32.tf32.tf32.f32 "
        "{%0,%1,%2,%3}, {%4,%5,%6,%7}, {%8,%9}, {%0,%1,%2,%3};\n"
        : "+f"(c[0]), "+f"(c[1]), "+f"(c[2]), "+f"(c[3])
        : "r"(a[0]), "r"(a[1]), "r"(a[2]), "r"(a[3]), "r"(b[0]), "r"(b[1]));
}

__device__ __forceinline__ void cp16(void* dst_smem, const float* src, bool pred) {
    unsigned d = (unsigned)__cvta_generic_to_shared(dst_smem);
    int sz = pred ? 16 : 0;
    asm volatile("cp.async.cg.shared.global [%0], [%1], 16, %2;\n"
                 :: "r"(d), "l"(src), "r"(sz));
}

// =====================================================================
// TF32 tensor-core GEMM: C = act(A[M,K] @ W[Ncols,K]^T + bias)
// BM=BN=128, BK=32, 256 threads (8 warps, 2x4), warp tile 64x32,
// mma m16n8k8 tf32, cp.async double-buffered smem.
// =====================================================================
#define TFPAD 36   // row stride in floats (32 + 4 pad)

template<bool CONV>
__global__ void __launch_bounds__(256) gemm_tf32(
    const float* __restrict__ A, const float* __restrict__ W,
    const float* __restrict__ bias, float* __restrict__ C,
    int M, int Ncols, int K, int ldc, int coff, int act, int dil)
{
    extern __shared__ float smem[];
    float* As = smem;                     // [2][128][TFPAD]
    float* Bs = smem + 2 * 128 * TFPAD;   // [2][128][TFPAD]

    const int tid = threadIdx.x;
    const int lane = tid & 31;
    const int wid = tid >> 5;
    const int wm = wid >> 2;
    const int wn = wid & 3;
    const int g = lane >> 2;
    const int t = lane & 3;
    const int row0 = blockIdx.y * 128;
    const int col0 = blockIdx.x * 128;
    const int KT = K >> 5;

    float acc[4][4][4];
    #pragma unroll
    for (int i = 0; i < 4; i++)
        #pragma unroll
        for (int j = 0; j < 4; j++)
            #pragma unroll
            for (int q = 0; q < 4; q++) acc[i][j][q] = 0.f;

    auto load_tile = [&](int kt, int buf) {
        int k0 = kt << 5;
        int ksl = 0, h0 = k0, shift = 0;
        if (CONV) {
            ksl = k0 >> 10;
            h0 = k0 & (HDIM - 1);
            shift = (ksl - 1) * dil;
        }
        float* Ad = As + buf * 128 * TFPAD;
        float* Bd = Bs + buf * 128 * TFPAD;
        #pragma unroll
        for (int i = 0; i < 4; i++) {
            int idx = tid + i * 256;
            int r = idx >> 3;
            int c4 = (idx & 7) << 2;
            const float* srcA;
            bool pred = true;
            if (CONV) {
                int n = row0 + r;
                int s2 = (n & (SDIM - 1)) + shift;
                pred = ((unsigned)s2 < (unsigned)SDIM);
                srcA = pred ? (A + (size_t)(n + shift) * HDIM + h0 + c4) : A;
            } else {
                srcA = A + (size_t)(row0 + r) * K + k0 + c4;
            }
            cp16(Ad + r * TFPAD + c4, srcA, pred);
            const float* srcB;
            if (CONV)
                srcB = W + ((size_t)ksl * HDIM + col0 + r) * HDIM + h0 + c4;
            else
                srcB = W + (size_t)(col0 + r) * K + k0 + c4;
            cp16(Bd + r * TFPAD + c4, srcB, true);
        }
    };

    load_tile(0, 0);
    asm volatile("cp.async.commit_group;\n" ::);

    for (int kt = 0; kt < KT; kt++) {
        int buf = kt & 1;
        if (kt + 1 < KT) load_tile(kt + 1, buf ^ 1);
        asm volatile("cp.async.commit_group;\n" ::);
        asm volatile("cp.async.wait_group 1;\n" ::);
        __syncthreads();

        const float* AsB = As + buf * 128 * TFPAD;
        const float* BsB = Bs + buf * 128 * TFPAD;
        #pragma unroll
        for (int kk = 0; kk < 4; kk++) {
            unsigned af[4][4], bf[4][2];
            #pragma unroll
            for (int mt = 0; mt < 4; mt++) {
                const float* p = AsB + (wm * 64 + mt * 16 + g) * TFPAD + kk * 8 + t;
                af[mt][0] = cvt_tf32(p[0]);
                af[mt][1] = cvt_tf32(p[8 * TFPAD]);
                af[mt][2] = cvt_tf32(p[4]);
                af[mt][3] = cvt_tf32(p[8 * TFPAD + 4]);
            }
            #pragma unroll
            for (int nt = 0; nt < 4; nt++) {
                const float* p = BsB + (wn * 32 + nt * 8 + g) * TFPAD + kk * 8 + t;
                bf[nt][0] = cvt_tf32(p[0]);
                bf[nt][1] = cvt_tf32(p[4]);
            }
            #pragma unroll
            for (int mt = 0; mt < 4; mt++)
                #pragma unroll
                for (int nt = 0; nt < 4; nt++)
                    mma_tf32(acc[mt][nt], af[mt], bf[nt]);
        }
        __syncthreads();
    }

    #pragma unroll
    for (int mt = 0; mt < 4; mt++) {
        int r0 = row0 + wm * 64 + mt * 16 + g;
        int r1 = r0 + 8;
        #pragma unroll
        for (int nt = 0; nt < 4; nt++) {
            int c = col0 + wn * 32 + nt * 8 + 2 * t;
            float b0v = bias ? bias[c] : 0.f;
            float b1v = bias ? bias[c + 1] : 0.f;
            float v[4] = {acc[mt][nt][0] + b0v, acc[mt][nt][1] + b1v,
                          acc[mt][nt][2] + b0v, acc[mt][nt][3] + b1v};
            if (CONV || act == 2) {
                #pragma unroll
                for (int q = 0; q < 4; q++)
                    v[q] = 0.5f * v[q] * (1.f + erff(v[q] * 0.70710678118654752f));
            } else if (act == 1) {
                #pragma unroll
                for (int q = 0; q < 4; q++) v[q] = fmaxf(v[q], 0.f);
            }
            *reinterpret_cast<float2*>(C + (size_t)r0 * ldc + coff + c) = make_float2(v[0], v[1]);
            *reinterpret_cast<float2*>(C + (size_t)r1 * ldc + coff + c) = make_float2(v[2], v[3]);
        }
    }
}

// ---------------- fp32 SIMT GEMM (router inter only — exact) ----------------
__global__ void __launch_bounds__(256) gemm_bias_act(
    const float* __restrict__ A, const float* __restrict__ W,
    const float* __restrict__ bias, float* __restrict__ C,
    int M, int Ncols, int K, int ldc, int coff, int act)
{
    __shared__ float As[16][132];
    __shared__ float Bs[16][68];
    const int tid = threadIdx.x;
    const int tx = tid & 15;
    const int ty = tid >> 4;
    const int row0 = blockIdx.y * 128;
    const int col0 = blockIdx.x * 64;

    float acc[8][4];
    #pragma unroll
    for (int i = 0; i < 8; i++)
        #pragma unroll
        for (int j = 0; j < 4; j++) acc[i][j] = 0.f;

    for (int k0 = 0; k0 < K; k0 += 16) {
        #pragma unroll
        for (int i = 0; i < 2; i++) {
            int f = tid + i * 256;
            int r = f >> 2;
            int c = (f & 3) << 2;
            float4 v = *reinterpret_cast<const float4*>(A + (size_t)(row0 + r) * K + (k0 + c));
            As[c + 0][r] = v.x; As[c + 1][r] = v.y; As[c + 2][r] = v.z; As[c + 3][r] = v.w;
        }
        {
            int r = tid >> 2;
            int c = (tid & 3) << 2;
            float4 v = *reinterpret_cast<const float4*>(W + (size_t)(col0 + r) * K + (k0 + c));
            Bs[c + 0][r] = v.x; Bs[c + 1][r] = v.y; Bs[c + 2][r] = v.z; Bs[c + 3][r] = v.w;
        }
        __syncthreads();
        #pragma unroll
        for (int k = 0; k < 16; k++) {
            float4 a0 = *reinterpret_cast<const float4*>(&As[k][ty * 8]);
            float4 a1 = *reinterpret_cast<const float4*>(&As[k][ty * 8 + 4]);
            float4 b4 = *reinterpret_cast<const float4*>(&Bs[k][tx * 4]);
            float av[8] = {a0.x, a0.y, a0.z, a0.w, a1.x, a1.y, a1.z, a1.w};
            float bv[4] = {b4.x, b4.y, b4.z, b4.w};
            #pragma unroll
            for (int i = 0; i < 8; i++)
                #pragma unroll
                for (int j = 0; j < 4; j++)
                    acc[i][j] = fmaf(av[i], bv[j], acc[i][j]);
        }
        __syncthreads();
    }
    #pragma unroll
    for (int j = 0; j < 4; j++) {
        int col = col0 + tx * 4 + j;
        float bv = bias ? bias[col] : 0.f;
        #pragma unroll
        for (int i = 0; i < 8; i++) {
            float v = acc[i][j] + bv;
            if (act == 1) v = fmaxf(v, 0.f);
            C[(size_t)(row0 + ty * 8 + i) * ldc + coff + col] = v;
        }
    }
}

// ---------------- conv weight repack ----------------
__global__ void repack_convw(const float* __restrict__ cw, float* __restrict__ out) {
    int idx = blockIdx.x * blockDim.x + threadIdx.x;
    const int total = NDIL * 3 * HDIM * HDIM;
    if (idx >= total) return;
    int hi = idx & (HDIM - 1);
    int t = idx >> 10;
    int ho = t & (HDIM - 1);
    int t2 = t >> 10;
    int k = t2 % 3;
    int d = t2 / 3;
    out[idx] = cw[(((size_t)d * HDIM + ho) * HDIM + hi) * 3 + k];
}

__global__ void zero_usage(float* usage) {
    int i = blockIdx.x * blockDim.x + threadIdx.x;
    if (i < PDIM) usage[i] = 0.f;
}

// ---------------- top-8 candidates (tf32 logits) + fp32 rescore + top-2 ----------------
__device__ __forceinline__ bool better(float va, int ia, float vb, int ib) {
    return (va > vb) || (va == vb && ia < ib);
}

__device__ __forceinline__ void ins2(float& v1, int& i1, float& v2, int& i2, float v, int i) {
    if (better(v, i, v1, i1)) { v2 = v1; i2 = i1; v1 = v; i1 = i; }
    else if (better(v, i, v2, i2)) { v2 = v; i2 = i; }
}

__global__ void __launch_bounds__(256) topk_rescore_kernel(
    const float* __restrict__ logits,     // tf32-accurate [NTOK, PDIM]
    const float* __restrict__ inter,      // fp32-exact    [NTOK, INTER_DIM]
    const float* __restrict__ w2,         // [PDIM, INTER_DIM]
    const float* __restrict__ b2,
    const float* __restrict__ tpool,
    const float* __restrict__ temp_p, float* __restrict__ combined,
    float* __restrict__ usage)
{
    int gw = (blockIdx.x * blockDim.x + threadIdx.x) >> 5;
    int lane = threadIdx.x & 31;
    if (gw >= NTOK) return;
    float temp = fminf(fmaxf(*temp_p, 0.1f), 5.0f);
    float invt = 1.f / temp;

    // ---- per-lane sorted top-8 over its stripe of the tf32 logits row ----
    const float* lrow = logits + (size_t)gw * PDIM;
    float tv[8]; int ti[8];
    #pragma unroll
    for (int k = 0; k < 8; k++) { tv[k] = -FLT_MAX; ti[k] = 0x3fffffff; }
    for (int j = lane; j < PDIM; j += 32) {
        float v = fminf(fmaxf(lrow[j] * invt, -10.f), 10.f);
        if (better(v, j, tv[7], ti[7])) {
            tv[7] = v; ti[7] = j;
            #pragma unroll
            for (int k = 7; k > 0; k--) {
                bool sw = better(tv[k], ti[k], tv[k - 1], ti[k - 1]);
                float av = sw ? tv[k] : tv[k - 1];
                float bv2 = sw ? tv[k - 1] : tv[k];
                int ai = sw ? ti[k] : ti[k - 1];
                int bi = sw ? ti[k - 1] : ti[k];
                tv[k - 1] = av; tv[k] = bv2; ti[k - 1] = ai; ti[k] = bi;
            }
        }
    }

    // ---- warp merge: extract exact warp top-8 (8 rounds of argmax + remove) ----
    int cand[8];
    #pragma unroll
    for (int r = 0; r < 8; r++) {
        float bvv = tv[0]; int bii = ti[0];
        #pragma unroll
        for (int off = 16; off; off >>= 1) {
            float ov = __shfl_xor_sync(0xffffffffu, bvv, off);
            int oi = __shfl_xor_sync(0xffffffffu, bii, off);
            if (better(ov, oi, bvv, bii)) { bvv = ov; bii = oi; }
        }
        cand[r] = bii;
        if (ti[0] == bii) {   // owner lane removes its head
            #pragma unroll
            for (int k = 0; k < 7; k++) { tv[k] = tv[k + 1]; ti[k] = ti[k + 1]; }
            tv[7] = -FLT_MAX; ti[7] = 0x3fffffff;
        }
    }

    // ---- fp32 rescore of the 8 candidates ----
    const float* irow = inter + (size_t)gw * INTER_DIM;
    float xv[32];
    #pragma unroll
    for (int q = 0; q < 32; q++) xv[q] = irow[lane + q * 32];

    float v1 = -FLT_MAX, v2 = -FLT_MAX;
    int i1 = 0x3fffffff, i2 = 0x3fffffff;
    #pragma unroll
    for (int r = 0; r < 8; r++) {
        const float* wrow = w2 + (size_t)cand[r] * INTER_DIM;
        float s = 0.f;
        #pragma unroll
        for (int q = 0; q < 32; q++) s = fmaf(xv[q], wrow[lane + q * 32], s);
        #pragma unroll
        for (int off = 16; off; off >>= 1) s += __shfl_xor_sync(0xffffffffu, s, off);
        float v = fminf(fmaxf((s + b2[cand[r]]) * invt, -10.f), 10.f);
        ins2(v1, i1, v2, i2, v, cand[r]);
    }

    // ---- softmax over top-2, usage, expert mix ----
    float e = expf(v2 - v1);
    float w1 = 1.f / (1.f + e);
    float w2s = e / (1.f + e);
    if (lane == 0) {
        atomicAdd(&usage[i1], w1);
        atomicAdd(&usage[i2], w2s);
    }
    const float* p1 = tpool + (size_t)i1 * DDIM;
    const float* p2 = tpool + (size_t)i2 * DDIM;
    float* dst = combined + (size_t)gw * (2 * DDIM) + DDIM;
    for (int d = lane; d < DDIM; d += 32)
        dst[d] = w1 * p1[d] + w2s * p2[d];
}

// ---------------- layernorm over D=512, writes combined[:, :512] ----------------
__global__ void ln_kernel(const float* __restrict__ proj, const float* __restrict__ g,
                          const float* __restrict__ b, float* __restrict__ combined)
{
    __shared__ float sh[33];
    int n = blockIdx.x;
    const float* row = proj + (size_t)n * DDIM;
    float v[4];
    float s = 0.f;
    #pragma unroll
    for (int j = 0; j < 4; j++) { v[j] = row[threadIdx.x + j * 128]; s += v[j]; }
    float mean = block_reduce_sum(s, sh) * (1.f / DDIM);
    float q = 0.f;
    #pragma unroll
    for (int j = 0; j < 4; j++) { float d = v[j] - mean; q += d * d; }
    float var = block_reduce_sum(q, sh) * (1.f / DDIM);
    float rstd = rsqrtf(var + 1e-5f);
    float* dst = combined + (size_t)n * (2 * DDIM);
    #pragma unroll
    for (int j = 0; j < 4; j++) {
        int idx = threadIdx.x + j * 128;
        dst[idx] = (v[j] - mean) * rstd * g[idx] + b[idx];
    }
}

// ---------------- gate + final mix ----------------
__global__ void gate_combine(const float* __restrict__ x, const float* __restrict__ wg,
                             const float* __restrict__ bg, const float* __restrict__ local,
                             const float* __restrict__ glob, float* __restrict__ out)
{
    __shared__ float sh[33];
    int n = blockIdx.x;
    const float* xr = x + (size_t)n * HDIM;
    float s = 0.f;
    for (int j = threadIdx.x; j < HDIM; j += 128) s += xr[j] * wg[j];
    float dot = block_reduce_sum(s, sh);
    float g = 1.f / (1.f + expf(-(dot + bg[0])));
    const float* lr = local + (size_t)n * HDIM;
    const float* gr = glob + (size_t)n * HDIM;
    float* orow = out + (size_t)n * HDIM;
    for (int j = threadIdx.x; j < HDIM; j += 128)
        orow[j] = g * lr[j] + (1.f - g) * gr[j];
}

// ---------------- diversity loss ----------------
__global__ void divloss_kernel(const float* __restrict__ usage, float* __restrict__ out) {
    __shared__ float sh[33];
    float s = 0.f;
    for (int j = threadIdx.x; j < PDIM; j += 1024) s += usage[j];
    float total = block_reduce_sum(s, sh);
    float inv = 1.f / (total + 1e-8f);
    float q = 0.f;
    const float ip = 1.f / (float)PDIM;
    for (int j = threadIdx.x; j < PDIM; j += 1024) {
        float f = usage[j] * inv - ip;
        q += f * f;
    }
    float qt = block_reduce_sum(q, sh);
    if (threadIdx.x == 0) out[0] = (qt / (float)PDIM) * 0.01f;
}

// ---------------- host launcher ----------------
extern "C" void kernel_launch(void* const* d_in, const int* in_sizes, int n_in,
                              void* d_out, int out_size)
{
    const float* x      = (const float*)d_in[0];
    const float* tpool  = (const float*)d_in[1];
    const float* w1     = (const float*)d_in[2];
    const float* b1     = (const float*)d_in[3];
    const float* w2     = (const float*)d_in[4];
    const float* b2     = (const float*)d_in[5];
    const float* temp   = (const float*)d_in[6];
    const float* wproj  = (const float*)d_in[7];
    const float* bproj  = (const float*)d_in[8];
    const float* ln_g   = (const float*)d_in[9];
    const float* ln_b   = (const float*)d_in[10];
    const float* wmap   = (const float*)d_in[11];
    const float* bmap   = (const float*)d_in[12];
    const float* conv_w = (const float*)d_in[13];
    const float* conv_b = (const float*)d_in[14];
    const float* wout   = (const float*)d_in[15];
    const float* bout   = (const float*)d_in[16];
    const float* wrp    = (const float*)d_in[17];
    const float* brp    = (const float*)d_in[18];
    const float* wg     = (const float*)d_in[19];
    const float* bg     = (const float*)d_in[20];
    float* out = (float*)d_out;

    float *inter, *logits, *concat, *local, *combined, *transf, *glob, *proj, *convwt, *usage;
    cudaGetSymbolAddress((void**)&inter,    g_inter);
    cudaGetSymbolAddress((void**)&logits,   g_logits);
    cudaGetSymbolAddress((void**)&concat,   g_concat);
    cudaGetSymbolAddress((void**)&local,    g_local);
    cudaGetSymbolAddress((void**)&combined, g_combined);
    cudaGetSymbolAddress((void**)&transf,   g_transf);
    cudaGetSymbolAddress((void**)&glob,     g_global);
    cudaGetSymbolAddress((void**)&proj,     g_proj);
    cudaGetSymbolAddress((void**)&convwt,   g_convwt);
    cudaGetSymbolAddress((void**)&usage,    g_usage);

    const int TF_SMEM = 4 * 128 * TFPAD * sizeof(float);  // 73728 B
    static bool attr_set = false;
    if (!attr_set) {
        cudaFuncSetAttribute(gemm_tf32<false>, cudaFuncAttributeMaxDynamicSharedMemorySize, TF_SMEM);
        cudaFuncSetAttribute(gemm_tf32<true>,  cudaFuncAttributeMaxDynamicSharedMemorySize, TF_SMEM);
        attr_set = true;
    }

    const int total_cw = NDIL * 3 * HDIM * HDIM;
    repack_convw<<<(total_cw + 255) / 256, 256>>>(conv_w, convwt);
    zero_usage<<<(PDIM + 255) / 256, 256>>>(usage);

    // ---- router: inter exact fp32, logits tf32 tensor, exact candidate rescore ----
    gemm_bias_act<<<dim3(INTER_DIM / 64, NTOK / 128), 256>>>(
        x, w1, b1, inter, NTOK, INTER_DIM, HDIM, INTER_DIM, 0, 1);
    gemm_tf32<false><<<dim3(PDIM / 128, NTOK / 128), 256, TF_SMEM>>>(
        inter, w2, b2, logits, NTOK, PDIM, INTER_DIM, PDIM, 0, 0, 0);

    topk_rescore_kernel<<<(NTOK * 32 + 255) / 256, 256>>>(
        logits, inter, w2, b2, tpool, temp, combined, usage);

    // ---- projected_x (tf32) -> LN -> combined[:, :512] ----
    gemm_tf32<false><<<dim3(DDIM / 128, NTOK / 128), 256, TF_SMEM>>>(
        x, wproj, bproj, proj, NTOK, DDIM, HDIM, DDIM, 0, 0, 0);
    ln_kernel<<<NTOK, 128>>>(proj, ln_g, ln_b, combined);

    // ---- dilated convs (tf32 virtual im2col + fused GELU) -> concat ----
    const int dils[NDIL] = {1, 2, 4};
    for (int i = 0; i < NDIL; i++)
        gemm_tf32<true><<<dim3(HDIM / 128, NTOK / 128), 256, TF_SMEM>>>(
            x, convwt + (size_t)i * 3 * HDIM * HDIM, conv_b + i * HDIM, concat,
            NTOK, HDIM, 3 * HDIM, 3 * HDIM, i * HDIM, 2, dils[i]);

    // ---- local out (tf32) ----
    gemm_tf32<false><<<dim3(HDIM / 128, NTOK / 128), 256, TF_SMEM>>>(
        concat, wout, bout, local, NTOK, HDIM, 3 * HDIM, HDIM, 0, 0, 0);

    // ---- transformation + global out (tf32) ----
    gemm_tf32<false><<<dim3(DDIM / 128, NTOK / 128), 256, TF_SMEM>>>(
        combined, wmap, bmap, transf, NTOK, DDIM, 2 * DDIM, DDIM, 0, 0, 0);
    gemm_tf32<false><<<dim3(HDIM / 128, NTOK / 128), 256, TF_SMEM>>>(
        transf, wrp, brp, glob, NTOK, HDIM, DDIM, HDIM, 0, 0, 0);

    // gate + mix -> out
    gate_combine<<<NTOK, 128>>>(x, wg, bg, local, glob, out);

    // diversity loss -> last output element
    if (out_size > NTOK * HDIM)
        divloss_kernel<<<1, 1024>>>(usage, out + (size_t)NTOK * HDIM);
}

// round 5
// speedup vs baseline: 2.9247x; 1.0691x over previous
#include <cuda_runtime.h>
#include <cstdint>
#include <float.h>

// ---------------- problem constants ----------------
#define BDIM 4
#define SDIM 4096
#define HDIM 1024
#define PDIM 4096
#define DDIM 512
#define NTOK (BDIM * SDIM)          // 16384
#define INTER_DIM 1024
#define NDIL 3

// ---------------- scratch (device globals; no allocs allowed) ----------------
__device__ float g_inter[NTOK * INTER_DIM];         // exact fp32 (rescore)
__device__ float g_intert[NTOK * INTER_DIM];        // tf32-rounded (logits A)
__device__ float g_logits[(size_t)NTOK * PDIM];
__device__ float g_concat[(size_t)NTOK * 3 * HDIM]; // tf32-rounded GELU out
__device__ float g_local[NTOK * HDIM];
__device__ float g_combined[NTOK * 2 * DDIM];       // tf32-rounded
__device__ float g_transf[NTOK * DDIM];             // tf32-rounded
__device__ float g_global[NTOK * HDIM];
__device__ float g_proj[NTOK * DDIM];
__device__ float g_convwt[NDIL * 3 * HDIM * HDIM];  // repacked + rounded
__device__ float g_usage[PDIM];
// pre-rounded operands
__device__ float g_xt[NTOK * HDIM];                 // hi(x)
__device__ float g_xlo[NTOK * HDIM];                // lo(x)
__device__ float g_w1hi[INTER_DIM * HDIM];
__device__ float g_w1lo[INTER_DIM * HDIM];
__device__ float g_w2t[(size_t)PDIM * INTER_DIM];
__device__ float g_wprojt[DDIM * HDIM];
__device__ float g_woutt[HDIM * 3 * HDIM];
__device__ float g_wmapt[DDIM * 2 * DDIM];
__device__ float g_wrpt[HDIM * DDIM];

// ---------------- helpers ----------------
__device__ __forceinline__ float block_reduce_sum(float v, float* sh) {
    int tid = threadIdx.x;
    #pragma unroll
    for (int o = 16; o; o >>= 1) v += __shfl_xor_sync(0xffffffffu, v, o);
    if ((tid & 31) == 0) sh[tid >> 5] = v;
    __syncthreads();
    int nw = blockDim.x >> 5;
    float r = (tid < nw) ? sh[tid] : 0.f;
    if (tid < 32) {
        #pragma unroll
        for (int o = 16; o; o >>= 1) r += __shfl_xor_sync(0xffffffffu, r, o);
        if (tid == 0) sh[32] = r;
    }
    __syncthreads();
    float total = sh[32];
    __syncthreads();
    return total;
}

__device__ __forceinline__ unsigned cvt_tf32(float x) {
    unsigned r;
    asm("cvt.rna.tf32.f32 %0, %1;" : "=r"(r) : "f"(x));
    return r;
}
__device__ __forceinline__ float round_tf32f(float x) {
    return __uint_as_float(cvt_tf32(x));
}

__device__ __forceinline__ void mma_tf32(float* c, const unsigned* a, const unsigned* b) {
    asm volatile(
        "mma.sync.aligned.m16n8k8.row.col.f32.tf32.tf32.f32 "
        "{%0,%1,%2,%3}, {%4,%5,%6,%7}, {%8,%9}, {%0,%1,%2,%3};\n"
        : "+f"(c[0]), "+f"(c[1]), "+f"(c[2]), "+f"(c[3])
        : "r"(a[0]), "r"(a[1]), "r"(a[2]), "r"(a[3]), "r"(b[0]), "r"(b[1]));
}

__device__ __forceinline__ void cp16(void* dst_smem, const float* src, bool pred) {
    unsigned d = (unsigned)__cvta_generic_to_shared(dst_smem);
    int sz = pred ? 16 : 0;
    asm volatile("cp.async.cg.shared.global [%0], [%1], 16, %2;\n"
                 :: "r"(d), "l"(src), "r"(sz));
}

// =====================================================================
// TF32 tensor-core GEMM, operands PRE-ROUNDED to tf32 (no cvt in loop).
// MODE 0: plain  C = act(A @ W^T + b)
// MODE 1: conv   A = virtual im2col of x (token shift per 1024-slice)
// MODE 2: 3xTF32 virtual K=3072: s0 Ahi*Whi, s1 Ahi*Wlo, s2 Alo*Whi
// BM=BN=128, BK=32, 256 threads, warp tile 64x32, cp.async dbl-buffer.
// act: 0 none, 1 relu, 2 gelu.  roundC: round stores to tf32.
// C2 (optional): rounded copy of C.
// =====================================================================
#define TFPAD 36

template<int MODE>
__global__ void __launch_bounds__(256) gemm_tf32(
    const float* __restrict__ A, const float* __restrict__ Alo,
    const float* __restrict__ W, const float* __restrict__ Wlo,
    const float* __restrict__ bias, float* __restrict__ C, float* __restrict__ C2,
    int K, int ldc, int coff, int act, int dil, int roundC)
{
    extern __shared__ float smem[];
    float* As = smem;
    float* Bs = smem + 2 * 128 * TFPAD;

    const int tid = threadIdx.x;
    const int lane = tid & 31;
    const int wid = tid >> 5;
    const int wm = wid >> 2;
    const int wn = wid & 3;
    const int g = lane >> 2;
    const int t = lane & 3;
    const int row0 = blockIdx.y * 128;
    const int col0 = blockIdx.x * 128;
    const int KT = K >> 5;

    float acc[4][4][4];
    #pragma unroll
    for (int i = 0; i < 4; i++)
        #pragma unroll
        for (int j = 0; j < 4; j++)
            #pragma unroll
            for (int q = 0; q < 4; q++) acc[i][j][q] = 0.f;

    auto load_tile = [&](int kt, int buf) {
        int k0 = kt << 5;
        int ksl = 0, h0 = k0, shift = 0;
        if (MODE == 1 || MODE == 2) {
            ksl = k0 >> 10;
            h0 = k0 & (HDIM - 1);
            if (MODE == 1) shift = (ksl - 1) * dil;
        }
        float* Ad = As + buf * 128 * TFPAD;
        float* Bd = Bs + buf * 128 * TFPAD;
        #pragma unroll
        for (int i = 0; i < 4; i++) {
            int idx = tid + i * 256;
            int r = idx >> 3;
            int c4 = (idx & 7) << 2;
            const float* srcA;
            bool pred = true;
            if (MODE == 1) {
                int n = row0 + r;
                int s2 = (n & (SDIM - 1)) + shift;
                pred = ((unsigned)s2 < (unsigned)SDIM);
                srcA = pred ? (A + (size_t)(n + shift) * HDIM + h0 + c4) : A;
            } else if (MODE == 2) {
                const float* Ab = (ksl == 2) ? Alo : A;
                srcA = Ab + (size_t)(row0 + r) * HDIM + h0 + c4;
            } else {
                srcA = A + (size_t)(row0 + r) * K + k0 + c4;
            }
            cp16(Ad + r * TFPAD + c4, srcA, pred);
            const float* srcB;
            if (MODE == 1)
                srcB = W + ((size_t)ksl * HDIM + col0 + r) * HDIM + h0 + c4;
            else if (MODE == 2) {
                const float* Wb = (ksl == 1) ? Wlo : W;
                srcB = Wb + (size_t)(col0 + r) * HDIM + h0 + c4;
            } else
                srcB = W + (size_t)(col0 + r) * K + k0 + c4;
            cp16(Bd + r * TFPAD + c4, srcB, true);
        }
    };

    load_tile(0, 0);
    asm volatile("cp.async.commit_group;\n" ::);

    for (int kt = 0; kt < KT; kt++) {
        int buf = kt & 1;
        if (kt + 1 < KT) load_tile(kt + 1, buf ^ 1);
        asm volatile("cp.async.commit_group;\n" ::);
        asm volatile("cp.async.wait_group 1;\n" ::);
        __syncthreads();

        const unsigned* AsB = reinterpret_cast<const unsigned*>(As + buf * 128 * TFPAD);
        const unsigned* BsB = reinterpret_cast<const unsigned*>(Bs + buf * 128 * TFPAD);
        #pragma unroll
        for (int kk = 0; kk < 4; kk++) {
            unsigned af[4][4], bf[4][2];
            #pragma unroll
            for (int mt = 0; mt < 4; mt++) {
                const unsigned* p = AsB + (wm * 64 + mt * 16 + g) * TFPAD + kk * 8 + t;
                af[mt][0] = p[0];
                af[mt][1] = p[8 * TFPAD];
                af[mt][2] = p[4];
                af[mt][3] = p[8 * TFPAD + 4];
            }
            #pragma unroll
            for (int nt = 0; nt < 4; nt++) {
                const unsigned* p = BsB + (wn * 32 + nt * 8 + g) * TFPAD + kk * 8 + t;
                bf[nt][0] = p[0];
                bf[nt][1] = p[4];
            }
            #pragma unroll
            for (int mt = 0; mt < 4; mt++)
                #pragma unroll
                for (int nt = 0; nt < 4; nt++)
                    mma_tf32(acc[mt][nt], af[mt], bf[nt]);
        }
        __syncthreads();
    }

    #pragma unroll
    for (int mt = 0; mt < 4; mt++) {
        int r0 = row0 + wm * 64 + mt * 16 + g;
        int r1 = r0 + 8;
        #pragma unroll
        for (int nt = 0; nt < 4; nt++) {
            int c = col0 + wn * 32 + nt * 8 + 2 * t;
            float b0v = bias ? bias[c] : 0.f;
            float b1v = bias ? bias[c + 1] : 0.f;
            float v[4] = {acc[mt][nt][0] + b0v, acc[mt][nt][1] + b1v,
                          acc[mt][nt][2] + b0v, acc[mt][nt][3] + b1v};
            if (act == 2) {
                #pragma unroll
                for (int q = 0; q < 4; q++)
                    v[q] = 0.5f * v[q] * (1.f + erff(v[q] * 0.70710678118654752f));
            } else if (act == 1) {
                #pragma unroll
                for (int q = 0; q < 4; q++) v[q] = fmaxf(v[q], 0.f);
            }
            float w0 = roundC ? round_tf32f(v[0]) : v[0];
            float w1v = roundC ? round_tf32f(v[1]) : v[1];
            float w2v = roundC ? round_tf32f(v[2]) : v[2];
            float w3v = roundC ? round_tf32f(v[3]) : v[3];
            *reinterpret_cast<float2*>(C + (size_t)r0 * ldc + coff + c) = make_float2(w0, w1v);
            *reinterpret_cast<float2*>(C + (size_t)r1 * ldc + coff + c) = make_float2(w2v, w3v);
            if (C2) {
                *reinterpret_cast<float2*>(C2 + (size_t)r0 * ldc + coff + c) =
                    make_float2(round_tf32f(v[0]), round_tf32f(v[1]));
                *reinterpret_cast<float2*>(C2 + (size_t)r1 * ldc + coff + c) =
                    make_float2(round_tf32f(v[2]), round_tf32f(v[3]));
            }
        }
    }
}

// ---------------- prep: rounding / hi-lo split / repack ----------------
__global__ void round_tf32_kernel(const float* __restrict__ src, float* __restrict__ dst, int n4) {
    int i = blockIdx.x * blockDim.x + threadIdx.x;
    if (i >= n4) return;
    float4 v = reinterpret_cast<const float4*>(src)[i];
    v.x = round_tf32f(v.x); v.y = round_tf32f(v.y);
    v.z = round_tf32f(v.z); v.w = round_tf32f(v.w);
    reinterpret_cast<float4*>(dst)[i] = v;
}

__global__ void split_tf32_kernel(const float* __restrict__ src, float* __restrict__ hi,
                                  float* __restrict__ lo, int n4) {
    int i = blockIdx.x * blockDim.x + threadIdx.x;
    if (i >= n4) return;
    float4 v = reinterpret_cast<const float4*>(src)[i];
    float4 h, l;
    h.x = round_tf32f(v.x); l.x = round_tf32f(v.x - h.x);
    h.y = round_tf32f(v.y); l.y = round_tf32f(v.y - h.y);
    h.z = round_tf32f(v.z); l.z = round_tf32f(v.z - h.z);
    h.w = round_tf32f(v.w); l.w = round_tf32f(v.w - h.w);
    reinterpret_cast<float4*>(hi)[i] = h;
    reinterpret_cast<float4*>(lo)[i] = l;
}

__global__ void repack_convw(const float* __restrict__ cw, float* __restrict__ out) {
    int idx = blockIdx.x * blockDim.x + threadIdx.x;
    const int total = NDIL * 3 * HDIM * HDIM;
    if (idx >= total) return;
    int hi = idx & (HDIM - 1);
    int t = idx >> 10;
    int ho = t & (HDIM - 1);
    int t2 = t >> 10;
    int k = t2 % 3;
    int d = t2 / 3;
    out[idx] = round_tf32f(cw[(((size_t)d * HDIM + ho) * HDIM + hi) * 3 + k]);
}

__global__ void zero_usage(float* usage) {
    int i = blockIdx.x * blockDim.x + threadIdx.x;
    if (i < PDIM) usage[i] = 0.f;
}

// ---------------- top-8 candidates (tf32 logits) + fp32 rescore + top-2 ----------------
__device__ __forceinline__ bool better(float va, int ia, float vb, int ib) {
    return (va > vb) || (va == vb && ia < ib);
}
__device__ __forceinline__ void ins2(float& v1, int& i1, float& v2, int& i2, float v, int i) {
    if (better(v, i, v1, i1)) { v2 = v1; i2 = i1; v1 = v; i1 = i; }
    else if (better(v, i, v2, i2)) { v2 = v; i2 = i; }
}

__global__ void __launch_bounds__(256) topk_rescore_kernel(
    const float* __restrict__ logits, const float* __restrict__ inter,
    const float* __restrict__ w2, const float* __restrict__ b2,
    const float* __restrict__ tpool, const float* __restrict__ temp_p,
    float* __restrict__ combined, float* __restrict__ usage)
{
    int gw = (blockIdx.x * blockDim.x + threadIdx.x) >> 5;
    int lane = threadIdx.x & 31;
    if (gw >= NTOK) return;
    float temp = fminf(fmaxf(*temp_p, 0.1f), 5.0f);
    float invt = 1.f / temp;

    const float* lrow = logits + (size_t)gw * PDIM;
    float tv[8]; int ti[8];
    #pragma unroll
    for (int k = 0; k < 8; k++) { tv[k] = -FLT_MAX; ti[k] = 0x3fffffff; }
    for (int j = lane; j < PDIM; j += 32) {
        float v = fminf(fmaxf(lrow[j] * invt, -10.f), 10.f);
        if (better(v, j, tv[7], ti[7])) {
            tv[7] = v; ti[7] = j;
            #pragma unroll
            for (int k = 7; k > 0; k--) {
                bool sw = better(tv[k], ti[k], tv[k - 1], ti[k - 1]);
                float av = sw ? tv[k] : tv[k - 1];
                float bv2 = sw ? tv[k - 1] : tv[k];
                int ai = sw ? ti[k] : ti[k - 1];
                int bi = sw ? ti[k - 1] : ti[k];
                tv[k - 1] = av; tv[k] = bv2; ti[k - 1] = ai; ti[k] = bi;
            }
        }
    }

    int cand[8];
    #pragma unroll
    for (int r = 0; r < 8; r++) {
        float bvv = tv[0]; int bii = ti[0];
        #pragma unroll
        for (int off = 16; off; off >>= 1) {
            float ov = __shfl_xor_sync(0xffffffffu, bvv, off);
            int oi = __shfl_xor_sync(0xffffffffu, bii, off);
            if (better(ov, oi, bvv, bii)) { bvv = ov; bii = oi; }
        }
        cand[r] = bii;
        if (ti[0] == bii) {
            #pragma unroll
            for (int k = 0; k < 7; k++) { tv[k] = tv[k + 1]; ti[k] = ti[k + 1]; }
            tv[7] = -FLT_MAX; ti[7] = 0x3fffffff;
        }
    }

    const float* irow = inter + (size_t)gw * INTER_DIM;
    float xv[32];
    #pragma unroll
    for (int q = 0; q < 32; q++) xv[q] = irow[lane + q * 32];

    float v1 = -FLT_MAX, v2 = -FLT_MAX;
    int i1 = 0x3fffffff, i2 = 0x3fffffff;
    #pragma unroll
    for (int r = 0; r < 8; r++) {
        const float* wrow = w2 + (size_t)cand[r] * INTER_DIM;
        float s = 0.f;
        #pragma unroll
        for (int q = 0; q < 32; q++) s = fmaf(xv[q], wrow[lane + q * 32], s);
        #pragma unroll
        for (int off = 16; off; off >>= 1) s += __shfl_xor_sync(0xffffffffu, s, off);
        float v = fminf(fmaxf((s + b2[cand[r]]) * invt, -10.f), 10.f);
        ins2(v1, i1, v2, i2, v, cand[r]);
    }

    float e = expf(v2 - v1);
    float w1 = 1.f / (1.f + e);
    float w2s = e / (1.f + e);
    if (lane == 0) {
        atomicAdd(&usage[i1], w1);
        atomicAdd(&usage[i2], w2s);
    }
    const float* p1 = tpool + (size_t)i1 * DDIM;
    const float* p2 = tpool + (size_t)i2 * DDIM;
    float* dst = combined + (size_t)gw * (2 * DDIM) + DDIM;
    for (int d = lane; d < DDIM; d += 32)
        dst[d] = round_tf32f(w1 * p1[d] + w2s * p2[d]);
}

// ---------------- layernorm over D=512, writes rounded combined[:, :512] ----------------
__global__ void ln_kernel(const float* __restrict__ proj, const float* __restrict__ g,
                          const float* __restrict__ b, float* __restrict__ combined)
{
    __shared__ float sh[33];
    int n = blockIdx.x;
    const float* row = proj + (size_t)n * DDIM;
    float v[4];
    float s = 0.f;
    #pragma unroll
    for (int j = 0; j < 4; j++) { v[j] = row[threadIdx.x + j * 128]; s += v[j]; }
    float mean = block_reduce_sum(s, sh) * (1.f / DDIM);
    float q = 0.f;
    #pragma unroll
    for (int j = 0; j < 4; j++) { float d = v[j] - mean; q += d * d; }
    float var = block_reduce_sum(q, sh) * (1.f / DDIM);
    float rstd = rsqrtf(var + 1e-5f);
    float* dst = combined + (size_t)n * (2 * DDIM);
    #pragma unroll
    for (int j = 0; j < 4; j++) {
        int idx = threadIdx.x + j * 128;
        dst[idx] = round_tf32f((v[j] - mean) * rstd * g[idx] + b[idx]);
    }
}

// ---------------- gate + final mix ----------------
__global__ void gate_combine(const float* __restrict__ x, const float* __restrict__ wg,
                             const float* __restrict__ bg, const float* __restrict__ local,
                             const float* __restrict__ glob, float* __restrict__ out)
{
    __shared__ float sh[33];
    int n = blockIdx.x;
    const float* xr = x + (size_t)n * HDIM;
    float s = 0.f;
    for (int j = threadIdx.x; j < HDIM; j += 128) s += xr[j] * wg[j];
    float dot = block_reduce_sum(s, sh);
    float g = 1.f / (1.f + expf(-(dot + bg[0])));
    const float* lr = local + (size_t)n * HDIM;
    const float* gr = glob + (size_t)n * HDIM;
    float* orow = out + (size_t)n * HDIM;
    for (int j = threadIdx.x; j < HDIM; j += 128)
        orow[j] = g * lr[j] + (1.f - g) * gr[j];
}

// ---------------- diversity loss ----------------
__global__ void divloss_kernel(const float* __restrict__ usage, float* __restrict__ out) {
    __shared__ float sh[33];
    float s = 0.f;
    for (int j = threadIdx.x; j < PDIM; j += 1024) s += usage[j];
    float total = block_reduce_sum(s, sh);
    float inv = 1.f / (total + 1e-8f);
    float q = 0.f;
    const float ip = 1.f / (float)PDIM;
    for (int j = threadIdx.x; j < PDIM; j += 1024) {
        float f = usage[j] * inv - ip;
        q += f * f;
    }
    float qt = block_reduce_sum(q, sh);
    if (threadIdx.x == 0) out[0] = (qt / (float)PDIM) * 0.01f;
}

// ---------------- host launcher ----------------
extern "C" void kernel_launch(void* const* d_in, const int* in_sizes, int n_in,
                              void* d_out, int out_size)
{
    const float* x      = (const float*)d_in[0];
    const float* tpool  = (const float*)d_in[1];
    const float* w1     = (const float*)d_in[2];
    const float* b1     = (const float*)d_in[3];
    const float* w2     = (const float*)d_in[4];
    const float* b2     = (const float*)d_in[5];
    const float* temp   = (const float*)d_in[6];
    const float* wproj  = (const float*)d_in[7];
    const float* bproj  = (const float*)d_in[8];
    const float* ln_g   = (const float*)d_in[9];
    const float* ln_b   = (const float*)d_in[10];
    const float* wmap   = (const float*)d_in[11];
    const float* bmap   = (const float*)d_in[12];
    const float* conv_w = (const float*)d_in[13];
    const float* conv_b = (const float*)d_in[14];
    const float* wout   = (const float*)d_in[15];
    const float* bout   = (const float*)d_in[16];
    const float* wrp    = (const float*)d_in[17];
    const float* brp    = (const float*)d_in[18];
    const float* wg     = (const float*)d_in[19];
    const float* bg     = (const float*)d_in[20];
    float* out = (float*)d_out;

    float *inter, *intert, *logits, *concat, *local, *combined, *transf, *glob, *proj;
    float *convwt, *usage, *xt, *xlo, *w1hi, *w1lo, *w2t, *wprojt, *woutt, *wmapt, *wrpt;
    cudaGetSymbolAddress((void**)&inter,    g_inter);
    cudaGetSymbolAddress((void**)&intert,   g_intert);
    cudaGetSymbolAddress((void**)&logits,   g_logits);
    cudaGetSymbolAddress((void**)&concat,   g_concat);
    cudaGetSymbolAddress((void**)&local,    g_local);
    cudaGetSymbolAddress((void**)&combined, g_combined);
    cudaGetSymbolAddress((void**)&transf,   g_transf);
    cudaGetSymbolAddress((void**)&glob,     g_global);
    cudaGetSymbolAddress((void**)&proj,     g_proj);
    cudaGetSymbolAddress((void**)&convwt,   g_convwt);
    cudaGetSymbolAddress((void**)&usage,    g_usage);
    cudaGetSymbolAddress((void**)&xt,       g_xt);
    cudaGetSymbolAddress((void**)&xlo,      g_xlo);
    cudaGetSymbolAddress((void**)&w1hi,     g_w1hi);
    cudaGetSymbolAddress((void**)&w1lo,     g_w1lo);
    cudaGetSymbolAddress((void**)&w2t,      g_w2t);
    cudaGetSymbolAddress((void**)&wprojt,   g_wprojt);
    cudaGetSymbolAddress((void**)&woutt,    g_woutt);
    cudaGetSymbolAddress((void**)&wmapt,    g_wmapt);
    cudaGetSymbolAddress((void**)&wrpt,     g_wrpt);

    const int TF_SMEM = 4 * 128 * TFPAD * sizeof(float);  // 73728 B
    cudaFuncSetAttribute(gemm_tf32<0>, cudaFuncAttributeMaxDynamicSharedMemorySize, TF_SMEM);
    cudaFuncSetAttribute(gemm_tf32<1>, cudaFuncAttributeMaxDynamicSharedMemorySize, TF_SMEM);
    cudaFuncSetAttribute(gemm_tf32<2>, cudaFuncAttributeMaxDynamicSharedMemorySize, TF_SMEM);

    // ---- prep: repack+round conv weights, round/split operands ----
    const int total_cw = NDIL * 3 * HDIM * HDIM;
    repack_convw<<<(total_cw + 255) / 256, 256>>>(conv_w, convwt);
    zero_usage<<<(PDIM + 255) / 256, 256>>>(usage);
    split_tf32_kernel<<<(NTOK * HDIM / 4 + 255) / 256, 256>>>(x, xt, xlo, NTOK * HDIM / 4);
    split_tf32_kernel<<<(INTER_DIM * HDIM / 4 + 255) / 256, 256>>>(w1, w1hi, w1lo, INTER_DIM * HDIM / 4);
    round_tf32_kernel<<<((int)((size_t)PDIM * INTER_DIM / 4) + 255) / 256, 256>>>(w2, w2t, PDIM * INTER_DIM / 4);
    round_tf32_kernel<<<(DDIM * HDIM / 4 + 255) / 256, 256>>>(wproj, wprojt, DDIM * HDIM / 4);
    round_tf32_kernel<<<(HDIM * 3 * HDIM / 4 + 255) / 256, 256>>>(wout, woutt, HDIM * 3 * HDIM / 4);
    round_tf32_kernel<<<(DDIM * 2 * DDIM / 4 + 255) / 256, 256>>>(wmap, wmapt, DDIM * 2 * DDIM / 4);
    round_tf32_kernel<<<(HDIM * DDIM / 4 + 255) / 256, 256>>>(wrp, wrpt, HDIM * DDIM / 4);

    // ---- router inter: 3xTF32 split (near-fp32 exact), relu; dual write ----
    gemm_tf32<2><<<dim3(INTER_DIM / 128, NTOK / 128), 256, TF_SMEM>>>(
        xt, xlo, w1hi, w1lo, b1, inter, intert, 3 * HDIM, INTER_DIM, 0, 1, 0, 0);

    // ---- logits: single tf32 (candidates only) ----
    gemm_tf32<0><<<dim3(PDIM / 128, NTOK / 128), 256, TF_SMEM>>>(
        intert, nullptr, w2t, nullptr, b2, logits, nullptr, INTER_DIM, PDIM, 0, 0, 0, 0);

    topk_rescore_kernel<<<(NTOK * 32 + 255) / 256, 256>>>(
        logits, inter, w2, b2, tpool, temp, combined, usage);

    // ---- projected_x -> LN -> combined[:, :512] ----
    gemm_tf32<0><<<dim3(DDIM / 128, NTOK / 128), 256, TF_SMEM>>>(
        xt, nullptr, wprojt, nullptr, bproj, proj, nullptr, HDIM, DDIM, 0, 0, 0, 0);
    ln_kernel<<<NTOK, 128>>>(proj, ln_g, ln_b, combined);

    // ---- dilated convs (virtual im2col, GELU, rounded out) ----
    const int dils[NDIL] = {1, 2, 4};
    for (int i = 0; i < NDIL; i++)
        gemm_tf32<1><<<dim3(HDIM / 128, NTOK / 128), 256, TF_SMEM>>>(
            xt, nullptr, convwt + (size_t)i * 3 * HDIM * HDIM, nullptr, conv_b + i * HDIM,
            concat, nullptr, 3 * HDIM, 3 * HDIM, i * HDIM, 2, dils[i], 1);

    // ---- local out ----
    gemm_tf32<0><<<dim3(HDIM / 128, NTOK / 128), 256, TF_SMEM>>>(
        concat, nullptr, woutt, nullptr, bout, local, nullptr, 3 * HDIM, HDIM, 0, 0, 0, 0);

    // ---- transformation (rounded out) + global out ----
    gemm_tf32<0><<<dim3(DDIM / 128, NTOK / 128), 256, TF_SMEM>>>(
        combined, nullptr, wmapt, nullptr, bmap, transf, nullptr, 2 * DDIM, DDIM, 0, 0, 0, 1);
    gemm_tf32<0><<<dim3(HDIM / 128, NTOK / 128), 256, TF_SMEM>>>(
        transf, nullptr, wrpt, nullptr, brp, glob, nullptr, DDIM, HDIM, 0, 0, 0, 0);

    // gate + mix -> out
    gate_combine<<<NTOK, 128>>>(x, wg, bg, local, glob, out);

    // diversity loss -> last output element
    if (out_size > NTOK * HDIM)
        divloss_kernel<<<1, 1024>>>(usage, out + (size_t)NTOK * HDIM);
}

// round 6
// speedup vs baseline: 3.1660x; 1.0825x over previous
#include <cuda_runtime.h>
#include <cstdint>
#include <float.h>

// ---------------- problem constants ----------------
#define BDIM 4
#define SDIM 4096
#define HDIM 1024
#define PDIM 4096
#define DDIM 512
#define NTOK (BDIM * SDIM)          // 16384
#define INTER_DIM 1024
#define NDIL 3

// ---------------- scratch (device globals; no allocs allowed) ----------------
__device__ float g_inter[NTOK * INTER_DIM];         // exact fp32 (rescore)
__device__ float g_intert[NTOK * INTER_DIM];        // tf32-rounded (logits A)
__device__ float g_logits[(size_t)NTOK * PDIM];
__device__ float g_concat[(size_t)NTOK * 3 * HDIM]; // tf32-rounded GELU out
__device__ float g_local[NTOK * HDIM];
__device__ float g_combined[NTOK * 2 * DDIM];       // tf32-rounded
__device__ float g_transf[NTOK * DDIM];             // tf32-rounded
__device__ float g_global[NTOK * HDIM];
__device__ float g_proj[NTOK * DDIM];
__device__ float g_convwt[NDIL * 3 * HDIM * HDIM];  // repacked + rounded
__device__ float g_usage[PDIM];
// pre-rounded operands
__device__ float g_xt[NTOK * HDIM];                 // hi(x)
__device__ float g_xlo[NTOK * HDIM];                // lo(x)
__device__ float g_w1hi[INTER_DIM * HDIM];
__device__ float g_w1lo[INTER_DIM * HDIM];
__device__ float g_w2t[(size_t)PDIM * INTER_DIM];
__device__ float g_wprojt[DDIM * HDIM];
__device__ float g_woutt[HDIM * 3 * HDIM];
__device__ float g_wmapt[DDIM * 2 * DDIM];
__device__ float g_wrpt[HDIM * DDIM];

// ---------------- helpers ----------------
__device__ __forceinline__ float block_reduce_sum(float v, float* sh) {
    int tid = threadIdx.x;
    #pragma unroll
    for (int o = 16; o; o >>= 1) v += __shfl_xor_sync(0xffffffffu, v, o);
    if ((tid & 31) == 0) sh[tid >> 5] = v;
    __syncthreads();
    int nw = blockDim.x >> 5;
    float r = (tid < nw) ? sh[tid] : 0.f;
    if (tid < 32) {
        #pragma unroll
        for (int o = 16; o; o >>= 1) r += __shfl_xor_sync(0xffffffffu, r, o);
        if (tid == 0) sh[32] = r;
    }
    __syncthreads();
    float total = sh[32];
    __syncthreads();
    return total;
}

__device__ __forceinline__ unsigned cvt_tf32(float x) {
    unsigned r;
    asm("cvt.rna.tf32.f32 %0, %1;" : "=r"(r) : "f"(x));
    return r;
}
__device__ __forceinline__ float round_tf32f(float x) {
    return __uint_as_float(cvt_tf32(x));
}

__device__ __forceinline__ void mma_tf32(float* c, const unsigned* a, const unsigned* b) {
    asm volatile(
        "mma.sync.aligned.m16n8k8.row.col.f32.tf32.tf32.f32 "
        "{%0,%1,%2,%3}, {%4,%5,%6,%7}, {%8,%9}, {%0,%1,%2,%3};\n"
        : "+f"(c[0]), "+f"(c[1]), "+f"(c[2]), "+f"(c[3])
        : "r"(a[0]), "r"(a[1]), "r"(a[2]), "r"(a[3]), "r"(b[0]), "r"(b[1]));
}

__device__ __forceinline__ void ldsm_x4(unsigned addr, unsigned& r0, unsigned& r1,
                                        unsigned& r2, unsigned& r3) {
    asm volatile("ldmatrix.sync.aligned.m8n8.x4.shared.b16 {%0,%1,%2,%3}, [%4];"
                 : "=r"(r0), "=r"(r1), "=r"(r2), "=r"(r3) : "r"(addr));
}

__device__ __forceinline__ void cp16(void* dst_smem, const float* src, bool pred) {
    unsigned d = (unsigned)__cvta_generic_to_shared(dst_smem);
    int sz = pred ? 16 : 0;
    asm volatile("cp.async.cg.shared.global [%0], [%1], 16, %2;\n"
                 :: "r"(d), "l"(src), "r"(sz));
}

// =====================================================================
// TF32 tensor-core GEMM, operands PRE-ROUNDED to tf32 (no cvt in loop),
// fragments loaded via ldmatrix.x4 (value-transparent for 32-bit data).
// MODE 0: plain  C = act(A @ W^T + b)
// MODE 1: conv   A = virtual im2col of x (token shift per 1024-slice)
// MODE 2: 3xTF32 virtual K=3072: s0 Ahi*Whi, s1 Ahi*Wlo, s2 Alo*Whi
// BM=BN=128, BK=32, 256 threads, warp tile 64x32, cp.async dbl-buffer.
// =====================================================================
#define TFPAD 36

template<int MODE>
__global__ void __launch_bounds__(256) gemm_tf32(
    const float* __restrict__ A, const float* __restrict__ Alo,
    const float* __restrict__ W, const float* __restrict__ Wlo,
    const float* __restrict__ bias, float* __restrict__ C, float* __restrict__ C2,
    int K, int ldc, int coff, int act, int dil, int roundC)
{
    extern __shared__ float smem[];
    float* As = smem;
    float* Bs = smem + 2 * 128 * TFPAD;

    const int tid = threadIdx.x;
    const int lane = tid & 31;
    const int wid = tid >> 5;
    const int wm = wid >> 2;
    const int wn = wid & 3;
    const int g = lane >> 2;
    const int t = lane & 3;
    const int row0 = blockIdx.y * 128;
    const int col0 = blockIdx.x * 128;
    const int KT = K >> 5;

    // ldmatrix per-thread base addresses (byte offsets in shared space)
    const unsigned sA = (unsigned)__cvta_generic_to_shared(As);
    const unsigned sB = (unsigned)__cvta_generic_to_shared(Bs);
    // A tiles: tile=lane>>3 -> [rows g0..7 | +8 | k+4 cols | both]
    //   row_in_frag = lane&15 (tiles 0/1 rows, replicated for 2/3), khalf = lane>>4
    const unsigned aBase = sA + (((wm * 64 + (lane & 15)) * TFPAD + ((lane >> 4) & 1) * 4) << 2);
    // B tiles: [nt rows k0-3 | nt rows k4-7 | nt+1 rows k0-3 | nt+1 rows k4-7]
    const unsigned bBase = sB + (((wn * 32 + (lane & 7) + ((lane >> 4) & 1) * 8) * TFPAD
                                  + ((lane >> 3) & 1) * 4) << 2);
    const unsigned BUFO = 128 * TFPAD * 4;  // byte offset between buffers

    float acc[4][4][4];
    #pragma unroll
    for (int i = 0; i < 4; i++)
        #pragma unroll
        for (int j = 0; j < 4; j++)
            #pragma unroll
            for (int q = 0; q < 4; q++) acc[i][j][q] = 0.f;

    auto load_tile = [&](int kt, int buf) {
        int k0 = kt << 5;
        int ksl = 0, h0 = k0, shift = 0;
        if (MODE == 1 || MODE == 2) {
            ksl = k0 >> 10;
            h0 = k0 & (HDIM - 1);
            if (MODE == 1) shift = (ksl - 1) * dil;
        }
        float* Ad = As + buf * 128 * TFPAD;
        float* Bd = Bs + buf * 128 * TFPAD;
        #pragma unroll
        for (int i = 0; i < 4; i++) {
            int idx = tid + i * 256;
            int r = idx >> 3;
            int c4 = (idx & 7) << 2;
            const float* srcA;
            bool pred = true;
            if (MODE == 1) {
                int n = row0 + r;
                int s2 = (n & (SDIM - 1)) + shift;
                pred = ((unsigned)s2 < (unsigned)SDIM);
                srcA = pred ? (A + (size_t)(n + shift) * HDIM + h0 + c4) : A;
            } else if (MODE == 2) {
                const float* Ab = (ksl == 2) ? Alo : A;
                srcA = Ab + (size_t)(row0 + r) * HDIM + h0 + c4;
            } else {
                srcA = A + (size_t)(row0 + r) * K + k0 + c4;
            }
            cp16(Ad + r * TFPAD + c4, srcA, pred);
            const float* srcB;
            if (MODE == 1)
                srcB = W + ((size_t)ksl * HDIM + col0 + r) * HDIM + h0 + c4;
            else if (MODE == 2) {
                const float* Wb = (ksl == 1) ? Wlo : W;
                srcB = Wb + (size_t)(col0 + r) * HDIM + h0 + c4;
            } else
                srcB = W + (size_t)(col0 + r) * K + k0 + c4;
            cp16(Bd + r * TFPAD + c4, srcB, true);
        }
    };

    load_tile(0, 0);
    asm volatile("cp.async.commit_group;\n" ::);

    for (int kt = 0; kt < KT; kt++) {
        int buf = kt & 1;
        if (kt + 1 < KT) load_tile(kt + 1, buf ^ 1);
        asm volatile("cp.async.commit_group;\n" ::);
        asm volatile("cp.async.wait_group 1;\n" ::);
        __syncthreads();

        const unsigned aB = aBase + buf * BUFO;
        const unsigned bB = bBase + buf * BUFO;
        #pragma unroll
        for (int kk = 0; kk < 4; kk++) {
            unsigned af[4][4], bf[4][2];
            #pragma unroll
            for (int p = 0; p < 2; p++)
                ldsm_x4(bB + p * (16 * TFPAD * 4) + kk * 32,
                        bf[2 * p][0], bf[2 * p][1], bf[2 * p + 1][0], bf[2 * p + 1][1]);
            #pragma unroll
            for (int mt = 0; mt < 4; mt++)
                ldsm_x4(aB + mt * (16 * TFPAD * 4) + kk * 32,
                        af[mt][0], af[mt][1], af[mt][2], af[mt][3]);
            #pragma unroll
            for (int mt = 0; mt < 4; mt++)
                #pragma unroll
                for (int nt = 0; nt < 4; nt++)
                    mma_tf32(acc[mt][nt], af[mt], bf[nt]);
        }
        __syncthreads();
    }

    #pragma unroll
    for (int mt = 0; mt < 4; mt++) {
        int r0 = row0 + wm * 64 + mt * 16 + g;
        int r1 = r0 + 8;
        #pragma unroll
        for (int nt = 0; nt < 4; nt++) {
            int c = col0 + wn * 32 + nt * 8 + 2 * t;
            float b0v = bias ? bias[c] : 0.f;
            float b1v = bias ? bias[c + 1] : 0.f;
            float v[4] = {acc[mt][nt][0] + b0v, acc[mt][nt][1] + b1v,
                          acc[mt][nt][2] + b0v, acc[mt][nt][3] + b1v};
            if (act == 2) {
                #pragma unroll
                for (int q = 0; q < 4; q++)
                    v[q] = 0.5f * v[q] * (1.f + erff(v[q] * 0.70710678118654752f));
            } else if (act == 1) {
                #pragma unroll
                for (int q = 0; q < 4; q++) v[q] = fmaxf(v[q], 0.f);
            }
            float w0 = roundC ? round_tf32f(v[0]) : v[0];
            float w1v = roundC ? round_tf32f(v[1]) : v[1];
            float w2v = roundC ? round_tf32f(v[2]) : v[2];
            float w3v = roundC ? round_tf32f(v[3]) : v[3];
            *reinterpret_cast<float2*>(C + (size_t)r0 * ldc + coff + c) = make_float2(w0, w1v);
            *reinterpret_cast<float2*>(C + (size_t)r1 * ldc + coff + c) = make_float2(w2v, w3v);
            if (C2) {
                *reinterpret_cast<float2*>(C2 + (size_t)r0 * ldc + coff + c) =
                    make_float2(round_tf32f(v[0]), round_tf32f(v[1]));
                *reinterpret_cast<float2*>(C2 + (size_t)r1 * ldc + coff + c) =
                    make_float2(round_tf32f(v[2]), round_tf32f(v[3]));
            }
        }
    }
}

// ---------------- prep: rounding / hi-lo split / repack ----------------
__global__ void round_tf32_kernel(const float* __restrict__ src, float* __restrict__ dst, int n4) {
    int i = blockIdx.x * blockDim.x + threadIdx.x;
    if (i >= n4) return;
    float4 v = reinterpret_cast<const float4*>(src)[i];
    v.x = round_tf32f(v.x); v.y = round_tf32f(v.y);
    v.z = round_tf32f(v.z); v.w = round_tf32f(v.w);
    reinterpret_cast<float4*>(dst)[i] = v;
}

__global__ void split_tf32_kernel(const float* __restrict__ src, float* __restrict__ hi,
                                  float* __restrict__ lo, int n4) {
    int i = blockIdx.x * blockDim.x + threadIdx.x;
    if (i >= n4) return;
    float4 v = reinterpret_cast<const float4*>(src)[i];
    float4 h, l;
    h.x = round_tf32f(v.x); l.x = round_tf32f(v.x - h.x);
    h.y = round_tf32f(v.y); l.y = round_tf32f(v.y - h.y);
    h.z = round_tf32f(v.z); l.z = round_tf32f(v.z - h.z);
    h.w = round_tf32f(v.w); l.w = round_tf32f(v.w - h.w);
    reinterpret_cast<float4*>(hi)[i] = h;
    reinterpret_cast<float4*>(lo)[i] = l;
}

__global__ void repack_convw(const float* __restrict__ cw, float* __restrict__ out) {
    int idx = blockIdx.x * blockDim.x + threadIdx.x;
    const int total = NDIL * 3 * HDIM * HDIM;
    if (idx >= total) return;
    int hi = idx & (HDIM - 1);
    int t = idx >> 10;
    int ho = t & (HDIM - 1);
    int t2 = t >> 10;
    int k = t2 % 3;
    int d = t2 / 3;
    out[idx] = round_tf32f(cw[(((size_t)d * HDIM + ho) * HDIM + hi) * 3 + k]);
}

__global__ void zero_usage(float* usage) {
    int i = blockIdx.x * blockDim.x + threadIdx.x;
    if (i < PDIM) usage[i] = 0.f;
}

// ---------------- top-8 candidates (tf32 logits) + fp32 rescore + top-2 ----------------
__device__ __forceinline__ bool better(float va, int ia, float vb, int ib) {
    return (va > vb) || (va == vb && ia < ib);
}
__device__ __forceinline__ void ins2(float& v1, int& i1, float& v2, int& i2, float v, int i) {
    if (better(v, i, v1, i1)) { v2 = v1; i2 = i1; v1 = v; i1 = i; }
    else if (better(v, i, v2, i2)) { v2 = v; i2 = i; }
}

__global__ void __launch_bounds__(256) topk_rescore_kernel(
    const float* __restrict__ logits, const float* __restrict__ inter,
    const float* __restrict__ w2, const float* __restrict__ b2,
    const float* __restrict__ tpool, const float* __restrict__ temp_p,
    float* __restrict__ combined, float* __restrict__ usage)
{
    int gw = (blockIdx.x * blockDim.x + threadIdx.x) >> 5;
    int lane = threadIdx.x & 31;
    if (gw >= NTOK) return;
    float temp = fminf(fmaxf(*temp_p, 0.1f), 5.0f);
    float invt = 1.f / temp;

    const float* lrow = logits + (size_t)gw * PDIM;
    float tv[8]; int ti[8];
    #pragma unroll
    for (int k = 0; k < 8; k++) { tv[k] = -FLT_MAX; ti[k] = 0x3fffffff; }
    for (int j = lane; j < PDIM; j += 32) {
        float v = fminf(fmaxf(lrow[j] * invt, -10.f), 10.f);
        if (better(v, j, tv[7], ti[7])) {
            tv[7] = v; ti[7] = j;
            #pragma unroll
            for (int k = 7; k > 0; k--) {
                bool sw = better(tv[k], ti[k], tv[k - 1], ti[k - 1]);
                float av = sw ? tv[k] : tv[k - 1];
                float bv2 = sw ? tv[k - 1] : tv[k];
                int ai = sw ? ti[k] : ti[k - 1];
                int bi = sw ? ti[k - 1] : ti[k];
                tv[k - 1] = av; tv[k] = bv2; ti[k - 1] = ai; ti[k] = bi;
            }
        }
    }

    int cand[8];
    #pragma unroll
    for (int r = 0; r < 8; r++) {
        float bvv = tv[0]; int bii = ti[0];
        #pragma unroll
        for (int off = 16; off; off >>= 1) {
            float ov = __shfl_xor_sync(0xffffffffu, bvv, off);
            int oi = __shfl_xor_sync(0xffffffffu, bii, off);
            if (better(ov, oi, bvv, bii)) { bvv = ov; bii = oi; }
        }
        cand[r] = bii;
        if (ti[0] == bii) {
            #pragma unroll
            for (int k = 0; k < 7; k++) { tv[k] = tv[k + 1]; ti[k] = ti[k + 1]; }
            tv[7] = -FLT_MAX; ti[7] = 0x3fffffff;
        }
    }

    const float* irow = inter + (size_t)gw * INTER_DIM;
    float xv[32];
    #pragma unroll
    for (int q = 0; q < 32; q++) xv[q] = irow[lane + q * 32];

    float v1 = -FLT_MAX, v2 = -FLT_MAX;
    int i1 = 0x3fffffff, i2 = 0x3fffffff;
    #pragma unroll
    for (int r = 0; r < 8; r++) {
        const float* wrow = w2 + (size_t)cand[r] * INTER_DIM;
        float s = 0.f;
        #pragma unroll
        for (int q = 0; q < 32; q++) s = fmaf(xv[q], wrow[lane + q * 32], s);
        #pragma unroll
        for (int off = 16; off; off >>= 1) s += __shfl_xor_sync(0xffffffffu, s, off);
        float v = fminf(fmaxf((s + b2[cand[r]]) * invt, -10.f), 10.f);
        ins2(v1, i1, v2, i2, v, cand[r]);
    }

    float e = expf(v2 - v1);
    float w1 = 1.f / (1.f + e);
    float w2s = e / (1.f + e);
    if (lane == 0) {
        atomicAdd(&usage[i1], w1);
        atomicAdd(&usage[i2], w2s);
    }
    const float* p1 = tpool + (size_t)i1 * DDIM;
    const float* p2 = tpool + (size_t)i2 * DDIM;
    float* dst = combined + (size_t)gw * (2 * DDIM) + DDIM;
    for (int d = lane; d < DDIM; d += 32)
        dst[d] = round_tf32f(w1 * p1[d] + w2s * p2[d]);
}

// ---------------- layernorm over D=512, writes rounded combined[:, :512] ----------------
__global__ void ln_kernel(const float* __restrict__ proj, const float* __restrict__ g,
                          const float* __restrict__ b, float* __restrict__ combined)
{
    __shared__ float sh[33];
    int n = blockIdx.x;
    const float* row = proj + (size_t)n * DDIM;
    float v[4];
    float s = 0.f;
    #pragma unroll
    for (int j = 0; j < 4; j++) { v[j] = row[threadIdx.x + j * 128]; s += v[j]; }
    float mean = block_reduce_sum(s, sh) * (1.f / DDIM);
    float q = 0.f;
    #pragma unroll
    for (int j = 0; j < 4; j++) { float d = v[j] - mean; q += d * d; }
    float var = block_reduce_sum(q, sh) * (1.f / DDIM);
    float rstd = rsqrtf(var + 1e-5f);
    float* dst = combined + (size_t)n * (2 * DDIM);
    #pragma unroll
    for (int j = 0; j < 4; j++) {
        int idx = threadIdx.x + j * 128;
        dst[idx] = round_tf32f((v[j] - mean) * rstd * g[idx] + b[idx]);
    }
}

// ---------------- gate + final mix ----------------
__global__ void gate_combine(const float* __restrict__ x, const float* __restrict__ wg,
                             const float* __restrict__ bg, const float* __restrict__ local,
                             const float* __restrict__ glob, float* __restrict__ out)
{
    __shared__ float sh[33];
    int n = blockIdx.x;
    const float* xr = x + (size_t)n * HDIM;
    float s = 0.f;
    for (int j = threadIdx.x; j < HDIM; j += 128) s += xr[j] * wg[j];
    float dot = block_reduce_sum(s, sh);
    float g = 1.f / (1.f + expf(-(dot + bg[0])));
    const float* lr = local + (size_t)n * HDIM;
    const float* gr = glob + (size_t)n * HDIM;
    float* orow = out + (size_t)n * HDIM;
    for (int j = threadIdx.x; j < HDIM; j += 128)
        orow[j] = g * lr[j] + (1.f - g) * gr[j];
}

// ---------------- diversity loss ----------------
__global__ void divloss_kernel(const float* __restrict__ usage, float* __restrict__ out) {
    __shared__ float sh[33];
    float s = 0.f;
    for (int j = threadIdx.x; j < PDIM; j += 1024) s += usage[j];
    float total = block_reduce_sum(s, sh);
    float inv = 1.f / (total + 1e-8f);
    float q = 0.f;
    const float ip = 1.f / (float)PDIM;
    for (int j = threadIdx.x; j < PDIM; j += 1024) {
        float f = usage[j] * inv - ip;
        q += f * f;
    }
    float qt = block_reduce_sum(q, sh);
    if (threadIdx.x == 0) out[0] = (qt / (float)PDIM) * 0.01f;
}

// ---------------- host launcher ----------------
extern "C" void kernel_launch(void* const* d_in, const int* in_sizes, int n_in,
                              void* d_out, int out_size)
{
    const float* x      = (const float*)d_in[0];
    const float* tpool  = (const float*)d_in[1];
    const float* w1     = (const float*)d_in[2];
    const float* b1     = (const float*)d_in[3];
    const float* w2     = (const float*)d_in[4];
    const float* b2     = (const float*)d_in[5];
    const float* temp   = (const float*)d_in[6];
    const float* wproj  = (const float*)d_in[7];
    const float* bproj  = (const float*)d_in[8];
    const float* ln_g   = (const float*)d_in[9];
    const float* ln_b   = (const float*)d_in[10];
    const float* wmap   = (const float*)d_in[11];
    const float* bmap   = (const float*)d_in[12];
    const float* conv_w = (const float*)d_in[13];
    const float* conv_b = (const float*)d_in[14];
    const float* wout   = (const float*)d_in[15];
    const float* bout   = (const float*)d_in[16];
    const float* wrp    = (const float*)d_in[17];
    const float* brp    = (const float*)d_in[18];
    const float* wg     = (const float*)d_in[19];
    const float* bg     = (const float*)d_in[20];
    float* out = (float*)d_out;

    float *inter, *intert, *logits, *concat, *local, *combined, *transf, *glob, *proj;
    float *convwt, *usage, *xt, *xlo, *w1hi, *w1lo, *w2t, *wprojt, *woutt, *wmapt, *wrpt;
    cudaGetSymbolAddress((void**)&inter,    g_inter);
    cudaGetSymbolAddress((void**)&intert,   g_intert);
    cudaGetSymbolAddress((void**)&logits,   g_logits);
    cudaGetSymbolAddress((void**)&concat,   g_concat);
    cudaGetSymbolAddress((void**)&local,    g_local);
    cudaGetSymbolAddress((void**)&combined, g_combined);
    cudaGetSymbolAddress((void**)&transf,   g_transf);
    cudaGetSymbolAddress((void**)&glob,     g_global);
    cudaGetSymbolAddress((void**)&proj,     g_proj);
    cudaGetSymbolAddress((void**)&convwt,   g_convwt);
    cudaGetSymbolAddress((void**)&usage,    g_usage);
    cudaGetSymbolAddress((void**)&xt,       g_xt);
    cudaGetSymbolAddress((void**)&xlo,      g_xlo);
    cudaGetSymbolAddress((void**)&w1hi,     g_w1hi);
    cudaGetSymbolAddress((void**)&w1lo,     g_w1lo);
    cudaGetSymbolAddress((void**)&w2t,      g_w2t);
    cudaGetSymbolAddress((void**)&wprojt,   g_wprojt);
    cudaGetSymbolAddress((void**)&woutt,    g_woutt);
    cudaGetSymbolAddress((void**)&wmapt,    g_wmapt);
    cudaGetSymbolAddress((void**)&wrpt,     g_wrpt);

    const int TF_SMEM = 4 * 128 * TFPAD * sizeof(float);  // 73728 B
    cudaFuncSetAttribute(gemm_tf32<0>, cudaFuncAttributeMaxDynamicSharedMemorySize, TF_SMEM);
    cudaFuncSetAttribute(gemm_tf32<1>, cudaFuncAttributeMaxDynamicSharedMemorySize, TF_SMEM);
    cudaFuncSetAttribute(gemm_tf32<2>, cudaFuncAttributeMaxDynamicSharedMemorySize, TF_SMEM);

    // ---- prep: repack+round conv weights, round/split operands ----
    const int total_cw = NDIL * 3 * HDIM * HDIM;
    repack_convw<<<(total_cw + 255) / 256, 256>>>(conv_w, convwt);
    zero_usage<<<(PDIM + 255) / 256, 256>>>(usage);
    split_tf32_kernel<<<(NTOK * HDIM / 4 + 255) / 256, 256>>>(x, xt, xlo, NTOK * HDIM / 4);
    split_tf32_kernel<<<(INTER_DIM * HDIM / 4 + 255) / 256, 256>>>(w1, w1hi, w1lo, INTER_DIM * HDIM / 4);
    round_tf32_kernel<<<((int)((size_t)PDIM * INTER_DIM / 4) + 255) / 256, 256>>>(w2, w2t, PDIM * INTER_DIM / 4);
    round_tf32_kernel<<<(DDIM * HDIM / 4 + 255) / 256, 256>>>(wproj, wprojt, DDIM * HDIM / 4);
    round_tf32_kernel<<<(HDIM * 3 * HDIM / 4 + 255) / 256, 256>>>(wout, woutt, HDIM * 3 * HDIM / 4);
    round_tf32_kernel<<<(DDIM * 2 * DDIM / 4 + 255) / 256, 256>>>(wmap, wmapt, DDIM * 2 * DDIM / 4);
    round_tf32_kernel<<<(HDIM * DDIM / 4 + 255) / 256, 256>>>(wrp, wrpt, HDIM * DDIM / 4);

    // ---- router inter: 3xTF32 split (near-fp32 exact), relu; dual write ----
    gemm_tf32<2><<<dim3(INTER_DIM / 128, NTOK / 128), 256, TF_SMEM>>>(
        xt, xlo, w1hi, w1lo, b1, inter, intert, 3 * HDIM, INTER_DIM, 0, 1, 0, 0);

    // ---- logits: single tf32 (candidates only) ----
    gemm_tf32<0><<<dim3(PDIM / 128, NTOK / 128), 256, TF_SMEM>>>(
        intert, nullptr, w2t, nullptr, b2, logits, nullptr, INTER_DIM, PDIM, 0, 0, 0, 0);

    topk_rescore_kernel<<<(NTOK * 32 + 255) / 256, 256>>>(
        logits, inter, w2, b2, tpool, temp, combined, usage);

    // ---- projected_x -> LN -> combined[:, :512] ----
    gemm_tf32<0><<<dim3(DDIM / 128, NTOK / 128), 256, TF_SMEM>>>(
        xt, nullptr, wprojt, nullptr, bproj, proj, nullptr, HDIM, DDIM, 0, 0, 0, 0);
    ln_kernel<<<NTOK, 128>>>(proj, ln_g, ln_b, combined);

    // ---- dilated convs (virtual im2col, GELU, rounded out) ----
    const int dils[NDIL] = {1, 2, 4};
    for (int i = 0; i < NDIL; i++)
        gemm_tf32<1><<<dim3(HDIM / 128, NTOK / 128), 256, TF_SMEM>>>(
            xt, nullptr, convwt + (size_t)i * 3 * HDIM * HDIM, nullptr, conv_b + i * HDIM,
            concat, nullptr, 3 * HDIM, 3 * HDIM, i * HDIM, 2, dils[i], 1);

    // ---- local out ----
    gemm_tf32<0><<<dim3(HDIM / 128, NTOK / 128), 256, TF_SMEM>>>(
        concat, nullptr, woutt, nullptr, bout, local, nullptr, 3 * HDIM, HDIM, 0, 0, 0, 0);

    // ---- transformation (rounded out) + global out ----
    gemm_tf32<0><<<dim3(DDIM / 128, NTOK / 128), 256, TF_SMEM>>>(
        combined, nullptr, wmapt, nullptr, bmap, transf, nullptr, 2 * DDIM, DDIM, 0, 0, 0, 1);
    gemm_tf32<0><<<dim3(HDIM / 128, NTOK / 128), 256, TF_SMEM>>>(
        transf, nullptr, wrpt, nullptr, brp, glob, nullptr, DDIM, HDIM, 0, 0, 0, 0);

    // gate + mix -> out
    gate_combine<<<NTOK, 128>>>(x, wg, bg, local, glob, out);

    // diversity loss -> last output element
    if (out_size > NTOK * HDIM)
        divloss_kernel<<<1, 1024>>>(usage, out + (size_t)NTOK * HDIM);
}

// round 8
// speedup vs baseline: 3.1736x; 1.0024x over previous
#include <cuda_runtime.h>
#include <cuda_bf16.h>
#include <cstdint>
#include <float.h>

// ---------------- problem constants ----------------
#define BDIM 4
#define SDIM 4096
#define HDIM 1024
#define PDIM 4096
#define DDIM 512
#define NTOK (BDIM * SDIM)          // 16384
#define INTER_DIM 1024
#define NDIL 3

// ---------------- scratch (device globals; no allocs allowed) ----------------
__device__ float g_inter[NTOK * INTER_DIM];         // near-exact fp32 (rescore)
__device__ float g_logits[(size_t)NTOK * PDIM];     // bf16-accurate screen
__device__ float g_concat[(size_t)NTOK * 3 * HDIM]; // tf32-rounded GELU out
__device__ float g_local[NTOK * HDIM];
__device__ float g_combined[NTOK * 2 * DDIM];       // tf32-rounded
__device__ float g_transf[NTOK * DDIM];             // tf32-rounded
__device__ float g_global[NTOK * HDIM];
__device__ float g_proj[NTOK * DDIM];
__device__ float g_convwt[NDIL * 3 * HDIM * HDIM];  // repacked + tf32-rounded
__device__ float g_usage[PDIM];
// pre-rounded tf32 operands (continuous paths)
__device__ float g_xt[NTOK * HDIM];                 // tf32(x)
__device__ float g_wprojt[DDIM * HDIM];
__device__ float g_woutt[HDIM * 3 * HDIM];
__device__ float g_wmapt[DDIM * 2 * DDIM];
__device__ float g_wrpt[HDIM * DDIM];
// bf16 router operands
__device__ __nv_bfloat16 g_xhb[NTOK * HDIM];        // hi(x) bf16
__device__ __nv_bfloat16 g_xlb[NTOK * HDIM];        // lo(x) bf16
__device__ __nv_bfloat16 g_w1hb[INTER_DIM * HDIM];
__device__ __nv_bfloat16 g_w1lb[INTER_DIM * HDIM];
__device__ __nv_bfloat16 g_w2b[(size_t)PDIM * INTER_DIM];
__device__ __nv_bfloat16 g_interb[NTOK * INTER_DIM];// bf16(inter) (logits A)

// ---------------- helpers ----------------
__device__ __forceinline__ float block_reduce_sum(float v, float* sh) {
    int tid = threadIdx.x;
    #pragma unroll
    for (int o = 16; o; o >>= 1) v += __shfl_xor_sync(0xffffffffu, v, o);
    if ((tid & 31) == 0) sh[tid >> 5] = v;
    __syncthreads();
    int nw = blockDim.x >> 5;
    float r = (tid < nw) ? sh[tid] : 0.f;
    if (tid < 32) {
        #pragma unroll
        for (int o = 16; o; o >>= 1) r += __shfl_xor_sync(0xffffffffu, r, o);
        if (tid == 0) sh[32] = r;
    }
    __syncthreads();
    float total = sh[32];
    __syncthreads();
    return total;
}

__device__ __forceinline__ unsigned cvt_tf32(float x) {
    unsigned r;
    asm("cvt.rna.tf32.f32 %0, %1;" : "=r"(r) : "f"(x));
    return r;
}
__device__ __forceinline__ float round_tf32f(float x) {
    return __uint_as_float(cvt_tf32(x));
}

__device__ __forceinline__ void mma_tf32(float* c, const unsigned* a, const unsigned* b) {
    asm volatile(
        "mma.sync.aligned.m16n8k8.row.col.f32.tf32.tf32.f32 "
        "{%0,%1,%2,%3}, {%4,%5,%6,%7}, {%8,%9}, {%0,%1,%2,%3};\n"
        : "+f"(c[0]), "+f"(c[1]), "+f"(c[2]), "+f"(c[3])
        : "r"(a[0]), "r"(a[1]), "r"(a[2]), "r"(a[3]), "r"(b[0]), "r"(b[1]));
}

__device__ __forceinline__ void mma_bf16(float* c, const unsigned* a, const unsigned* b) {
    asm volatile(
        "mma.sync.aligned.m16n8k16.row.col.f32.bf16.bf16.f32 "
        "{%0,%1,%2,%3}, {%4,%5,%6,%7}, {%8,%9}, {%0,%1,%2,%3};\n"
        : "+f"(c[0]), "+f"(c[1]), "+f"(c[2]), "+f"(c[3])
        : "r"(a[0]), "r"(a[1]), "r"(a[2]), "r"(a[3]), "r"(b[0]), "r"(b[1]));
}

__device__ __forceinline__ void ldsm_x4(unsigned addr, unsigned& r0, unsigned& r1,
                                        unsigned& r2, unsigned& r3) {
    asm volatile("ldmatrix.sync.aligned.m8n8.x4.shared.b16 {%0,%1,%2,%3}, [%4];"
                 : "=r"(r0), "=r"(r1), "=r"(r2), "=r"(r3) : "r"(addr));
}

__device__ __forceinline__ void cp16(void* dst_smem, const void* src, bool pred) {
    unsigned d = (unsigned)__cvta_generic_to_shared(dst_smem);
    int sz = pred ? 16 : 0;
    asm volatile("cp.async.cg.shared.global [%0], [%1], 16, %2;\n"
                 :: "r"(d), "l"(src), "r"(sz));
}

// =====================================================================
// TF32 tensor-core GEMM (operands pre-rounded, ldmatrix fragments).
// MODE 0: plain  C = act(A @ W^T + b)
// MODE 1: conv   A = virtual im2col of x (token shift per 1024-slice)
// BM=BN=128, BK=32, 256 threads, warp tile 64x32, cp.async dbl-buffer.
// =====================================================================
#define TFPAD 36

template<int MODE>
__global__ void __launch_bounds__(256) gemm_tf32(
    const float* __restrict__ A, const float* __restrict__ W,
    const float* __restrict__ bias, float* __restrict__ C,
    int K, int ldc, int coff, int act, int dil, int roundC)
{
    extern __shared__ float smem[];
    float* As = smem;
    float* Bs = smem + 2 * 128 * TFPAD;

    const int tid = threadIdx.x;
    const int lane = tid & 31;
    const int wid = tid >> 5;
    const int wm = wid >> 2;
    const int wn = wid & 3;
    const int g = lane >> 2;
    const int t = lane & 3;
    const int row0 = blockIdx.y * 128;
    const int col0 = blockIdx.x * 128;
    const int KT = K >> 5;

    const unsigned sA = (unsigned)__cvta_generic_to_shared(As);
    const unsigned sB = (unsigned)__cvta_generic_to_shared(Bs);
    const unsigned aBase = sA + (((wm * 64 + (lane & 15)) * TFPAD + ((lane >> 4) & 1) * 4) << 2);
    const unsigned bBase = sB + (((wn * 32 + (lane & 7) + ((lane >> 4) & 1) * 8) * TFPAD
                                  + ((lane >> 3) & 1) * 4) << 2);
    const unsigned BUFO = 128 * TFPAD * 4;

    float acc[4][4][4];
    #pragma unroll
    for (int i = 0; i < 4; i++)
        #pragma unroll
        for (int j = 0; j < 4; j++)
            #pragma unroll
            for (int q = 0; q < 4; q++) acc[i][j][q] = 0.f;

    auto load_tile = [&](int kt, int buf) {
        int k0 = kt << 5;
        int ksl = 0, h0 = k0, shift = 0;
        if (MODE == 1) {
            ksl = k0 >> 10;
            h0 = k0 & (HDIM - 1);
            shift = (ksl - 1) * dil;
        }
        float* Ad = As + buf * 128 * TFPAD;
        float* Bd = Bs + buf * 128 * TFPAD;
        #pragma unroll
        for (int i = 0; i < 4; i++) {
            int idx = tid + i * 256;
            int r = idx >> 3;
            int c4 = (idx & 7) << 2;
            const float* srcA;
            bool pred = true;
            if (MODE == 1) {
                int n = row0 + r;
                int s2 = (n & (SDIM - 1)) + shift;
                pred = ((unsigned)s2 < (unsigned)SDIM);
                srcA = pred ? (A + (size_t)(n + shift) * HDIM + h0 + c4) : A;
            } else {
                srcA = A + (size_t)(row0 + r) * K + k0 + c4;
            }
            cp16(Ad + r * TFPAD + c4, srcA, pred);
            const float* srcB;
            if (MODE == 1)
                srcB = W + ((size_t)ksl * HDIM + col0 + r) * HDIM + h0 + c4;
            else
                srcB = W + (size_t)(col0 + r) * K + k0 + c4;
            cp16(Bd + r * TFPAD + c4, srcB, true);
        }
    };

    load_tile(0, 0);
    asm volatile("cp.async.commit_group;\n" ::);

    for (int kt = 0; kt < KT; kt++) {
        int buf = kt & 1;
        if (kt + 1 < KT) load_tile(kt + 1, buf ^ 1);
        asm volatile("cp.async.commit_group;\n" ::);
        asm volatile("cp.async.wait_group 1;\n" ::);
        __syncthreads();

        const unsigned aB = aBase + buf * BUFO;
        const unsigned bB = bBase + buf * BUFO;
        #pragma unroll
        for (int kk = 0; kk < 4; kk++) {
            unsigned af[4][4], bf[4][2];
            #pragma unroll
            for (int p = 0; p < 2; p++)
                ldsm_x4(bB + p * (16 * TFPAD * 4) + kk * 32,
                        bf[2 * p][0], bf[2 * p][1], bf[2 * p + 1][0], bf[2 * p + 1][1]);
            #pragma unroll
            for (int mt = 0; mt < 4; mt++)
                ldsm_x4(aB + mt * (16 * TFPAD * 4) + kk * 32,
                        af[mt][0], af[mt][1], af[mt][2], af[mt][3]);
            #pragma unroll
            for (int mt = 0; mt < 4; mt++)
                #pragma unroll
                for (int nt = 0; nt < 4; nt++)
                    mma_tf32(acc[mt][nt], af[mt], bf[nt]);
        }
        __syncthreads();
    }

    #pragma unroll
    for (int mt = 0; mt < 4; mt++) {
        int r0 = row0 + wm * 64 + mt * 16 + g;
        int r1 = r0 + 8;
        #pragma unroll
        for (int nt = 0; nt < 4; nt++) {
            int c = col0 + wn * 32 + nt * 8 + 2 * t;
            float b0v = bias ? bias[c] : 0.f;
            float b1v = bias ? bias[c + 1] : 0.f;
            float v[4] = {acc[mt][nt][0] + b0v, acc[mt][nt][1] + b1v,
                          acc[mt][nt][2] + b0v, acc[mt][nt][3] + b1v};
            if (act == 2) {
                #pragma unroll
                for (int q = 0; q < 4; q++)
                    v[q] = 0.5f * v[q] * (1.f + erff(v[q] * 0.70710678118654752f));
            } else if (act == 1) {
                #pragma unroll
                for (int q = 0; q < 4; q++) v[q] = fmaxf(v[q], 0.f);
            }
            if (roundC) {
                #pragma unroll
                for (int q = 0; q < 4; q++) v[q] = round_tf32f(v[q]);
            }
            *reinterpret_cast<float2*>(C + (size_t)r0 * ldc + coff + c) = make_float2(v[0], v[1]);
            *reinterpret_cast<float2*>(C + (size_t)r1 * ldc + coff + c) = make_float2(v[2], v[3]);
        }
    }
}

// =====================================================================
// BF16 tensor-core GEMM (router only): C = act(A @ W^T + b)
// MODE 0: plain (A, W bf16)
// MODE 2: 3xBF16 virtual K=3072: s0 Ahi*Whi, s1 Ahi*Wlo, s2 Alo*Whi
// BM=BN=128, BK=32 halves, mma m16n8k16, warp tile 64x32.
// C fp32; C2 (optional) bf16 copy of C.
// =====================================================================
#define HPAD 40   // halves per smem row (80 B), 16B-aligned, conflict-free ldsm

template<int MODE>
__global__ void __launch_bounds__(256) gemm_bf16k(
    const __nv_bfloat16* __restrict__ A, const __nv_bfloat16* __restrict__ Alo,
    const __nv_bfloat16* __restrict__ W, const __nv_bfloat16* __restrict__ Wlo,
    const float* __restrict__ bias, float* __restrict__ C, __nv_bfloat16* __restrict__ C2,
    int K, int ldc, int act)
{
    extern __shared__ __nv_bfloat16 hsm[];
    __nv_bfloat16* As = hsm;                   // [2][128][HPAD]
    __nv_bfloat16* Bs = hsm + 2 * 128 * HPAD;

    const int tid = threadIdx.x;
    const int lane = tid & 31;
    const int wid = tid >> 5;
    const int wm = wid >> 2;
    const int wn = wid & 3;
    const int g = lane >> 2;
    const int t = lane & 3;
    const int row0 = blockIdx.y * 128;
    const int col0 = blockIdx.x * 128;
    const int KT = K >> 5;          // 32 halves per chunk

    const unsigned sA = (unsigned)__cvta_generic_to_shared(As);
    const unsigned sB = (unsigned)__cvta_generic_to_shared(Bs);
    // A m16k16 tile: lanes 0-15 rows (k0 16B), lanes 16-31 same rows +16B (k8-15)
    const unsigned aBase = sA + (wm * 64 + (lane & 15)) * (HPAD * 2) + ((lane >> 4) & 1) * 16;
    // B x4 = two n8 frags: lanes 0-7 n0-7@k0, 8-15 n0-7@k8, 16-23 n8-15@k0, 24-31 n8-15@k8
    const unsigned bBase = sB + (wn * 32 + (lane & 7) + ((lane >> 4) & 1) * 8) * (HPAD * 2)
                              + ((lane >> 3) & 1) * 16;
    const unsigned BUFO = 128 * HPAD * 2;

    float acc[4][4][4];
    #pragma unroll
    for (int i = 0; i < 4; i++)
        #pragma unroll
        for (int j = 0; j < 4; j++)
            #pragma unroll
            for (int q = 0; q < 4; q++) acc[i][j][q] = 0.f;

    auto load_tile = [&](int kt, int buf) {
        int k0 = kt << 5;
        int ksl = 0, h0 = k0;
        if (MODE == 2) { ksl = k0 >> 10; h0 = k0 & (HDIM - 1); }
        __nv_bfloat16* Ad = As + buf * 128 * HPAD;
        __nv_bfloat16* Bd = Bs + buf * 128 * HPAD;
        // 128 rows x 32 halves = 512 x 8-half chunks each for A and B; 2/thread each
        #pragma unroll
        for (int i = 0; i < 2; i++) {
            int idx = tid + i * 256;
            int r = idx >> 2;
            int c8 = (idx & 3) << 3;
            const __nv_bfloat16* srcA;
            if (MODE == 2) {
                const __nv_bfloat16* Ab = (ksl == 2) ? Alo : A;
                srcA = Ab + (size_t)(row0 + r) * HDIM + h0 + c8;
            } else {
                srcA = A + (size_t)(row0 + r) * K + k0 + c8;
            }
            cp16(Ad + r * HPAD + c8, srcA, true);
            const __nv_bfloat16* srcB;
            if (MODE == 2) {
                const __nv_bfloat16* Wb = (ksl == 1) ? Wlo : W;
                srcB = Wb + (size_t)(col0 + r) * HDIM + h0 + c8;
            } else {
                srcB = W + (size_t)(col0 + r) * K + k0 + c8;
            }
            cp16(Bd + r * HPAD + c8, srcB, true);
        }
    };

    load_tile(0, 0);
    asm volatile("cp.async.commit_group;\n" ::);

    for (int kt = 0; kt < KT; kt++) {
        int buf = kt & 1;
        if (kt + 1 < KT) load_tile(kt + 1, buf ^ 1);
        asm volatile("cp.async.commit_group;\n" ::);
        asm volatile("cp.async.wait_group 1;\n" ::);
        __syncthreads();

        const unsigned aB = aBase + buf * BUFO;
        const unsigned bB = bBase + buf * BUFO;
        #pragma unroll
        for (int kk = 0; kk < 2; kk++) {      // two k16 slabs per 32-half chunk
            unsigned af[4][4], bf[4][2];
            #pragma unroll
            for (int p = 0; p < 2; p++)
                ldsm_x4(bB + p * (16 * HPAD * 2) + kk * 32,
                        bf[2 * p][0], bf[2 * p][1], bf[2 * p + 1][0], bf[2 * p + 1][1]);
            #pragma unroll
            for (int mt = 0; mt < 4; mt++)
                ldsm_x4(aB + mt * (16 * HPAD * 2) + kk * 32,
                        af[mt][0], af[mt][1], af[mt][2], af[mt][3]);
            #pragma unroll
            for (int mt = 0; mt < 4; mt++)
                #pragma unroll
                for (int nt = 0; nt < 4; nt++)
                    mma_bf16(acc[mt][nt], af[mt], bf[nt]);
        }
        __syncthreads();
    }

    #pragma unroll
    for (int mt = 0; mt < 4; mt++) {
        int r0 = row0 + wm * 64 + mt * 16 + g;
        int r1 = r0 + 8;
        #pragma unroll
        for (int nt = 0; nt < 4; nt++) {
            int c = col0 + wn * 32 + nt * 8 + 2 * t;
            float b0v = bias ? bias[c] : 0.f;
            float b1v = bias ? bias[c + 1] : 0.f;
            float v[4] = {acc[mt][nt][0] + b0v, acc[mt][nt][1] + b1v,
                          acc[mt][nt][2] + b0v, acc[mt][nt][3] + b1v};
            if (act == 1) {
                #pragma unroll
                for (int q = 0; q < 4; q++) v[q] = fmaxf(v[q], 0.f);
            }
            *reinterpret_cast<float2*>(C + (size_t)r0 * ldc + c) = make_float2(v[0], v[1]);
            *reinterpret_cast<float2*>(C + (size_t)r1 * ldc + c) = make_float2(v[2], v[3]);
            if (C2) {
                __nv_bfloat162 p0, p1;
                p0.x = __float2bfloat16_rn(v[0]); p0.y = __float2bfloat16_rn(v[1]);
                p1.x = __float2bfloat16_rn(v[2]); p1.y = __float2bfloat16_rn(v[3]);
                *reinterpret_cast<__nv_bfloat162*>(C2 + (size_t)r0 * ldc + c) = p0;
                *reinterpret_cast<__nv_bfloat162*>(C2 + (size_t)r1 * ldc + c) = p1;
            }
        }
    }
}

// ---------------- prep: rounding / splits / repack ----------------
__global__ void round_tf32_kernel(const float* __restrict__ src, float* __restrict__ dst, int n4) {
    int i = blockIdx.x * blockDim.x + threadIdx.x;
    if (i >= n4) return;
    float4 v = reinterpret_cast<const float4*>(src)[i];
    v.x = round_tf32f(v.x); v.y = round_tf32f(v.y);
    v.z = round_tf32f(v.z); v.w = round_tf32f(v.w);
    reinterpret_cast<float4*>(dst)[i] = v;
}

__global__ void split_bf16_kernel(const float* __restrict__ src, __nv_bfloat16* __restrict__ hi,
                                  __nv_bfloat16* __restrict__ lo, int n) {
    int i = blockIdx.x * blockDim.x + threadIdx.x;
    if (i >= n) return;
    float v = src[i];
    __nv_bfloat16 h = __float2bfloat16_rn(v);
    hi[i] = h;
    lo[i] = __float2bfloat16_rn(v - __bfloat162float(h));
}

__global__ void round_bf16_kernel(const float* __restrict__ src, __nv_bfloat16* __restrict__ dst, int n) {
    int i = blockIdx.x * blockDim.x + threadIdx.x;
    if (i >= n) return;
    dst[i] = __float2bfloat16_rn(src[i]);
}

__global__ void repack_convw(const float* __restrict__ cw, float* __restrict__ out) {
    int idx = blockIdx.x * blockDim.x + threadIdx.x;
    const int total = NDIL * 3 * HDIM * HDIM;
    if (idx >= total) return;
    int hi = idx & (HDIM - 1);
    int t = idx >> 10;
    int ho = t & (HDIM - 1);
    int t2 = t >> 10;
    int k = t2 % 3;
    int d = t2 / 3;
    out[idx] = round_tf32f(cw[(((size_t)d * HDIM + ho) * HDIM + hi) * 3 + k]);
}

__global__ void zero_usage(float* usage) {
    int i = blockIdx.x * blockDim.x + threadIdx.x;
    if (i < PDIM) usage[i] = 0.f;
}

// ---------------- top-8 candidates (bf16-accurate logits) + fp32 rescore + top-2 ----------------
__device__ __forceinline__ bool better(float va, int ia, float vb, int ib) {
    return (va > vb) || (va == vb && ia < ib);
}
__device__ __forceinline__ void ins2(float& v1, int& i1, float& v2, int& i2, float v, int i) {
    if (better(v, i, v1, i1)) { v2 = v1; i2 = i1; v1 = v; i1 = i; }
    else if (better(v, i, v2, i2)) { v2 = v; i2 = i; }
}

__global__ void __launch_bounds__(256) topk_rescore_kernel(
    const float* __restrict__ logits, const float* __restrict__ inter,
    const float* __restrict__ w2, const float* __restrict__ b2,
    const float* __restrict__ tpool, const float* __restrict__ temp_p,
    float* __restrict__ combined, float* __restrict__ usage)
{
    int gw = (blockIdx.x * blockDim.x + threadIdx.x) >> 5;
    int lane = threadIdx.x & 31;
    if (gw >= NTOK) return;
    float temp = fminf(fmaxf(*temp_p, 0.1f), 5.0f);
    float invt = 1.f / temp;

    const float* lrow = logits + (size_t)gw * PDIM;
    float tv[8]; int ti[8];
    #pragma unroll
    for (int k = 0; k < 8; k++) { tv[k] = -FLT_MAX; ti[k] = 0x3fffffff; }
    for (int j = lane; j < PDIM; j += 32) {
        float v = fminf(fmaxf(lrow[j] * invt, -10.f), 10.f);
        if (better(v, j, tv[7], ti[7])) {
            tv[7] = v; ti[7] = j;
            #pragma unroll
            for (int k = 7; k > 0; k--) {
                bool sw = better(tv[k], ti[k], tv[k - 1], ti[k - 1]);
                float av = sw ? tv[k] : tv[k - 1];
                float bv2 = sw ? tv[k - 1] : tv[k];
                int ai = sw ? ti[k] : ti[k - 1];
                int bi = sw ? ti[k - 1] : ti[k];
                tv[k - 1] = av; tv[k] = bv2; ti[k - 1] = ai; ti[k] = bi;
            }
        }
    }

    int cand[8];
    #pragma unroll
    for (int r = 0; r < 8; r++) {
        float bvv = tv[0]; int bii = ti[0];
        #pragma unroll
        for (int off = 16; off; off >>= 1) {
            float ov = __shfl_xor_sync(0xffffffffu, bvv, off);
            int oi = __shfl_xor_sync(0xffffffffu, bii, off);
            if (better(ov, oi, bvv, bii)) { bvv = ov; bii = oi; }
        }
        cand[r] = bii;
        if (ti[0] == bii) {
            #pragma unroll
            for (int k = 0; k < 7; k++) { tv[k] = tv[k + 1]; ti[k] = ti[k + 1]; }
            tv[7] = -FLT_MAX; ti[7] = 0x3fffffff;
        }
    }

    const float* irow = inter + (size_t)gw * INTER_DIM;
    float xv[32];
    #pragma unroll
    for (int q = 0; q < 32; q++) xv[q] = irow[lane + q * 32];

    float v1 = -FLT_MAX, v2 = -FLT_MAX;
    int i1 = 0x3fffffff, i2 = 0x3fffffff;
    #pragma unroll
    for (int r = 0; r < 8; r++) {
        const float* wrow = w2 + (size_t)cand[r] * INTER_DIM;
        float s = 0.f;
        #pragma unroll
        for (int q = 0; q < 32; q++) s = fmaf(xv[q], wrow[lane + q * 32], s);
        #pragma unroll
        for (int off = 16; off; off >>= 1) s += __shfl_xor_sync(0xffffffffu, s, off);
        float v = fminf(fmaxf((s + b2[cand[r]]) * invt, -10.f), 10.f);
        ins2(v1, i1, v2, i2, v, cand[r]);
    }

    float e = expf(v2 - v1);
    float w1 = 1.f / (1.f + e);
    float w2s = e / (1.f + e);
    if (lane == 0) {
        atomicAdd(&usage[i1], w1);
        atomicAdd(&usage[i2], w2s);
    }
    const float* p1 = tpool + (size_t)i1 * DDIM;
    const float* p2 = tpool + (size_t)i2 * DDIM;
    float* dst = combined + (size_t)gw * (2 * DDIM) + DDIM;
    for (int d = lane; d < DDIM; d += 32)
        dst[d] = round_tf32f(w1 * p1[d] + w2s * p2[d]);
}

// ---------------- layernorm over D=512, writes rounded combined[:, :512] ----------------
__global__ void ln_kernel(const float* __restrict__ proj, const float* __restrict__ g,
                          const float* __restrict__ b, float* __restrict__ combined)
{
    __shared__ float sh[33];
    int n = blockIdx.x;
    const float* row = proj + (size_t)n * DDIM;
    float v[4];
    float s = 0.f;
    #pragma unroll
    for (int j = 0; j < 4; j++) { v[j] = row[threadIdx.x + j * 128]; s += v[j]; }
    float mean = block_reduce_sum(s, sh) * (1.f / DDIM);
    float q = 0.f;
    #pragma unroll
    for (int j = 0; j < 4; j++) { float d = v[j] - mean; q += d * d; }
    float var = block_reduce_sum(q, sh) * (1.f / DDIM);
    float rstd = rsqrtf(var + 1e-5f);
    float* dst = combined + (size_t)n * (2 * DDIM);
    #pragma unroll
    for (int j = 0; j < 4; j++) {
        int idx = threadIdx.x + j * 128;
        dst[idx] = round_tf32f((v[j] - mean) * rstd * g[idx] + b[idx]);
    }
}

// ---------------- gate + final mix ----------------
__global__ void gate_combine(const float* __restrict__ x, const float* __restrict__ wg,
                             const float* __restrict__ bg, const float* __restrict__ local,
                             const float* __restrict__ glob, float* __restrict__ out)
{
    __shared__ float sh[33];
    int n = blockIdx.x;
    const float* xr = x + (size_t)n * HDIM;
    float s = 0.f;
    for (int j = threadIdx.x; j < HDIM; j += 128) s += xr[j] * wg[j];
    float dot = block_reduce_sum(s, sh);
    float g = 1.f / (1.f + expf(-(dot + bg[0])));
    const float* lr = local + (size_t)n * HDIM;
    const float* gr = glob + (size_t)n * HDIM;
    float* orow = out + (size_t)n * HDIM;
    for (int j = threadIdx.x; j < HDIM; j += 128)
        orow[j] = g * lr[j] + (1.f - g) * gr[j];
}

// ---------------- diversity loss ----------------
__global__ void divloss_kernel(const float* __restrict__ usage, float* __restrict__ out) {
    __shared__ float sh[33];
    float s = 0.f;
    for (int j = threadIdx.x; j < PDIM; j += 1024) s += usage[j];
    float total = block_reduce_sum(s, sh);
    float inv = 1.f / (total + 1e-8f);
    float q = 0.f;
    const float ip = 1.f / (float)PDIM;
    for (int j = threadIdx.x; j < PDIM; j += 1024) {
        float f = usage[j] * inv - ip;
        q += f * f;
    }
    float qt = block_reduce_sum(q, sh);
    if (threadIdx.x == 0) out[0] = (qt / (float)PDIM) * 0.01f;
}

// ---------------- host launcher ----------------
extern "C" void kernel_launch(void* const* d_in, const int* in_sizes, int n_in,
                              void* d_out, int out_size)
{
    const float* x      = (const float*)d_in[0];
    const float* tpool  = (const float*)d_in[1];
    const float* w1     = (const float*)d_in[2];
    const float* b1     = (const float*)d_in[3];
    const float* w2     = (const float*)d_in[4];
    const float* b2     = (const float*)d_in[5];
    const float* temp   = (const float*)d_in[6];
    const float* wproj  = (const float*)d_in[7];
    const float* bproj  = (const float*)d_in[8];
    const float* ln_g   = (const float*)d_in[9];
    const float* ln_b   = (const float*)d_in[10];
    const float* wmap   = (const float*)d_in[11];
    const float* bmap   = (const float*)d_in[12];
    const float* conv_w = (const float*)d_in[13];
    const float* conv_b = (const float*)d_in[14];
    const float* wout   = (const float*)d_in[15];
    const float* bout   = (const float*)d_in[16];
    const float* wrp    = (const float*)d_in[17];
    const float* brp    = (const float*)d_in[18];
    const float* wg     = (const float*)d_in[19];
    const float* bg     = (const float*)d_in[20];
    float* out = (float*)d_out;

    float *inter, *logits, *concat, *local, *combined, *transf, *glob, *proj;
    float *convwt, *usage, *xt, *wprojt, *woutt, *wmapt, *wrpt;
    __nv_bfloat16 *xhb, *xlb, *w1hb, *w1lb, *w2b, *interb;
    cudaGetSymbolAddress((void**)&inter,    g_inter);
    cudaGetSymbolAddress((void**)&logits,   g_logits);
    cudaGetSymbolAddress((void**)&concat,   g_concat);
    cudaGetSymbolAddress((void**)&local,    g_local);
    cudaGetSymbolAddress((void**)&combined, g_combined);
    cudaGetSymbolAddress((void**)&transf,   g_transf);
    cudaGetSymbolAddress((void**)&glob,     g_global);
    cudaGetSymbolAddress((void**)&proj,     g_proj);
    cudaGetSymbolAddress((void**)&convwt,   g_convwt);
    cudaGetSymbolAddress((void**)&usage,    g_usage);
    cudaGetSymbolAddress((void**)&xt,       g_xt);
    cudaGetSymbolAddress((void**)&wprojt,   g_wprojt);
    cudaGetSymbolAddress((void**)&woutt,    g_woutt);
    cudaGetSymbolAddress((void**)&wmapt,    g_wmapt);
    cudaGetSymbolAddress((void**)&wrpt,     g_wrpt);
    cudaGetSymbolAddress((void**)&xhb,      g_xhb);
    cudaGetSymbolAddress((void**)&xlb,      g_xlb);
    cudaGetSymbolAddress((void**)&w1hb,     g_w1hb);
    cudaGetSymbolAddress((void**)&w1lb,     g_w1lb);
    cudaGetSymbolAddress((void**)&w2b,      g_w2b);
    cudaGetSymbolAddress((void**)&interb,   g_interb);

    const int TF_SMEM = 4 * 128 * TFPAD * sizeof(float);          // 73728 B
    const int BF_SMEM = 4 * 128 * HPAD * sizeof(__nv_bfloat16);   // 40960 B
    cudaFuncSetAttribute(gemm_tf32<0>, cudaFuncAttributeMaxDynamicSharedMemorySize, TF_SMEM);
    cudaFuncSetAttribute(gemm_tf32<1>, cudaFuncAttributeMaxDynamicSharedMemorySize, TF_SMEM);
    cudaFuncSetAttribute(gemm_bf16k<0>, cudaFuncAttributeMaxDynamicSharedMemorySize, BF_SMEM);
    cudaFuncSetAttribute(gemm_bf16k<2>, cudaFuncAttributeMaxDynamicSharedMemorySize, BF_SMEM);

    // ---- prep ----
    const int total_cw = NDIL * 3 * HDIM * HDIM;
    repack_convw<<<(total_cw + 255) / 256, 256>>>(conv_w, convwt);
    zero_usage<<<(PDIM + 255) / 256, 256>>>(usage);
    round_tf32_kernel<<<(NTOK * HDIM / 4 + 255) / 256, 256>>>(x, xt, NTOK * HDIM / 4);
    round_tf32_kernel<<<(DDIM * HDIM / 4 + 255) / 256, 256>>>(wproj, wprojt, DDIM * HDIM / 4);
    round_tf32_kernel<<<(HDIM * 3 * HDIM / 4 + 255) / 256, 256>>>(wout, woutt, HDIM * 3 * HDIM / 4);
    round_tf32_kernel<<<(DDIM * 2 * DDIM / 4 + 255) / 256, 256>>>(wmap, wmapt, DDIM * 2 * DDIM / 4);
    round_tf32_kernel<<<(HDIM * DDIM / 4 + 255) / 256, 256>>>(wrp, wrpt, HDIM * DDIM / 4);
    split_bf16_kernel<<<(NTOK * HDIM + 255) / 256, 256>>>(x, xhb, xlb, NTOK * HDIM);
    split_bf16_kernel<<<(INTER_DIM * HDIM + 255) / 256, 256>>>(w1, w1hb, w1lb, INTER_DIM * HDIM);
    round_bf16_kernel<<<((int)((size_t)PDIM * INTER_DIM) + 255) / 256, 256>>>(
        w2, w2b, PDIM * INTER_DIM);

    // ---- router inter: 3xBF16 split (near-fp32), relu; dual write fp32 + bf16 ----
    gemm_bf16k<2><<<dim3(INTER_DIM / 128, NTOK / 128), 256, BF_SMEM>>>(
        xhb, xlb, w1hb, w1lb, b1, inter, interb, 3 * HDIM, INTER_DIM, 1);

    // ---- logits: single bf16 (top-8 screening only) ----
    gemm_bf16k<0><<<dim3(PDIM / 128, NTOK / 128), 256, BF_SMEM>>>(
        interb, nullptr, w2b, nullptr, b2, logits, nullptr, INTER_DIM, PDIM, 0);

    topk_rescore_kernel<<<(NTOK * 32 + 255) / 256, 256>>>(
        logits, inter, w2, b2, tpool, temp, combined, usage);

    // ---- projected_x (tf32) -> LN -> combined[:, :512] ----
    gemm_tf32<0><<<dim3(DDIM / 128, NTOK / 128), 256, TF_SMEM>>>(
        xt, wprojt, bproj, proj, HDIM, DDIM, 0, 0, 0, 0);
    ln_kernel<<<NTOK, 128>>>(proj, ln_g, ln_b, combined);

    // ---- dilated convs (tf32 virtual im2col, GELU, rounded out) ----
    const int dils[NDIL] = {1, 2, 4};
    for (int i = 0; i < NDIL; i++)
        gemm_tf32<1><<<dim3(HDIM / 128, NTOK / 128), 256, TF_SMEM>>>(
            xt, convwt + (size_t)i * 3 * HDIM * HDIM, conv_b + i * HDIM, concat,
            3 * HDIM, 3 * HDIM, i * HDIM, 2, dils[i], 1);

    // ---- local out (tf32) ----
    gemm_tf32<0><<<dim3(HDIM / 128, NTOK / 128), 256, TF_SMEM>>>(
        concat, woutt, bout, local, 3 * HDIM, HDIM, 0, 0, 0, 0);

    // ---- transformation (rounded out) + global out (tf32) ----
    gemm_tf32<0><<<dim3(DDIM / 128, NTOK / 128), 256, TF_SMEM>>>(
        combined, wmapt, bmap, transf, 2 * DDIM, DDIM, 0, 0, 0, 1);
    gemm_tf32<0><<<dim3(HDIM / 128, NTOK / 128), 256, TF_SMEM>>>(
        transf, wrpt, brp, glob, DDIM, HDIM, 0, 0, 0, 0);

    // gate + mix -> out
    gate_combine<<<NTOK, 128>>>(x, wg, bg, local, glob, out);

    // diversity loss -> last output element
    if (out_size > NTOK * HDIM)
        divloss_kernel<<<1, 1024>>>(usage, out + (size_t)NTOK * HDIM);
}

// round 9
// speedup vs baseline: 3.7791x; 1.1908x over previous
#include <cuda_runtime.h>
#include <cuda_bf16.h>
#include <cstdint>
#include <float.h>

// ---------------- problem constants ----------------
#define BDIM 4
#define SDIM 4096
#define HDIM 1024
#define PDIM 4096
#define DDIM 512
#define NTOK (BDIM * SDIM)          // 16384
#define INTER_DIM 1024
#define NDIL 3

// ---------------- scratch (device globals; no allocs allowed) ----------------
__device__ float g_inter[NTOK * INTER_DIM];         // near-exact fp32 (rescore)
__device__ __nv_bfloat16 g_logitsb[(size_t)NTOK * PDIM]; // bf16 screen logits
__device__ float g_concat[(size_t)NTOK * 3 * HDIM]; // tf32-rounded GELU out
__device__ float g_local[NTOK * HDIM];
__device__ float g_combined[NTOK * 2 * DDIM];       // tf32-rounded
__device__ float g_transf[NTOK * DDIM];             // tf32-rounded
__device__ float g_global[NTOK * HDIM];
__device__ float g_proj[NTOK * DDIM];
__device__ float g_convwt[NDIL * 3 * HDIM * HDIM];  // repacked + tf32-rounded
__device__ float g_usage[PDIM];
// pre-rounded tf32 operands (continuous paths)
__device__ float g_xt[NTOK * HDIM];                 // tf32(x)
__device__ float g_wprojt[DDIM * HDIM];
__device__ float g_woutt[HDIM * 3 * HDIM];
__device__ float g_wmapt[DDIM * 2 * DDIM];
__device__ float g_wrpt[HDIM * DDIM];
// bf16 router operands
__device__ __nv_bfloat16 g_xhb[NTOK * HDIM];        // hi(x) bf16
__device__ __nv_bfloat16 g_xlb[NTOK * HDIM];        // lo(x) bf16
__device__ __nv_bfloat16 g_w1hb[INTER_DIM * HDIM];
__device__ __nv_bfloat16 g_w1lb[INTER_DIM * HDIM];
__device__ __nv_bfloat16 g_w2b[(size_t)PDIM * INTER_DIM];
__device__ __nv_bfloat16 g_interb[NTOK * INTER_DIM];// bf16(inter) (logits A)

// ---------------- helpers ----------------
__device__ __forceinline__ float block_reduce_sum(float v, float* sh) {
    int tid = threadIdx.x;
    #pragma unroll
    for (int o = 16; o; o >>= 1) v += __shfl_xor_sync(0xffffffffu, v, o);
    if ((tid & 31) == 0) sh[tid >> 5] = v;
    __syncthreads();
    int nw = blockDim.x >> 5;
    float r = (tid < nw) ? sh[tid] : 0.f;
    if (tid < 32) {
        #pragma unroll
        for (int o = 16; o; o >>= 1) r += __shfl_xor_sync(0xffffffffu, r, o);
        if (tid == 0) sh[32] = r;
    }
    __syncthreads();
    float total = sh[32];
    __syncthreads();
    return total;
}

__device__ __forceinline__ unsigned cvt_tf32(float x) {
    unsigned r;
    asm("cvt.rna.tf32.f32 %0, %1;" : "=r"(r) : "f"(x));
    return r;
}
__device__ __forceinline__ float round_tf32f(float x) {
    return __uint_as_float(cvt_tf32(x));
}

__device__ __forceinline__ void mma_tf32(float* c, const unsigned* a, const unsigned* b) {
    asm volatile(
        "mma.sync.aligned.m16n8k8.row.col.f32.tf32.tf32.f32 "
        "{%0,%1,%2,%3}, {%4,%5,%6,%7}, {%8,%9}, {%0,%1,%2,%3};\n"
        : "+f"(c[0]), "+f"(c[1]), "+f"(c[2]), "+f"(c[3])
        : "r"(a[0]), "r"(a[1]), "r"(a[2]), "r"(a[3]), "r"(b[0]), "r"(b[1]));
}

__device__ __forceinline__ void mma_bf16(float* c, const unsigned* a, const unsigned* b) {
    asm volatile(
        "mma.sync.aligned.m16n8k16.row.col.f32.bf16.bf16.f32 "
        "{%0,%1,%2,%3}, {%4,%5,%6,%7}, {%8,%9}, {%0,%1,%2,%3};\n"
        : "+f"(c[0]), "+f"(c[1]), "+f"(c[2]), "+f"(c[3])
        : "r"(a[0]), "r"(a[1]), "r"(a[2]), "r"(a[3]), "r"(b[0]), "r"(b[1]));
}

__device__ __forceinline__ void ldsm_x4(unsigned addr, unsigned& r0, unsigned& r1,
                                        unsigned& r2, unsigned& r3) {
    asm volatile("ldmatrix.sync.aligned.m8n8.x4.shared.b16 {%0,%1,%2,%3}, [%4];"
                 : "=r"(r0), "=r"(r1), "=r"(r2), "=r"(r3) : "r"(addr));
}

__device__ __forceinline__ void cp16(void* dst_smem, const void* src, bool pred) {
    unsigned d = (unsigned)__cvta_generic_to_shared(dst_smem);
    int sz = pred ? 16 : 0;
    asm volatile("cp.async.cg.shared.global [%0], [%1], 16, %2;\n"
                 :: "r"(d), "l"(src), "r"(sz));
}
#define CP_COMMIT() asm volatile("cp.async.commit_group;\n" ::)
#define CP_WAIT1()  asm volatile("cp.async.wait_group 1;\n" ::)

// =====================================================================
// TF32 tensor-core GEMM (operands pre-rounded, ldmatrix fragments).
// MODE 0: plain  C = act(A @ W^T + b)
// MODE 1: conv   A = virtual im2col of x (token shift per 1024-slice)
// BM=BN=128, BK=32, 256 threads, warp tile 64x32, cp.async 3-stage,
// ONE __syncthreads per K-chunk, 2 CTAs/SM.
// =====================================================================
#define TFPAD 36

template<int MODE>
__global__ void __launch_bounds__(256, 2) gemm_tf32(
    const float* __restrict__ A, const float* __restrict__ W,
    const float* __restrict__ bias, float* __restrict__ C,
    int K, int ldc, int coff, int act, int dil, int roundC)
{
    extern __shared__ float smem[];
    float* As = smem;                      // [3][128][TFPAD]
    float* Bs = smem + 3 * 128 * TFPAD;    // [3][128][TFPAD]

    const int tid = threadIdx.x;
    const int lane = tid & 31;
    const int wid = tid >> 5;
    const int wm = wid >> 2;
    const int wn = wid & 3;
    const int g = lane >> 2;
    const int t = lane & 3;
    const int row0 = blockIdx.y * 128;
    const int col0 = blockIdx.x * 128;
    const int KT = K >> 5;

    const unsigned sA = (unsigned)__cvta_generic_to_shared(As);
    const unsigned sB = (unsigned)__cvta_generic_to_shared(Bs);
    const unsigned aBase = sA + (((wm * 64 + (lane & 15)) * TFPAD + ((lane >> 4) & 1) * 4) << 2);
    const unsigned bBase = sB + (((wn * 32 + (lane & 7) + ((lane >> 4) & 1) * 8) * TFPAD
                                  + ((lane >> 3) & 1) * 4) << 2);
    const unsigned BUFO = 128 * TFPAD * 4;

    float acc[4][4][4];
    #pragma unroll
    for (int i = 0; i < 4; i++)
        #pragma unroll
        for (int j = 0; j < 4; j++)
            #pragma unroll
            for (int q = 0; q < 4; q++) acc[i][j][q] = 0.f;

    auto load_tile = [&](int kt, int buf) {
        int k0 = kt << 5;
        int ksl = 0, h0 = k0, shift = 0;
        if (MODE == 1) {
            ksl = k0 >> 10;
            h0 = k0 & (HDIM - 1);
            shift = (ksl - 1) * dil;
        }
        float* Ad = As + buf * 128 * TFPAD;
        float* Bd = Bs + buf * 128 * TFPAD;
        #pragma unroll
        for (int i = 0; i < 4; i++) {
            int idx = tid + i * 256;
            int r = idx >> 3;
            int c4 = (idx & 7) << 2;
            const float* srcA;
            bool pred = true;
            if (MODE == 1) {
                int n = row0 + r;
                int s2 = (n & (SDIM - 1)) + shift;
                pred = ((unsigned)s2 < (unsigned)SDIM);
                srcA = pred ? (A + (size_t)(n + shift) * HDIM + h0 + c4) : A;
            } else {
                srcA = A + (size_t)(row0 + r) * K + k0 + c4;
            }
            cp16(Ad + r * TFPAD + c4, srcA, pred);
            const float* srcB;
            if (MODE == 1)
                srcB = W + ((size_t)ksl * HDIM + col0 + r) * HDIM + h0 + c4;
            else
                srcB = W + (size_t)(col0 + r) * K + k0 + c4;
            cp16(Bd + r * TFPAD + c4, srcB, true);
        }
    };

    // 3-stage prologue
    load_tile(0, 0); CP_COMMIT();
    if (KT > 1) load_tile(1, 1);
    CP_COMMIT();

    int buf = 0;
    for (int kt = 0; kt < KT; kt++) {
        CP_WAIT1();            // tile kt complete (kt+1 may be pending)
        __syncthreads();       // visibility + buffer-reuse ordering
        if (kt + 2 < KT) load_tile(kt + 2, (buf + 2 >= 3) ? buf - 1 : buf + 2);
        CP_COMMIT();           // (possibly empty group keeps wait arithmetic uniform)

        const unsigned aB = aBase + buf * BUFO;
        const unsigned bB = bBase + buf * BUFO;
        #pragma unroll
        for (int kk = 0; kk < 4; kk++) {
            unsigned af[4][4], bf[4][2];
            #pragma unroll
            for (int p = 0; p < 2; p++)
                ldsm_x4(bB + p * (16 * TFPAD * 4) + kk * 32,
                        bf[2 * p][0], bf[2 * p][1], bf[2 * p + 1][0], bf[2 * p + 1][1]);
            #pragma unroll
            for (int mt = 0; mt < 4; mt++)
                ldsm_x4(aB + mt * (16 * TFPAD * 4) + kk * 32,
                        af[mt][0], af[mt][1], af[mt][2], af[mt][3]);
            #pragma unroll
            for (int mt = 0; mt < 4; mt++)
                #pragma unroll
                for (int nt = 0; nt < 4; nt++)
                    mma_tf32(acc[mt][nt], af[mt], bf[nt]);
        }
        buf = (buf + 1 == 3) ? 0 : buf + 1;
    }

    #pragma unroll
    for (int mt = 0; mt < 4; mt++) {
        int r0 = row0 + wm * 64 + mt * 16 + g;
        int r1 = r0 + 8;
        #pragma unroll
        for (int nt = 0; nt < 4; nt++) {
            int c = col0 + wn * 32 + nt * 8 + 2 * t;
            float b0v = bias ? bias[c] : 0.f;
            float b1v = bias ? bias[c + 1] : 0.f;
            float v[4] = {acc[mt][nt][0] + b0v, acc[mt][nt][1] + b1v,
                          acc[mt][nt][2] + b0v, acc[mt][nt][3] + b1v};
            if (act == 2) {
                #pragma unroll
                for (int q = 0; q < 4; q++)
                    v[q] = 0.5f * v[q] * (1.f + erff(v[q] * 0.70710678118654752f));
            } else if (act == 1) {
                #pragma unroll
                for (int q = 0; q < 4; q++) v[q] = fmaxf(v[q], 0.f);
            }
            if (roundC) {
                #pragma unroll
                for (int q = 0; q < 4; q++) v[q] = round_tf32f(v[q]);
            }
            *reinterpret_cast<float2*>(C + (size_t)r0 * ldc + coff + c) = make_float2(v[0], v[1]);
            *reinterpret_cast<float2*>(C + (size_t)r1 * ldc + coff + c) = make_float2(v[2], v[3]);
        }
    }
}

// =====================================================================
// BF16 tensor-core GEMM (router only).
// MODE 0: plain. MODE 2: 3xBF16 virtual K=3072.
// C fp32 (optional); C2 bf16 (optional). 3-stage pipeline, 1 sync/chunk.
// =====================================================================
#define HPAD 40

template<int MODE>
__global__ void __launch_bounds__(256, 2) gemm_bf16k(
    const __nv_bfloat16* __restrict__ A, const __nv_bfloat16* __restrict__ Alo,
    const __nv_bfloat16* __restrict__ W, const __nv_bfloat16* __restrict__ Wlo,
    const float* __restrict__ bias, float* __restrict__ C, __nv_bfloat16* __restrict__ C2,
    int K, int ldc, int act)
{
    extern __shared__ __nv_bfloat16 hsm[];
    __nv_bfloat16* As = hsm;                   // [3][128][HPAD]
    __nv_bfloat16* Bs = hsm + 3 * 128 * HPAD;

    const int tid = threadIdx.x;
    const int lane = tid & 31;
    const int wid = tid >> 5;
    const int wm = wid >> 2;
    const int wn = wid & 3;
    const int g = lane >> 2;
    const int t = lane & 3;
    const int row0 = blockIdx.y * 128;
    const int col0 = blockIdx.x * 128;
    const int KT = K >> 5;

    const unsigned sA = (unsigned)__cvta_generic_to_shared(As);
    const unsigned sB = (unsigned)__cvta_generic_to_shared(Bs);
    const unsigned aBase = sA + (wm * 64 + (lane & 15)) * (HPAD * 2) + ((lane >> 4) & 1) * 16;
    const unsigned bBase = sB + (wn * 32 + (lane & 7) + ((lane >> 4) & 1) * 8) * (HPAD * 2)
                              + ((lane >> 3) & 1) * 16;
    const unsigned BUFO = 128 * HPAD * 2;

    float acc[4][4][4];
    #pragma unroll
    for (int i = 0; i < 4; i++)
        #pragma unroll
        for (int j = 0; j < 4; j++)
            #pragma unroll
            for (int q = 0; q < 4; q++) acc[i][j][q] = 0.f;

    auto load_tile = [&](int kt, int buf) {
        int k0 = kt << 5;
        int ksl = 0, h0 = k0;
        if (MODE == 2) { ksl = k0 >> 10; h0 = k0 & (HDIM - 1); }
        __nv_bfloat16* Ad = As + buf * 128 * HPAD;
        __nv_bfloat16* Bd = Bs + buf * 128 * HPAD;
        #pragma unroll
        for (int i = 0; i < 2; i++) {
            int idx = tid + i * 256;
            int r = idx >> 2;
            int c8 = (idx & 3) << 3;
            const __nv_bfloat16* srcA;
            if (MODE == 2) {
                const __nv_bfloat16* Ab = (ksl == 2) ? Alo : A;
                srcA = Ab + (size_t)(row0 + r) * HDIM + h0 + c8;
            } else {
                srcA = A + (size_t)(row0 + r) * K + k0 + c8;
            }
            cp16(Ad + r * HPAD + c8, srcA, true);
            const __nv_bfloat16* srcB;
            if (MODE == 2) {
                const __nv_bfloat16* Wb = (ksl == 1) ? Wlo : W;
                srcB = Wb + (size_t)(col0 + r) * HDIM + h0 + c8;
            } else {
                srcB = W + (size_t)(col0 + r) * K + k0 + c8;
            }
            cp16(Bd + r * HPAD + c8, srcB, true);
        }
    };

    load_tile(0, 0); CP_COMMIT();
    if (KT > 1) load_tile(1, 1);
    CP_COMMIT();

    int buf = 0;
    for (int kt = 0; kt < KT; kt++) {
        CP_WAIT1();
        __syncthreads();
        if (kt + 2 < KT) load_tile(kt + 2, (buf + 2 >= 3) ? buf - 1 : buf + 2);
        CP_COMMIT();

        const unsigned aB = aBase + buf * BUFO;
        const unsigned bB = bBase + buf * BUFO;
        #pragma unroll
        for (int kk = 0; kk < 2; kk++) {
            unsigned af[4][4], bf[4][2];
            #pragma unroll
            for (int p = 0; p < 2; p++)
                ldsm_x4(bB + p * (16 * HPAD * 2) + kk * 32,
                        bf[2 * p][0], bf[2 * p][1], bf[2 * p + 1][0], bf[2 * p + 1][1]);
            #pragma unroll
            for (int mt = 0; mt < 4; mt++)
                ldsm_x4(aB + mt * (16 * HPAD * 2) + kk * 32,
                        af[mt][0], af[mt][1], af[mt][2], af[mt][3]);
            #pragma unroll
            for (int mt = 0; mt < 4; mt++)
                #pragma unroll
                for (int nt = 0; nt < 4; nt++)
                    mma_bf16(acc[mt][nt], af[mt], bf[nt]);
        }
        buf = (buf + 1 == 3) ? 0 : buf + 1;
    }

    #pragma unroll
    for (int mt = 0; mt < 4; mt++) {
        int r0 = row0 + wm * 64 + mt * 16 + g;
        int r1 = r0 + 8;
        #pragma unroll
        for (int nt = 0; nt < 4; nt++) {
            int c = col0 + wn * 32 + nt * 8 + 2 * t;
            float b0v = bias ? bias[c] : 0.f;
            float b1v = bias ? bias[c + 1] : 0.f;
            float v[4] = {acc[mt][nt][0] + b0v, acc[mt][nt][1] + b1v,
                          acc[mt][nt][2] + b0v, acc[mt][nt][3] + b1v};
            if (act == 1) {
                #pragma unroll
                for (int q = 0; q < 4; q++) v[q] = fmaxf(v[q], 0.f);
            }
            if (C) {
                *reinterpret_cast<float2*>(C + (size_t)r0 * ldc + c) = make_float2(v[0], v[1]);
                *reinterpret_cast<float2*>(C + (size_t)r1 * ldc + c) = make_float2(v[2], v[3]);
            }
            if (C2) {
                __nv_bfloat162 p0, p1;
                p0.x = __float2bfloat16_rn(v[0]); p0.y = __float2bfloat16_rn(v[1]);
                p1.x = __float2bfloat16_rn(v[2]); p1.y = __float2bfloat16_rn(v[3]);
                *reinterpret_cast<__nv_bfloat162*>(C2 + (size_t)r0 * ldc + c) = p0;
                *reinterpret_cast<__nv_bfloat162*>(C2 + (size_t)r1 * ldc + c) = p1;
            }
        }
    }
}

// ---------------- prep kernels ----------------
__global__ void round_tf32_kernel(const float* __restrict__ src, float* __restrict__ dst, int n4) {
    int i = blockIdx.x * blockDim.x + threadIdx.x;
    if (i >= n4) return;
    float4 v = reinterpret_cast<const float4*>(src)[i];
    v.x = round_tf32f(v.x); v.y = round_tf32f(v.y);
    v.z = round_tf32f(v.z); v.w = round_tf32f(v.w);
    reinterpret_cast<float4*>(dst)[i] = v;
}

// fused: xt = tf32(x); (xhb, xlb) = bf16 split of x
__global__ void prep_x_kernel(const float* __restrict__ src, float* __restrict__ xt,
                              __nv_bfloat16* __restrict__ hi, __nv_bfloat16* __restrict__ lo,
                              int n4) {
    int i = blockIdx.x * blockDim.x + threadIdx.x;
    if (i >= n4) return;
    float4 v = reinterpret_cast<const float4*>(src)[i];
    float4 r;
    r.x = round_tf32f(v.x); r.y = round_tf32f(v.y);
    r.z = round_tf32f(v.z); r.w = round_tf32f(v.w);
    reinterpret_cast<float4*>(xt)[i] = r;
    __nv_bfloat162 h0, h1, l0, l1;
    h0.x = __float2bfloat16_rn(v.x); l0.x = __float2bfloat16_rn(v.x - __bfloat162float(h0.x));
    h0.y = __float2bfloat16_rn(v.y); l0.y = __float2bfloat16_rn(v.y - __bfloat162float(h0.y));
    h1.x = __float2bfloat16_rn(v.z); l1.x = __float2bfloat16_rn(v.z - __bfloat162float(h1.x));
    h1.y = __float2bfloat16_rn(v.w); l1.y = __float2bfloat16_rn(v.w - __bfloat162float(h1.y));
    reinterpret_cast<__nv_bfloat162*>(hi)[2 * i] = h0;
    reinterpret_cast<__nv_bfloat162*>(hi)[2 * i + 1] = h1;
    reinterpret_cast<__nv_bfloat162*>(lo)[2 * i] = l0;
    reinterpret_cast<__nv_bfloat162*>(lo)[2 * i + 1] = l1;
}

__global__ void split_bf16_kernel(const float* __restrict__ src, __nv_bfloat16* __restrict__ hi,
                                  __nv_bfloat16* __restrict__ lo, int n) {
    int i = blockIdx.x * blockDim.x + threadIdx.x;
    if (i >= n) return;
    float v = src[i];
    __nv_bfloat16 h = __float2bfloat16_rn(v);
    hi[i] = h;
    lo[i] = __float2bfloat16_rn(v - __bfloat162float(h));
}

__global__ void round_bf16_kernel(const float* __restrict__ src, __nv_bfloat16* __restrict__ dst, int n) {
    int i = blockIdx.x * blockDim.x + threadIdx.x;
    if (i >= n) return;
    dst[i] = __float2bfloat16_rn(src[i]);
}

__global__ void repack_convw(const float* __restrict__ cw, float* __restrict__ out) {
    int idx = blockIdx.x * blockDim.x + threadIdx.x;
    const int total = NDIL * 3 * HDIM * HDIM;
    if (idx >= total) return;
    int hi = idx & (HDIM - 1);
    int t = idx >> 10;
    int ho = t & (HDIM - 1);
    int t2 = t >> 10;
    int k = t2 % 3;
    int d = t2 / 3;
    out[idx] = round_tf32f(cw[(((size_t)d * HDIM + ho) * HDIM + hi) * 3 + k]);
}

__global__ void zero_usage(float* usage) {
    int i = blockIdx.x * blockDim.x + threadIdx.x;
    if (i < PDIM) usage[i] = 0.f;
}

// ---------------- top-8 (bf16 logits) + fp32 rescore + exact top-2 ----------------
__device__ __forceinline__ bool better(float va, int ia, float vb, int ib) {
    return (va > vb) || (va == vb && ia < ib);
}
__device__ __forceinline__ void ins2(float& v1, int& i1, float& v2, int& i2, float v, int i) {
    if (better(v, i, v1, i1)) { v2 = v1; i2 = i1; v1 = v; i1 = i; }
    else if (better(v, i, v2, i2)) { v2 = v; i2 = i; }
}

__global__ void __launch_bounds__(256) topk_rescore_kernel(
    const __nv_bfloat16* __restrict__ logits, const float* __restrict__ inter,
    const float* __restrict__ w2, const float* __restrict__ b2,
    const float* __restrict__ tpool, const float* __restrict__ temp_p,
    float* __restrict__ combined, float* __restrict__ usage)
{
    int gw = (blockIdx.x * blockDim.x + threadIdx.x) >> 5;
    int lane = threadIdx.x & 31;
    if (gw >= NTOK) return;
    float temp = fminf(fmaxf(*temp_p, 0.1f), 5.0f);
    float invt = 1.f / temp;

    const __nv_bfloat16* lrow = logits + (size_t)gw * PDIM;
    float tv[8]; int ti[8];
    #pragma unroll
    for (int k = 0; k < 8; k++) { tv[k] = -FLT_MAX; ti[k] = 0x3fffffff; }
    auto push = [&](float v, int j) {
        if (better(v, j, tv[7], ti[7])) {
            tv[7] = v; ti[7] = j;
            #pragma unroll
            for (int k = 7; k > 0; k--) {
                bool sw = better(tv[k], ti[k], tv[k - 1], ti[k - 1]);
                float av = sw ? tv[k] : tv[k - 1];
                float bv2 = sw ? tv[k - 1] : tv[k];
                int ai = sw ? ti[k] : ti[k - 1];
                int bi = sw ? ti[k - 1] : ti[k];
                tv[k - 1] = av; tv[k] = bv2; ti[k - 1] = ai; ti[k] = bi;
            }
        }
    };
    for (int j = lane * 2; j < PDIM; j += 64) {
        __nv_bfloat162 p = *reinterpret_cast<const __nv_bfloat162*>(lrow + j);
        push(fminf(fmaxf(__bfloat162float(p.x) * invt, -10.f), 10.f), j);
        push(fminf(fmaxf(__bfloat162float(p.y) * invt, -10.f), 10.f), j + 1);
    }

    int cand[8];
    #pragma unroll
    for (int r = 0; r < 8; r++) {
        float bvv = tv[0]; int bii = ti[0];
        #pragma unroll
        for (int off = 16; off; off >>= 1) {
            float ov = __shfl_xor_sync(0xffffffffu, bvv, off);
            int oi = __shfl_xor_sync(0xffffffffu, bii, off);
            if (better(ov, oi, bvv, bii)) { bvv = ov; bii = oi; }
        }
        cand[r] = bii;
        if (ti[0] == bii) {
            #pragma unroll
            for (int k = 0; k < 7; k++) { tv[k] = tv[k + 1]; ti[k] = ti[k + 1]; }
            tv[7] = -FLT_MAX; ti[7] = 0x3fffffff;
        }
    }

    const float* irow = inter + (size_t)gw * INTER_DIM;
    float xv[32];
    #pragma unroll
    for (int q = 0; q < 32; q++) xv[q] = irow[lane + q * 32];

    float v1 = -FLT_MAX, v2 = -FLT_MAX;
    int i1 = 0x3fffffff, i2 = 0x3fffffff;
    #pragma unroll
    for (int r = 0; r < 8; r++) {
        const float* wrow = w2 + (size_t)cand[r] * INTER_DIM;
        float s = 0.f;
        #pragma unroll
        for (int q = 0; q < 32; q++) s = fmaf(xv[q], wrow[lane + q * 32], s);
        #pragma unroll
        for (int off = 16; off; off >>= 1) s += __shfl_xor_sync(0xffffffffu, s, off);
        float v = fminf(fmaxf((s + b2[cand[r]]) * invt, -10.f), 10.f);
        ins2(v1, i1, v2, i2, v, cand[r]);
    }

    float e = expf(v2 - v1);
    float w1 = 1.f / (1.f + e);
    float w2s = e / (1.f + e);
    if (lane == 0) {
        atomicAdd(&usage[i1], w1);
        atomicAdd(&usage[i2], w2s);
    }
    const float* p1 = tpool + (size_t)i1 * DDIM;
    const float* p2 = tpool + (size_t)i2 * DDIM;
    float* dst = combined + (size_t)gw * (2 * DDIM) + DDIM;
    for (int d = lane; d < DDIM; d += 32)
        dst[d] = round_tf32f(w1 * p1[d] + w2s * p2[d]);
}

// ---------------- layernorm over D=512, writes rounded combined[:, :512] ----------------
__global__ void ln_kernel(const float* __restrict__ proj, const float* __restrict__ g,
                          const float* __restrict__ b, float* __restrict__ combined)
{
    __shared__ float sh[33];
    int n = blockIdx.x;
    const float* row = proj + (size_t)n * DDIM;
    float v[4];
    float s = 0.f;
    #pragma unroll
    for (int j = 0; j < 4; j++) { v[j] = row[threadIdx.x + j * 128]; s += v[j]; }
    float mean = block_reduce_sum(s, sh) * (1.f / DDIM);
    float q = 0.f;
    #pragma unroll
    for (int j = 0; j < 4; j++) { float d = v[j] - mean; q += d * d; }
    float var = block_reduce_sum(q, sh) * (1.f / DDIM);
    float rstd = rsqrtf(var + 1e-5f);
    float* dst = combined + (size_t)n * (2 * DDIM);
    #pragma unroll
    for (int j = 0; j < 4; j++) {
        int idx = threadIdx.x + j * 128;
        dst[idx] = round_tf32f((v[j] - mean) * rstd * g[idx] + b[idx]);
    }
}

// ---------------- gate + final mix ----------------
__global__ void gate_combine(const float* __restrict__ x, const float* __restrict__ wg,
                             const float* __restrict__ bg, const float* __restrict__ local,
                             const float* __restrict__ glob, float* __restrict__ out)
{
    __shared__ float sh[33];
    int n = blockIdx.x;
    const float* xr = x + (size_t)n * HDIM;
    float s = 0.f;
    for (int j = threadIdx.x; j < HDIM; j += 128) s += xr[j] * wg[j];
    float dot = block_reduce_sum(s, sh);
    float g = 1.f / (1.f + expf(-(dot + bg[0])));
    const float* lr = local + (size_t)n * HDIM;
    const float* gr = glob + (size_t)n * HDIM;
    float* orow = out + (size_t)n * HDIM;
    for (int j = threadIdx.x; j < HDIM; j += 128)
        orow[j] = g * lr[j] + (1.f - g) * gr[j];
}

// ---------------- diversity loss ----------------
__global__ void divloss_kernel(const float* __restrict__ usage, float* __restrict__ out) {
    __shared__ float sh[33];
    float s = 0.f;
    for (int j = threadIdx.x; j < PDIM; j += 1024) s += usage[j];
    float total = block_reduce_sum(s, sh);
    float inv = 1.f / (total + 1e-8f);
    float q = 0.f;
    const float ip = 1.f / (float)PDIM;
    for (int j = threadIdx.x; j < PDIM; j += 1024) {
        float f = usage[j] * inv - ip;
        q += f * f;
    }
    float qt = block_reduce_sum(q, sh);
    if (threadIdx.x == 0) out[0] = (qt / (float)PDIM) * 0.01f;
}

// ---------------- host launcher ----------------
extern "C" void kernel_launch(void* const* d_in, const int* in_sizes, int n_in,
                              void* d_out, int out_size)
{
    const float* x      = (const float*)d_in[0];
    const float* tpool  = (const float*)d_in[1];
    const float* w1     = (const float*)d_in[2];
    const float* b1     = (const float*)d_in[3];
    const float* w2     = (const float*)d_in[4];
    const float* b2     = (const float*)d_in[5];
    const float* temp   = (const float*)d_in[6];
    const float* wproj  = (const float*)d_in[7];
    const float* bproj  = (const float*)d_in[8];
    const float* ln_g   = (const float*)d_in[9];
    const float* ln_b   = (const float*)d_in[10];
    const float* wmap   = (const float*)d_in[11];
    const float* bmap   = (const float*)d_in[12];
    const float* conv_w = (const float*)d_in[13];
    const float* conv_b = (const float*)d_in[14];
    const float* wout   = (const float*)d_in[15];
    const float* bout   = (const float*)d_in[16];
    const float* wrp    = (const float*)d_in[17];
    const float* brp    = (const float*)d_in[18];
    const float* wg     = (const float*)d_in[19];
    const float* bg     = (const float*)d_in[20];
    float* out = (float*)d_out;

    float *inter, *concat, *local, *combined, *transf, *glob, *proj;
    float *convwt, *usage, *xt, *wprojt, *woutt, *wmapt, *wrpt;
    __nv_bfloat16 *logitsb, *xhb, *xlb, *w1hb, *w1lb, *w2b, *interb;
    cudaGetSymbolAddress((void**)&inter,    g_inter);
    cudaGetSymbolAddress((void**)&logitsb,  g_logitsb);
    cudaGetSymbolAddress((void**)&concat,   g_concat);
    cudaGetSymbolAddress((void**)&local,    g_local);
    cudaGetSymbolAddress((void**)&combined, g_combined);
    cudaGetSymbolAddress((void**)&transf,   g_transf);
    cudaGetSymbolAddress((void**)&glob,     g_global);
    cudaGetSymbolAddress((void**)&proj,     g_proj);
    cudaGetSymbolAddress((void**)&convwt,   g_convwt);
    cudaGetSymbolAddress((void**)&usage,    g_usage);
    cudaGetSymbolAddress((void**)&xt,       g_xt);
    cudaGetSymbolAddress((void**)&wprojt,   g_wprojt);
    cudaGetSymbolAddress((void**)&woutt,    g_woutt);
    cudaGetSymbolAddress((void**)&wmapt,    g_wmapt);
    cudaGetSymbolAddress((void**)&wrpt,     g_wrpt);
    cudaGetSymbolAddress((void**)&xhb,      g_xhb);
    cudaGetSymbolAddress((void**)&xlb,      g_xlb);
    cudaGetSymbolAddress((void**)&w1hb,     g_w1hb);
    cudaGetSymbolAddress((void**)&w1lb,     g_w1lb);
    cudaGetSymbolAddress((void**)&w2b,      g_w2b);
    cudaGetSymbolAddress((void**)&interb,   g_interb);

    const int TF_SMEM = 6 * 128 * TFPAD * sizeof(float);          // 110592 B
    const int BF_SMEM = 6 * 128 * HPAD * sizeof(__nv_bfloat16);   // 61440 B
    cudaFuncSetAttribute(gemm_tf32<0>, cudaFuncAttributeMaxDynamicSharedMemorySize, TF_SMEM);
    cudaFuncSetAttribute(gemm_tf32<1>, cudaFuncAttributeMaxDynamicSharedMemorySize, TF_SMEM);
    cudaFuncSetAttribute(gemm_bf16k<0>, cudaFuncAttributeMaxDynamicSharedMemorySize, BF_SMEM);
    cudaFuncSetAttribute(gemm_bf16k<2>, cudaFuncAttributeMaxDynamicSharedMemorySize, BF_SMEM);

    // ---- prep ----
    const int total_cw = NDIL * 3 * HDIM * HDIM;
    repack_convw<<<(total_cw + 255) / 256, 256>>>(conv_w, convwt);
    zero_usage<<<(PDIM + 255) / 256, 256>>>(usage);
    prep_x_kernel<<<(NTOK * HDIM / 4 + 255) / 256, 256>>>(x, xt, xhb, xlb, NTOK * HDIM / 4);
    round_tf32_kernel<<<(DDIM * HDIM / 4 + 255) / 256, 256>>>(wproj, wprojt, DDIM * HDIM / 4);
    round_tf32_kernel<<<(HDIM * 3 * HDIM / 4 + 255) / 256, 256>>>(wout, woutt, HDIM * 3 * HDIM / 4);
    round_tf32_kernel<<<(DDIM * 2 * DDIM / 4 + 255) / 256, 256>>>(wmap, wmapt, DDIM * 2 * DDIM / 4);
    round_tf32_kernel<<<(HDIM * DDIM / 4 + 255) / 256, 256>>>(wrp, wrpt, HDIM * DDIM / 4);
    split_bf16_kernel<<<(INTER_DIM * HDIM + 255) / 256, 256>>>(w1, w1hb, w1lb, INTER_DIM * HDIM);
    round_bf16_kernel<<<((int)((size_t)PDIM * INTER_DIM) + 255) / 256, 256>>>(
        w2, w2b, PDIM * INTER_DIM);

    // ---- router inter: 3xBF16 split, relu; dual write fp32 + bf16 ----
    gemm_bf16k<2><<<dim3(INTER_DIM / 128, NTOK / 128), 256, BF_SMEM>>>(
        xhb, xlb, w1hb, w1lb, b1, inter, interb, 3 * HDIM, INTER_DIM, 1);

    // ---- logits: single bf16, bf16 output (top-8 screen only) ----
    gemm_bf16k<0><<<dim3(PDIM / 128, NTOK / 128), 256, BF_SMEM>>>(
        interb, nullptr, w2b, nullptr, b2, nullptr, logitsb, INTER_DIM, PDIM, 0);

    topk_rescore_kernel<<<(NTOK * 32 + 255) / 256, 256>>>(
        logitsb, inter, w2, b2, tpool, temp, combined, usage);

    // ---- projected_x (tf32) -> LN -> combined[:, :512] ----
    gemm_tf32<0><<<dim3(DDIM / 128, NTOK / 128), 256, TF_SMEM>>>(
        xt, wprojt, bproj, proj, HDIM, DDIM, 0, 0, 0, 0);
    ln_kernel<<<NTOK, 128>>>(proj, ln_g, ln_b, combined);

    // ---- dilated convs (tf32 virtual im2col, GELU, rounded out) ----
    const int dils[NDIL] = {1, 2, 4};
    for (int i = 0; i < NDIL; i++)
        gemm_tf32<1><<<dim3(HDIM / 128, NTOK / 128), 256, TF_SMEM>>>(
            xt, convwt + (size_t)i * 3 * HDIM * HDIM, conv_b + i * HDIM, concat,
            3 * HDIM, 3 * HDIM, i * HDIM, 2, dils[i], 1);

    // ---- local out (tf32) ----
    gemm_tf32<0><<<dim3(HDIM / 128, NTOK / 128), 256, TF_SMEM>>>(
        concat, woutt, bout, local, 3 * HDIM, HDIM, 0, 0, 0, 0);

    // ---- transformation (rounded out) + global out (tf32) ----
    gemm_tf32<0><<<dim3(DDIM / 128, NTOK / 128), 256, TF_SMEM>>>(
        combined, wmapt, bmap, transf, 2 * DDIM, DDIM, 0, 0, 0, 1);
    gemm_tf32<0><<<dim3(HDIM / 128, NTOK / 128), 256, TF_SMEM>>>(
        transf, wrpt, brp, glob, DDIM, HDIM, 0, 0, 0, 0);

    // gate + mix -> out
    gate_combine<<<NTOK, 128>>>(x, wg, bg, local, glob, out);

    // diversity loss -> last output element
    if (out_size > NTOK * HDIM)
        divloss_kernel<<<1, 1024>>>(usage, out + (size_t)NTOK * HDIM);
}